// round 2
// baseline (speedup 1.0000x reference)
#include <cuda_runtime.h>
#include <cuda_bf16.h>

// ---------------------------------------------------------------------------
// SelectionGNN (clique + line expansion), B=8, N=4096, E=1, K=3, F=[16,32,16]
//
// Structure per layer:  y = relu( sum_k W_k S^k x + b )
// S (node index) and W (feature index) commute, so for Fin>Fout layers we
// project first (v_k = W_k x, Fout=16 channels) and Horner:
//     t1 = S v2 + v1 ;  y = relu(S t1 + v0 + b)
// => every diffusion GEMM runs at C = B*16 = 128 columns.
// 8 diffusion GEMMs of 4096x128x4096 dominate (34.4 GFLOP fp32).
// ---------------------------------------------------------------------------

#define NNODES 4096
#define BATCH  8
#define CCOLS  128           // B * 16 channels in every diffusion

// scratch (device globals: no allocation allowed)
__device__ __align__(16) float g_z1 [BATCH*16*NNODES];
__device__ __align__(16) float g_z2 [BATCH*16*NNODES];
__device__ __align__(16) float g_v0 [BATCH*16*NNODES];
__device__ __align__(16) float g_v1 [BATCH*16*NNODES];
__device__ __align__(16) float g_v2 [BATCH*16*NNODES];
__device__ __align__(16) float g_y32[BATCH*32*NNODES];
__device__ __align__(16) float g_y16[BATCH*16*NNODES];
__device__ __align__(16) float g_h  [BATCH*64];

// ---------------------------------------------------------------------------
// Diffusion GEMM:  Y[c, n] = sum_m S[n, m] * Z[c, m]      (stored Y[c*4096+n])
// M = 4096 (n), N = 128 (c), K = 4096 (m).
// MODE 0: Y = S Z
// MODE 1: Y = S Z + V
// MODE 2: Y = relu(S Z + V + bias[c % 16])
// Block tile 64x32, K-tile 32, 128 threads, 4x4 per thread, double-buffered.
// ---------------------------------------------------------------------------
#define BM 64
#define BN 32
#define BK 32
#define NKT (NNODES / BK)    // 128 k-tiles

template <int MODE>
__global__ __launch_bounds__(128, 2)
void gemm_diffuse(const float* __restrict__ S,
                  const float* __restrict__ Z,
                  const float* __restrict__ V,
                  const float* __restrict__ bias,
                  float* __restrict__ Y)
{
    __shared__ float As[2][BK][BM + 1];   // [k][n]
    __shared__ float Bs[2][BK][BN + 1];   // [k][c]

    const int tid = threadIdx.x;          // 0..127
    const int n0  = blockIdx.x * BM;
    const int c0  = blockIdx.y * BN;
    const int tn  = (tid & 15) * 4;       // 0..60
    const int tc  = (tid >> 4) * 4;       // 0..28

    float4 rA[4], rB[2];

    // ---- global loads into registers ----
    auto ldg_tile = [&](int k0) {
#pragma unroll
        for (int v = 0; v < 4; v++) {
            int l = tid + v * 128;                 // 0..511
            int row = l >> 3, col = (l & 7) * 4;   // 64 rows x 32 cols
            rA[v] = *reinterpret_cast<const float4*>(
                S + (size_t)(n0 + row) * NNODES + k0 + col);
        }
#pragma unroll
        for (int v = 0; v < 2; v++) {
            int l = tid + v * 128;                 // 0..255
            int row = l >> 3, col = (l & 7) * 4;   // 32 rows x 32 cols
            rB[v] = *reinterpret_cast<const float4*>(
                Z + (size_t)(c0 + row) * NNODES + k0 + col);
        }
    };
    // ---- registers -> shared (transposed to [k][n] / [k][c]) ----
    auto sts_tile = [&](int buf) {
#pragma unroll
        for (int v = 0; v < 4; v++) {
            int l = tid + v * 128;
            int row = l >> 3, col = (l & 7) * 4;
            As[buf][col + 0][row] = rA[v].x;
            As[buf][col + 1][row] = rA[v].y;
            As[buf][col + 2][row] = rA[v].z;
            As[buf][col + 3][row] = rA[v].w;
        }
#pragma unroll
        for (int v = 0; v < 2; v++) {
            int l = tid + v * 128;
            int row = l >> 3, col = (l & 7) * 4;
            Bs[buf][col + 0][row] = rB[v].x;
            Bs[buf][col + 1][row] = rB[v].y;
            Bs[buf][col + 2][row] = rB[v].z;
            Bs[buf][col + 3][row] = rB[v].w;
        }
    };

    float acc[4][4] = {};

    ldg_tile(0);
    sts_tile(0);
    __syncthreads();

    for (int kt = 0; kt < NKT; kt++) {
        const int buf = kt & 1;
        if (kt + 1 < NKT) ldg_tile((kt + 1) * BK);   // overlap with compute

#pragma unroll
        for (int k = 0; k < BK; k++) {
            float a0 = As[buf][k][tn + 0];
            float a1 = As[buf][k][tn + 1];
            float a2 = As[buf][k][tn + 2];
            float a3 = As[buf][k][tn + 3];
            float b0 = Bs[buf][k][tc + 0];
            float b1 = Bs[buf][k][tc + 1];
            float b2 = Bs[buf][k][tc + 2];
            float b3 = Bs[buf][k][tc + 3];
            acc[0][0] += a0 * b0; acc[0][1] += a0 * b1; acc[0][2] += a0 * b2; acc[0][3] += a0 * b3;
            acc[1][0] += a1 * b0; acc[1][1] += a1 * b1; acc[1][2] += a1 * b2; acc[1][3] += a1 * b3;
            acc[2][0] += a2 * b0; acc[2][1] += a2 * b1; acc[2][2] += a2 * b2; acc[2][3] += a2 * b3;
            acc[3][0] += a3 * b0; acc[3][1] += a3 * b1; acc[3][2] += a3 * b2; acc[3][3] += a3 * b3;
        }

        if (kt + 1 < NKT) sts_tile(buf ^ 1);
        __syncthreads();
    }

    // ---- epilogue ----
#pragma unroll
    for (int j = 0; j < 4; j++) {
        const int c = c0 + tc + j;
        float r0 = acc[0][j], r1 = acc[1][j], r2 = acc[2][j], r3 = acc[3][j];
        if (MODE >= 1) {
            float4 vv = *reinterpret_cast<const float4*>(V + (size_t)c * NNODES + n0 + tn);
            r0 += vv.x; r1 += vv.y; r2 += vv.z; r3 += vv.w;
        }
        if (MODE == 2) {
            float bv = bias[c & 15];     // c = b*16 + g  ->  g
            r0 = fmaxf(r0 + bv, 0.f);
            r1 = fmaxf(r1 + bv, 0.f);
            r2 = fmaxf(r2 + bv, 0.f);
            r3 = fmaxf(r3 + bv, 0.f);
        }
        float4 o = make_float4(r0, r1, r2, r3);
        *reinterpret_cast<float4*>(Y + (size_t)c * NNODES + n0 + tn) = o;
    }
}

// ---------------------------------------------------------------------------
// Combine (layers with Fin=16 -> Fout=32):
//   out[b,g,n] = relu( bias[g] + sum_{k<3} sum_{f<16} W[g,k,f] * z_k[b,f,n] )
// W layout: [Fout=32][E=1][K=3][Fin=16] -> flat g*48 + k*16 + f
// ---------------------------------------------------------------------------
__global__ __launch_bounds__(256)
void combine_k3(const float* __restrict__ z0, const float* __restrict__ z1,
                const float* __restrict__ z2, const float* __restrict__ W,
                const float* __restrict__ bias, float* __restrict__ out)
{
    __shared__ float Ws[32 * 48];
    const int tid = threadIdx.x;
    for (int i = tid; i < 32 * 48; i += 256) Ws[i] = W[i];
    __syncthreads();

    const int n = blockIdx.x * 256 + tid;
    const int b = blockIdx.y;

    float acc[32];
#pragma unroll
    for (int g = 0; g < 32; g++) acc[g] = bias[g];

    const float* zs[3] = {z0, z1, z2};
#pragma unroll
    for (int k = 0; k < 3; k++) {
        const float* z = zs[k];
#pragma unroll
        for (int f = 0; f < 16; f++) {
            float zv = z[((size_t)b * 16 + f) * NNODES + n];
#pragma unroll
            for (int g = 0; g < 32; g++)
                acc[g] += Ws[g * 48 + k * 16 + f] * zv;
        }
    }
#pragma unroll
    for (int g = 0; g < 32; g++)
        out[((size_t)b * 32 + g) * NNODES + n] = fmaxf(acc[g], 0.f);
}

// ---------------------------------------------------------------------------
// Projection (layers with Fin=32 -> Fout=16): v_k[b,g,n] = sum_f W[g,k,f] x[b,f,n]
// W layout: [16][1][3][32] -> flat g*96 + k*32 + f.   blockIdx.z = k.
// ---------------------------------------------------------------------------
__global__ __launch_bounds__(256)
void proj_k3(const float* __restrict__ in, const float* __restrict__ W,
             float* __restrict__ v0, float* __restrict__ v1, float* __restrict__ v2)
{
    const int k = blockIdx.z;
    __shared__ float Ws[16 * 32];
    const int tid = threadIdx.x;
    for (int i = tid; i < 16 * 32; i += 256)
        Ws[i] = W[(i >> 5) * 96 + k * 32 + (i & 31)];
    __syncthreads();

    const int n = blockIdx.x * 256 + tid;
    const int b = blockIdx.y;

    float acc[16] = {};
#pragma unroll
    for (int f = 0; f < 32; f++) {
        float xv = in[((size_t)b * 32 + f) * NNODES + n];
#pragma unroll
        for (int g = 0; g < 16; g++)
            acc[g] += Ws[g * 32 + f] * xv;
    }
    float* v = (k == 0) ? v0 : ((k == 1) ? v1 : v2);
#pragma unroll
    for (int g = 0; g < 16; g++)
        v[((size_t)b * 16 + g) * NNODES + n] = acc[g];
}

// ---------------------------------------------------------------------------
// MLP stage 1: h[b,j] = relu( bm1[j] + dot(yflat[b,:], Wm1[j,:]) ), len 65536
// ---------------------------------------------------------------------------
__global__ __launch_bounds__(256)
void mlp1(const float* __restrict__ y, const float* __restrict__ W1,
          const float* __restrict__ b1, float* __restrict__ h)
{
    const int j = blockIdx.x;   // 0..63
    const int b = blockIdx.y;   // 0..7
    const float4* yb = reinterpret_cast<const float4*>(y + (size_t)b * 65536);
    const float4* wj = reinterpret_cast<const float4*>(W1 + (size_t)j * 65536);

    float s = 0.f;
    for (int i = threadIdx.x; i < 16384; i += 256) {
        float4 a = yb[i], c = wj[i];
        s += a.x * c.x + a.y * c.y + a.z * c.z + a.w * c.w;
    }
#pragma unroll
    for (int o = 16; o > 0; o >>= 1) s += __shfl_down_sync(0xffffffffu, s, o);

    __shared__ float red[8];
    if ((threadIdx.x & 31) == 0) red[threadIdx.x >> 5] = s;
    __syncthreads();
    if (threadIdx.x == 0) {
        float t = 0.f;
#pragma unroll
        for (int w = 0; w < 8; w++) t += red[w];
        h[b * 64 + j] = fmaxf(t + b1[j], 0.f);
    }
}

// MLP stage 2: out[b] = bm2[0] + sum_j Wm2[j] * h[b,j]
__global__ __launch_bounds__(64)
void mlp2(const float* __restrict__ h, const float* __restrict__ W2,
          const float* __restrict__ b2, float* __restrict__ out)
{
    const int b = blockIdx.x;
    float v = h[b * 64 + threadIdx.x] * W2[threadIdx.x];
#pragma unroll
    for (int o = 16; o > 0; o >>= 1) v += __shfl_down_sync(0xffffffffu, v, o);
    __shared__ float s2[2];
    if ((threadIdx.x & 31) == 0) s2[threadIdx.x >> 5] = v;
    __syncthreads();
    if (threadIdx.x == 0) out[b] = s2[0] + s2[1] + b2[0];
}

// ---------------------------------------------------------------------------
extern "C" void kernel_launch(void* const* d_in, const int* in_sizes, int n_in,
                              void* d_out, int out_size)
{
    const float* x   = (const float*)d_in[0];
    const float* Sc  = (const float*)d_in[1];
    const float* Sl  = (const float*)d_in[2];
    const float* Wc1 = (const float*)d_in[3];
    const float* bc1 = (const float*)d_in[4];
    const float* Wc2 = (const float*)d_in[5];
    const float* bc2 = (const float*)d_in[6];
    const float* Wl1 = (const float*)d_in[7];
    const float* bl1 = (const float*)d_in[8];
    const float* Wl2 = (const float*)d_in[9];
    const float* bl2 = (const float*)d_in[10];
    const float* Wm1 = (const float*)d_in[11];
    const float* bm1 = (const float*)d_in[12];
    const float* Wm2 = (const float*)d_in[13];
    const float* bm2 = (const float*)d_in[14];
    float* out = (float*)d_out;

    float *z1, *z2, *v0, *v1, *v2, *y32, *y16, *h;
    cudaGetSymbolAddress((void**)&z1,  g_z1);
    cudaGetSymbolAddress((void**)&z2,  g_z2);
    cudaGetSymbolAddress((void**)&v0,  g_v0);
    cudaGetSymbolAddress((void**)&v1,  g_v1);
    cudaGetSymbolAddress((void**)&v2,  g_v2);
    cudaGetSymbolAddress((void**)&y32, g_y32);
    cudaGetSymbolAddress((void**)&y16, g_y16);
    cudaGetSymbolAddress((void**)&h,   g_h);

    const dim3 gG(NNODES / BM, CCOLS / BN);      // 64 x 4 = 256 blocks
    const dim3 gC(NNODES / 256, BATCH);          // combine / proj tiles
    const dim3 gP(NNODES / 256, BATCH, 3);

    // Layer 1 (clique, 16 -> 32): z1 = Sc x ; z2 = Sc z1 ; combine
    gemm_diffuse<0><<<gG, 128>>>(Sc, x,  nullptr, nullptr, z1);
    gemm_diffuse<0><<<gG, 128>>>(Sc, z1, nullptr, nullptr, z2);
    combine_k3<<<gC, 256>>>(x, z1, z2, Wc1, bc1, y32);

    // Layer 2 (clique, 32 -> 16): project then Horner
    proj_k3<<<gP, 256>>>(y32, Wc2, v0, v1, v2);
    gemm_diffuse<1><<<gG, 128>>>(Sc, v2, v1, nullptr, z1);
    gemm_diffuse<2><<<gG, 128>>>(Sc, z1, v0, bc2, y16);

    // Layer 3 (line, 16 -> 32)
    gemm_diffuse<0><<<gG, 128>>>(Sl, y16, nullptr, nullptr, z1);
    gemm_diffuse<0><<<gG, 128>>>(Sl, z1,  nullptr, nullptr, z2);
    combine_k3<<<gC, 256>>>(y16, z1, z2, Wl1, bl1, y32);

    // Layer 4 (line, 32 -> 16)
    proj_k3<<<gP, 256>>>(y32, Wl2, v0, v1, v2);
    gemm_diffuse<1><<<gG, 128>>>(Sl, v2, v1, nullptr, z1);
    gemm_diffuse<2><<<gG, 128>>>(Sl, z1, v0, bl2, y16);

    // MLP head
    mlp1<<<dim3(64, BATCH), 256>>>(y16, Wm1, bm1, h);
    mlp2<<<BATCH, 64>>>(h, Wm2, bm2, out);
}

// round 4
// speedup vs baseline: 3.0074x; 3.0074x over previous
#include <cuda_runtime.h>
#include <cuda_bf16.h>
#include <cstdint>

// ---------------------------------------------------------------------------
// SelectionGNN (clique+line), B=8, N=4096, E=1, K=3, F=[16,32,16]
// Diffusion GEMMs (8x: 128x4096x4096) on mma.sync bf16 (baseline PTX, no
// sm_103a-only features) with hi/lo split: D += Ah*Bh + Ah*Bl + Al*Bh,
// fp32 register accumulation. ldmatrix + cp.async double-buffered.
// ---------------------------------------------------------------------------

#define NNODES 4096
#define BATCH  8
#define CC     128            // channels = B*16 (GEMM M)
#define NT     128            // n-tile per CTA
#define BK     64             // k-tile (bf16) = 128 bytes/row (SW128)
#define SPLITK 4
#define KC     (NNODES / SPLITK)   // 1024 k per CTA
#define NKT    (KC / BK)           // 16 k-tiles

// ---------------- scratch (device globals; allocation is forbidden) --------
__device__ __align__(256) __nv_bfloat16 g_Schi[NNODES * NNODES];
__device__ __align__(256) __nv_bfloat16 g_Sclo[NNODES * NNODES];
__device__ __align__(256) __nv_bfloat16 g_Slhi[NNODES * NNODES];
__device__ __align__(256) __nv_bfloat16 g_Sllo[NNODES * NNODES];
__device__ __align__(256) __nv_bfloat16 g_xhi [CC * NNODES];
__device__ __align__(256) __nv_bfloat16 g_xlo [CC * NNODES];
__device__ __align__(256) __nv_bfloat16 g_ahi [CC * NNODES];
__device__ __align__(256) __nv_bfloat16 g_alo [CC * NNODES];
__device__ __align__(256) __nv_bfloat16 g_bhi [CC * NNODES];
__device__ __align__(256) __nv_bfloat16 g_blo [CC * NNODES];
__device__ __align__(256) float g_part[SPLITK * CC * NNODES];  // 8 MB
__device__ __align__(256) float g_z1f [CC * NNODES];
__device__ __align__(256) float g_z2f [CC * NNODES];
__device__ __align__(256) float g_v0  [CC * NNODES];
__device__ __align__(256) float g_v1  [CC * NNODES];
__device__ __align__(256) float g_y32 [BATCH * 32 * NNODES];
__device__ __align__(256) float g_y16 [CC * NNODES];
__device__ __align__(256) float g_h   [BATCH * 64];

// ---------------- PTX helpers (baseline PTX only) ---------------------------
__device__ __forceinline__ uint32_t smem_u32(const void* p) {
    uint32_t a;
    asm("{ .reg .u64 t; cvta.to.shared.u64 t, %1; cvt.u32.u64 %0, t; }" : "=r"(a) : "l"(p));
    return a;
}
#define CP16(dst, src) asm volatile("cp.async.cg.shared.global [%0], [%1], 16;" :: "r"(dst), "l"(src) : "memory")
#define CP_COMMIT()    asm volatile("cp.async.commit_group;" ::: "memory")
#define CP_WAIT1()     asm volatile("cp.async.wait_group 1;" ::: "memory")
#define CP_WAIT0()     asm volatile("cp.async.wait_group 0;" ::: "memory")

__device__ __forceinline__ void ldsm4(uint32_t& r0, uint32_t& r1, uint32_t& r2,
                                      uint32_t& r3, uint32_t addr) {
    asm volatile("ldmatrix.sync.aligned.m8n8.x4.shared.b16 {%0,%1,%2,%3}, [%4];"
                 : "=r"(r0), "=r"(r1), "=r"(r2), "=r"(r3) : "r"(addr));
}
__device__ __forceinline__ void mma16816(float& d0, float& d1, float& d2, float& d3,
                                         uint32_t a0, uint32_t a1, uint32_t a2, uint32_t a3,
                                         uint32_t b0, uint32_t b1) {
    asm volatile("mma.sync.aligned.m16n8k16.row.col.f32.bf16.bf16.f32 "
                 "{%0,%1,%2,%3}, {%4,%5,%6,%7}, {%8,%9}, {%0,%1,%2,%3};"
                 : "+f"(d0), "+f"(d1), "+f"(d2), "+f"(d3)
                 : "r"(a0), "r"(a1), "r"(a2), "r"(a3), "r"(b0), "r"(b1));
}

// ---------------------------------------------------------------------------
// HMMA diffusion GEMM: part[split][c][n0+n] = sum_{k in split} A[c,k]*B[n0+n,k]
// A = Z hi/lo [128][4096] (row-major, k contig) -> mma A (row.),
// B = S hi/lo [4096][4096] (k contig per n row)  -> mma B (col.).
// grid = (4096/NT, SPLITK) = 32 x 4 = 128 CTAs, 256 threads (8 warps 2x4).
// smem: 2 stages x (Ahi|Alo|Bhi|Blo, 16KB each) = 128KB, SW128-swizzled rows.
// ---------------------------------------------------------------------------
__global__ __launch_bounds__(256, 1)
void gemm_tc(const __nv_bfloat16* __restrict__ Ahi, const __nv_bfloat16* __restrict__ Alo,
             const __nv_bfloat16* __restrict__ Bhi, const __nv_bfloat16* __restrict__ Blo,
             float* __restrict__ part)
{
    extern __shared__ char smem[];
    const uint32_t sb = smem_u32(smem);

    const int tid  = threadIdx.x;
    const int wid  = tid >> 5, lane = tid & 31;
    const int wm   = wid >> 2;            // 0..1 -> m offset wm*64
    const int wn   = wid & 3;             // 0..3 -> n offset wn*32
    const int n0   = blockIdx.x * NT;
    const int split = blockIdx.y;
    const int kbase = split * KC;

    // ---- cp.async producer indexing: thread t loads row t/2, chunks (t&1)*4.. ----
    const int lr  = tid >> 1;             // 0..127
    const int lc0 = (tid & 1) * 4;        // 0 or 4
    const __nv_bfloat16* pAh = Ahi + (size_t)lr * NNODES + kbase;
    const __nv_bfloat16* pAl = Alo + (size_t)lr * NNODES + kbase;
    const __nv_bfloat16* pBh = Bhi + (size_t)(n0 + lr) * NNODES + kbase;
    const __nv_bfloat16* pBl = Blo + (size_t)(n0 + lr) * NNODES + kbase;
    const uint32_t swrow = (uint32_t)lr * 128;
    const int r7 = lr & 7;

    auto load_tile = [&](int tt) {
        const uint32_t st = sb + (uint32_t)(tt & 1) * 65536;
        const int koff = tt * BK;
#pragma unroll
        for (int j = 0; j < 4; j++) {
            const int c = lc0 + j;
            const uint32_t off = swrow + (uint32_t)((c ^ r7) << 4);
            CP16(st + off,         pAh + koff + c * 8);
            CP16(st + 16384 + off, pAl + koff + c * 8);
            CP16(st + 32768 + off, pBh + koff + c * 8);
            CP16(st + 49152 + off, pBl + koff + c * 8);
        }
    };

    // ---- ldmatrix row/seg precompute ----
    const int r8  = lane & 7;
    const int seg = lane >> 3;            // 0..3
    // A x4: seg0: m0-7 klo | seg1: m8-15 klo | seg2: m0-7 khi | seg3: m8-15 khi
    int rowA[4];
#pragma unroll
    for (int mt = 0; mt < 4; mt++)
        rowA[mt] = wm * 64 + mt * 16 + (seg & 1) * 8 + r8;
    const int segAk = seg >> 1;
    // B x4: seg0: nlo klo | seg1: nlo khi | seg2: nhi klo | seg3: nhi khi
    int rowB[2];
#pragma unroll
    for (int p = 0; p < 2; p++)
        rowB[p] = wn * 32 + p * 16 + (seg >> 1) * 8 + r8;
    const int segBk = seg & 1;

    float acc[4][4][4] = {};

    load_tile(0); CP_COMMIT();

#pragma unroll 1
    for (int tt = 0; tt < NKT; tt++) {
        if (tt + 1 < NKT) { load_tile(tt + 1); CP_COMMIT(); CP_WAIT1(); }
        else             { CP_WAIT0(); }
        __syncthreads();

        const uint32_t st = sb + (uint32_t)(tt & 1) * 65536;

#pragma unroll
        for (int ks = 0; ks < 4; ks++) {      // four k16 steps in BK=64
            uint32_t ah[4][4], al[4][4];
#pragma unroll
            for (int mt = 0; mt < 4; mt++) {
                const uint32_t off = (uint32_t)rowA[mt] * 128 +
                    (uint32_t)(((ks * 2 + segAk) ^ (rowA[mt] & 7)) << 4);
                ldsm4(ah[mt][0], ah[mt][1], ah[mt][2], ah[mt][3], st + off);
                ldsm4(al[mt][0], al[mt][1], al[mt][2], al[mt][3], st + 16384 + off);
            }
            uint32_t bh[4][2], bl[4][2];
#pragma unroll
            for (int p = 0; p < 2; p++) {
                const uint32_t off = (uint32_t)rowB[p] * 128 +
                    (uint32_t)(((ks * 2 + segBk) ^ (rowB[p] & 7)) << 4);
                ldsm4(bh[2*p][0], bh[2*p][1], bh[2*p+1][0], bh[2*p+1][1], st + 32768 + off);
                ldsm4(bl[2*p][0], bl[2*p][1], bl[2*p+1][0], bl[2*p+1][1], st + 49152 + off);
            }
#pragma unroll
            for (int mt = 0; mt < 4; mt++)
#pragma unroll
                for (int nt = 0; nt < 4; nt++) {
                    float* d = acc[mt][nt];
                    mma16816(d[0], d[1], d[2], d[3],
                             ah[mt][0], ah[mt][1], ah[mt][2], ah[mt][3],
                             bh[nt][0], bh[nt][1]);
                    mma16816(d[0], d[1], d[2], d[3],
                             ah[mt][0], ah[mt][1], ah[mt][2], ah[mt][3],
                             bl[nt][0], bl[nt][1]);
                    mma16816(d[0], d[1], d[2], d[3],
                             al[mt][0], al[mt][1], al[mt][2], al[mt][3],
                             bh[nt][0], bh[nt][1]);
                }
        }
        __syncthreads();
    }

    // ---- epilogue: D frag -> part[(split*128 + c) * 4096 + n] ----
    const int mrow = lane >> 2;           // 0..7
    const int ncol = (lane & 3) * 2;      // 0,2,4,6
#pragma unroll
    for (int mt = 0; mt < 4; mt++) {
#pragma unroll
        for (int nt = 0; nt < 4; nt++) {
            const int c = wm * 64 + mt * 16 + mrow;
            const int n = n0 + wn * 32 + nt * 8 + ncol;
            float* d0 = part + ((size_t)(split * CC + c)) * NNODES + n;
            float* d1 = part + ((size_t)(split * CC + c + 8)) * NNODES + n;
            *reinterpret_cast<float2*>(d0) = make_float2(acc[mt][nt][0], acc[mt][nt][1]);
            *reinterpret_cast<float2*>(d1) = make_float2(acc[mt][nt][2], acc[mt][nt][3]);
        }
    }
}

// ---------------------------------------------------------------------------
// fp32 -> (bf16 hi, bf16 lo) split, float4 granularity
// ---------------------------------------------------------------------------
__device__ __forceinline__ void split4(float4 a, uint2& H, uint2& L) {
    __nv_bfloat16 h0 = __float2bfloat16(a.x), h1 = __float2bfloat16(a.y);
    __nv_bfloat16 h2 = __float2bfloat16(a.z), h3 = __float2bfloat16(a.w);
    __nv_bfloat16 l0 = __float2bfloat16(a.x - __bfloat162float(h0));
    __nv_bfloat16 l1 = __float2bfloat16(a.y - __bfloat162float(h1));
    __nv_bfloat16 l2 = __float2bfloat16(a.z - __bfloat162float(h2));
    __nv_bfloat16 l3 = __float2bfloat16(a.w - __bfloat162float(h3));
    H.x = ((uint32_t)__bfloat16_as_ushort(h1) << 16) | __bfloat16_as_ushort(h0);
    H.y = ((uint32_t)__bfloat16_as_ushort(h3) << 16) | __bfloat16_as_ushort(h2);
    L.x = ((uint32_t)__bfloat16_as_ushort(l1) << 16) | __bfloat16_as_ushort(l0);
    L.y = ((uint32_t)__bfloat16_as_ushort(l3) << 16) | __bfloat16_as_ushort(l2);
}

__global__ __launch_bounds__(256)
void cvt_hilo(const float4* __restrict__ in, uint2* __restrict__ hi,
              uint2* __restrict__ lo, int n4)
{
    int i = blockIdx.x * 256 + threadIdx.x;
    if (i >= n4) return;
    uint2 H, L;
    split4(in[i], H, L);
    hi[i] = H; lo[i] = L;
}

// ---------------------------------------------------------------------------
// split-K reduce + epilogue. MODE 0: Y = sum; 1: Y = sum + V; 2: relu(sum+V+b)
// ---------------------------------------------------------------------------
template <int MODE>
__global__ __launch_bounds__(256)
void reduce_splitk(const float* __restrict__ part, const float* __restrict__ V,
                   const float* __restrict__ bias, float* __restrict__ Yf,
                   uint2* __restrict__ Yhi, uint2* __restrict__ Ylo)
{
    const int i = blockIdx.x * 256 + threadIdx.x;          // float4 index
    const float4* p = reinterpret_cast<const float4*>(part);
    const int STR = CC * NNODES / 4;
    float4 a = p[i];
    float4 b = p[i + STR];
    float4 c = p[i + 2 * STR];
    float4 d = p[i + 3 * STR];
    a.x += b.x + c.x + d.x; a.y += b.y + c.y + d.y;
    a.z += b.z + c.z + d.z; a.w += b.w + c.w + d.w;
    if (MODE >= 1) {
        float4 v = reinterpret_cast<const float4*>(V)[i];
        a.x += v.x; a.y += v.y; a.z += v.z; a.w += v.w;
    }
    if (MODE == 2) {
        const int ch = (i >> 10) & (CC - 1);               // 1024 float4 per row
        const float bv = bias[ch & 15];
        a.x = fmaxf(a.x + bv, 0.f); a.y = fmaxf(a.y + bv, 0.f);
        a.z = fmaxf(a.z + bv, 0.f); a.w = fmaxf(a.w + bv, 0.f);
    }
    if (Yf) reinterpret_cast<float4*>(Yf)[i] = a;
    if (Yhi) {
        uint2 H, L;
        split4(a, H, L);
        Yhi[i] = H; Ylo[i] = L;
    }
}

// ---------------------------------------------------------------------------
// Combine (16 -> 32): out[b,g,n] = relu(bias[g] + sum_{k,f} W[g,k,f] z_k[b,f,n])
// ---------------------------------------------------------------------------
__global__ __launch_bounds__(256)
void combine_k3(const float* __restrict__ z0, const float* __restrict__ z1,
                const float* __restrict__ z2, const float* __restrict__ W,
                const float* __restrict__ bias, float* __restrict__ out)
{
    __shared__ float Ws[32 * 48];
    const int tid = threadIdx.x;
    for (int i = tid; i < 32 * 48; i += 256) Ws[i] = W[i];
    __syncthreads();

    const int n = blockIdx.x * 256 + tid;
    const int b = blockIdx.y;
    float acc[32];
#pragma unroll
    for (int g = 0; g < 32; g++) acc[g] = bias[g];
    const float* zs[3] = {z0, z1, z2};
#pragma unroll
    for (int k = 0; k < 3; k++) {
        const float* z = zs[k];
#pragma unroll
        for (int f = 0; f < 16; f++) {
            float zv = z[((size_t)b * 16 + f) * NNODES + n];
#pragma unroll
            for (int g = 0; g < 32; g++) acc[g] += Ws[g * 48 + k * 16 + f] * zv;
        }
    }
#pragma unroll
    for (int g = 0; g < 32; g++)
        out[((size_t)b * 32 + g) * NNODES + n] = fmaxf(acc[g], 0.f);
}

// ---------------------------------------------------------------------------
// Projection (32 -> 16): v_k[b,g,n] = sum_f W[g,k,f] x[b,f,n]
// k=0,1 -> fp32 (V operands); k=2 -> bf16 hi/lo (MMA A operand)
// ---------------------------------------------------------------------------
__global__ __launch_bounds__(256)
void proj_k3(const float* __restrict__ in, const float* __restrict__ W,
             float* __restrict__ v0, float* __restrict__ v1,
             __nv_bfloat16* __restrict__ v2hi, __nv_bfloat16* __restrict__ v2lo)
{
    const int k = blockIdx.z;
    __shared__ float Ws[16 * 32];
    const int tid = threadIdx.x;
    for (int i = tid; i < 16 * 32; i += 256)
        Ws[i] = W[(i >> 5) * 96 + k * 32 + (i & 31)];
    __syncthreads();

    const int n = blockIdx.x * 256 + tid;
    const int b = blockIdx.y;
    float acc[16] = {};
#pragma unroll
    for (int f = 0; f < 32; f++) {
        float xv = in[((size_t)b * 32 + f) * NNODES + n];
#pragma unroll
        for (int g = 0; g < 16; g++) acc[g] += Ws[g * 32 + f] * xv;
    }
    if (k < 2) {
        float* v = (k == 0) ? v0 : v1;
#pragma unroll
        for (int g = 0; g < 16; g++)
            v[((size_t)b * 16 + g) * NNODES + n] = acc[g];
    } else {
#pragma unroll
        for (int g = 0; g < 16; g++) {
            size_t o = ((size_t)b * 16 + g) * NNODES + n;
            __nv_bfloat16 h = __float2bfloat16(acc[g]);
            v2hi[o] = h;
            v2lo[o] = __float2bfloat16(acc[g] - __bfloat162float(h));
        }
    }
}

// ---------------------------------------------------------------------------
// MLP head
// ---------------------------------------------------------------------------
__global__ __launch_bounds__(256)
void mlp1(const float* __restrict__ y, const float* __restrict__ W1,
          const float* __restrict__ b1, float* __restrict__ h)
{
    const int jg = blockIdx.x;   // 8 groups of 8 outputs
    const int b  = blockIdx.y;
    const float4* yb = reinterpret_cast<const float4*>(y + (size_t)b * 65536);
    float s[8] = {};
    for (int i = threadIdx.x; i < 16384; i += 256) {
        float4 a = yb[i];
#pragma unroll
        for (int jj = 0; jj < 8; jj++) {
            float4 w = reinterpret_cast<const float4*>(W1 + (size_t)(jg * 8 + jj) * 65536)[i];
            s[jj] += a.x * w.x + a.y * w.y + a.z * w.z + a.w * w.w;
        }
    }
    __shared__ float red[8][8];
    const int wid = threadIdx.x >> 5, lane = threadIdx.x & 31;
#pragma unroll
    for (int jj = 0; jj < 8; jj++) {
#pragma unroll
        for (int o = 16; o > 0; o >>= 1) s[jj] += __shfl_down_sync(0xffffffffu, s[jj], o);
    }
    if (lane == 0)
#pragma unroll
        for (int jj = 0; jj < 8; jj++) red[wid][jj] = s[jj];
    __syncthreads();
    if (threadIdx.x < 8) {
        float t = 0.f;
#pragma unroll
        for (int w = 0; w < 8; w++) t += red[w][threadIdx.x];
        h[b * 64 + jg * 8 + threadIdx.x] = fmaxf(t + b1[jg * 8 + threadIdx.x], 0.f);
    }
}

__global__ __launch_bounds__(64)
void mlp2(const float* __restrict__ h, const float* __restrict__ W2,
          const float* __restrict__ b2, float* __restrict__ out)
{
    const int b = blockIdx.x;
    float v = h[b * 64 + threadIdx.x] * W2[threadIdx.x];
#pragma unroll
    for (int o = 16; o > 0; o >>= 1) v += __shfl_down_sync(0xffffffffu, v, o);
    __shared__ float s2[2];
    if ((threadIdx.x & 31) == 0) s2[threadIdx.x >> 5] = v;
    __syncthreads();
    if (threadIdx.x == 0) out[b] = s2[0] + s2[1] + b2[0];
}

// ---------------------------------------------------------------------------
extern "C" void kernel_launch(void* const* d_in, const int* in_sizes, int n_in,
                              void* d_out, int out_size)
{
    const float* x   = (const float*)d_in[0];
    const float* Sc  = (const float*)d_in[1];
    const float* Sl  = (const float*)d_in[2];
    const float* Wc1 = (const float*)d_in[3];
    const float* bc1 = (const float*)d_in[4];
    const float* Wc2 = (const float*)d_in[5];
    const float* bc2 = (const float*)d_in[6];
    const float* Wl1 = (const float*)d_in[7];
    const float* bl1 = (const float*)d_in[8];
    const float* Wl2 = (const float*)d_in[9];
    const float* bl2 = (const float*)d_in[10];
    const float* Wm1 = (const float*)d_in[11];
    const float* bm1 = (const float*)d_in[12];
    const float* Wm2 = (const float*)d_in[13];
    const float* bm2 = (const float*)d_in[14];
    float* out = (float*)d_out;

    cudaFuncSetAttribute(gemm_tc, cudaFuncAttributeMaxDynamicSharedMemorySize, 2 * 65536);

    __nv_bfloat16 *Schi, *Sclo, *Slhi, *Sllo, *xhi, *xlo, *ahi, *alo, *bhi, *blo;
    float *part, *z1f, *z2f, *v0, *v1, *y32, *y16, *h;
    cudaGetSymbolAddress((void**)&Schi, g_Schi); cudaGetSymbolAddress((void**)&Sclo, g_Sclo);
    cudaGetSymbolAddress((void**)&Slhi, g_Slhi); cudaGetSymbolAddress((void**)&Sllo, g_Sllo);
    cudaGetSymbolAddress((void**)&xhi, g_xhi);   cudaGetSymbolAddress((void**)&xlo, g_xlo);
    cudaGetSymbolAddress((void**)&ahi, g_ahi);   cudaGetSymbolAddress((void**)&alo, g_alo);
    cudaGetSymbolAddress((void**)&bhi, g_bhi);   cudaGetSymbolAddress((void**)&blo, g_blo);
    cudaGetSymbolAddress((void**)&part, g_part);
    cudaGetSymbolAddress((void**)&z1f, g_z1f);   cudaGetSymbolAddress((void**)&z2f, g_z2f);
    cudaGetSymbolAddress((void**)&v0, g_v0);     cudaGetSymbolAddress((void**)&v1, g_v1);
    cudaGetSymbolAddress((void**)&y32, g_y32);   cudaGetSymbolAddress((void**)&y16, g_y16);
    cudaGetSymbolAddress((void**)&h, g_h);

    const int SN4 = NNODES * NNODES / 4;          // 4M float4
    const int XN4 = CC * NNODES / 4;              // 128K float4
    cvt_hilo<<<SN4 / 256, 256>>>((const float4*)Sc, (uint2*)Schi, (uint2*)Sclo, SN4);
    cvt_hilo<<<SN4 / 256, 256>>>((const float4*)Sl, (uint2*)Slhi, (uint2*)Sllo, SN4);
    cvt_hilo<<<XN4 / 256, 256>>>((const float4*)x,  (uint2*)xhi,  (uint2*)xlo,  XN4);

    const dim3 gG(NNODES / NT, SPLITK);           // 32 x 4 = 128 CTAs
    const int  SM = 2 * 65536;
    const dim3 gR(CC * NNODES / 4 / 256);         // 512 blocks
    const dim3 gC(NNODES / 256, BATCH);
    const dim3 gP(NNODES / 256, BATCH, 3);

    // ---- Layer 1 (clique, 16 -> 32) ----
    gemm_tc<<<gG, 256, SM>>>(xhi, xlo, Schi, Sclo, part);
    reduce_splitk<0><<<gR, 256>>>(part, nullptr, nullptr, z1f, (uint2*)ahi, (uint2*)alo);
    gemm_tc<<<gG, 256, SM>>>(ahi, alo, Schi, Sclo, part);
    reduce_splitk<0><<<gR, 256>>>(part, nullptr, nullptr, z2f, nullptr, nullptr);
    combine_k3<<<gC, 256>>>(x, z1f, z2f, Wc1, bc1, y32);

    // ---- Layer 2 (clique, 32 -> 16): project then Horner ----
    proj_k3<<<gP, 256>>>(y32, Wc2, v0, v1, bhi, blo);
    gemm_tc<<<gG, 256, SM>>>(bhi, blo, Schi, Sclo, part);
    reduce_splitk<1><<<gR, 256>>>(part, v1, nullptr, nullptr, (uint2*)ahi, (uint2*)alo);
    gemm_tc<<<gG, 256, SM>>>(ahi, alo, Schi, Sclo, part);
    reduce_splitk<2><<<gR, 256>>>(part, v0, bc2, y16, (uint2*)bhi, (uint2*)blo);

    // ---- Layer 3 (line, 16 -> 32) ----
    gemm_tc<<<gG, 256, SM>>>(bhi, blo, Slhi, Sllo, part);
    reduce_splitk<0><<<gR, 256>>>(part, nullptr, nullptr, z1f, (uint2*)ahi, (uint2*)alo);
    gemm_tc<<<gG, 256, SM>>>(ahi, alo, Slhi, Sllo, part);
    reduce_splitk<0><<<gR, 256>>>(part, nullptr, nullptr, z2f, nullptr, nullptr);
    combine_k3<<<gC, 256>>>(y16, z1f, z2f, Wl1, bl1, y32);

    // ---- Layer 4 (line, 32 -> 16) ----
    proj_k3<<<gP, 256>>>(y32, Wl2, v0, v1, bhi, blo);
    gemm_tc<<<gG, 256, SM>>>(bhi, blo, Slhi, Sllo, part);
    reduce_splitk<1><<<gR, 256>>>(part, v1, nullptr, nullptr, (uint2*)ahi, (uint2*)alo);
    gemm_tc<<<gG, 256, SM>>>(ahi, alo, Slhi, Sllo, part);
    reduce_splitk<2><<<gR, 256>>>(part, v0, bl2, y16, nullptr, nullptr);

    // ---- MLP head ----
    mlp1<<<dim3(8, BATCH), 256>>>(y16, Wm1, bm1, h);
    mlp2<<<BATCH, 64>>>(h, Wm2, bm2, out);
}

// round 5
// speedup vs baseline: 3.5935x; 1.1949x over previous
#include <cuda_runtime.h>
#include <cuda_bf16.h>
#include <cstdint>

// ---------------------------------------------------------------------------
// SelectionGNN (clique+line), B=8, N=4096, E=1, K=3, F=[16,32,16]
// Diffusion GEMMs (8x: 128x4096x4096) on mma.sync bf16 hi/lo split
// (D += Ah*Bh + Ah*Bl + Al*Bh, fp32 accum). Loads via cp.async.bulk (TMA,
// one 256B op per row covering hi+lo) into 272B-stride padded smem rows
// (conflict-free ldmatrix without swizzle). 3-stage mbarrier pipeline.
//
// Combined operand layout: row r of a [R][4096] fp32 matrix is stored as
// [R][8192] bf16: k-tile kt (64 k) -> elements [kt*128, kt*128+64) = hi,
// [kt*128+64, kt*128+128) = lo.
// ---------------------------------------------------------------------------

#define NNODES 4096
#define BATCH  8
#define CC     128            // channels = B*16 (GEMM M)
#define NT     128            // n-tile per CTA
#define SPLITK 4
#define KC     (NNODES / SPLITK)   // 1024 k per CTA
#define NKT    (KC / 64)           // 16 k-tiles (64 k each)

#define ROWSTR   272               // 256B data + 16B pad
#define TILESZ   (128 * ROWSTR)    // 34816
#define STAGESZ  (2 * TILESZ)      // A tile + B tile = 69632
#define NSTAGE   3
#define SMEMSZ   (64 + NSTAGE * STAGESZ)   // 208960

// ---------------- scratch (device globals; allocation is forbidden) --------
__device__ __align__(256) __nv_bfloat16 g_Sc2[NNODES * 2 * NNODES]; // 64MB
__device__ __align__(256) __nv_bfloat16 g_Sl2[NNODES * 2 * NNODES]; // 64MB
__device__ __align__(256) __nv_bfloat16 g_x2 [CC * 2 * NNODES];
__device__ __align__(256) __nv_bfloat16 g_a2 [CC * 2 * NNODES];
__device__ __align__(256) __nv_bfloat16 g_b2 [CC * 2 * NNODES];
__device__ __align__(256) float g_part[SPLITK * CC * NNODES];  // 8 MB
__device__ __align__(256) float g_z1f [CC * NNODES];
__device__ __align__(256) float g_z2f [CC * NNODES];
__device__ __align__(256) float g_v0  [CC * NNODES];
__device__ __align__(256) float g_v1  [CC * NNODES];
__device__ __align__(256) float g_y32 [BATCH * 32 * NNODES];
__device__ __align__(256) float g_y16 [CC * NNODES];
__device__ __align__(256) float g_hp  [8 * BATCH * 64];

// ---------------- PTX helpers (baseline sm_90-level PTX only) ---------------
__device__ __forceinline__ uint32_t smem_u32(const void* p) {
    uint32_t a;
    asm("{ .reg .u64 t; cvta.to.shared.u64 t, %1; cvt.u32.u64 %0, t; }" : "=r"(a) : "l"(p));
    return a;
}
#define MBAR_INIT(a, c) asm volatile("mbarrier.init.shared.b64 [%0], %1;" :: "r"(a), "r"(c) : "memory")

#define MBAR_WAIT(mbar, par) do {                                              \
    uint32_t _m = (mbar), _p = (par), _d;                                      \
    asm volatile("{ .reg .pred p;"                                             \
        " mbarrier.try_wait.parity.acquire.cta.shared::cta.b64 p, [%1], %2;"   \
        " selp.b32 %0, 1, 0, p; }" : "=r"(_d) : "r"(_m), "r"(_p) : "memory");  \
    if (!_d) {                                                                 \
        asm volatile("{ .reg .pred P1;"                                        \
        " W%=: mbarrier.try_wait.parity.acquire.cta.shared::cta.b64 P1, [%0], %1, 0x989680;" \
        " @P1 bra.uni D%=; bra.uni W%=; D%=: }" :: "r"(_m), "r"(_p) : "memory"); } \
} while (0)

#define MBAR_EXPECT(mbar, bytes) \
    asm volatile("mbarrier.arrive.expect_tx.shared.b64 _, [%0], %1;" :: "r"(mbar), "r"(bytes) : "memory")

#define BULK_G2S(dst, src, bytes, mbar) \
    asm volatile("cp.async.bulk.shared::cluster.global.mbarrier::complete_tx::bytes [%0], [%1], %2, [%3];" \
                 :: "r"(dst), "l"(src), "r"(bytes), "r"(mbar) : "memory")

__device__ __forceinline__ void ldsm4(uint32_t& r0, uint32_t& r1, uint32_t& r2,
                                      uint32_t& r3, uint32_t addr) {
    asm volatile("ldmatrix.sync.aligned.m8n8.x4.shared.b16 {%0,%1,%2,%3}, [%4];"
                 : "=r"(r0), "=r"(r1), "=r"(r2), "=r"(r3) : "r"(addr));
}
__device__ __forceinline__ void mma16816(float& d0, float& d1, float& d2, float& d3,
                                         uint32_t a0, uint32_t a1, uint32_t a2, uint32_t a3,
                                         uint32_t b0, uint32_t b1) {
    asm volatile("mma.sync.aligned.m16n8k16.row.col.f32.bf16.bf16.f32 "
                 "{%0,%1,%2,%3}, {%4,%5,%6,%7}, {%8,%9}, {%0,%1,%2,%3};"
                 : "+f"(d0), "+f"(d1), "+f"(d2), "+f"(d3)
                 : "r"(a0), "r"(a1), "r"(a2), "r"(a3), "r"(b0), "r"(b1));
}

// ---------------------------------------------------------------------------
// HMMA diffusion GEMM: part[split][c][n0+n] = sum_{k in split} A[c,k]*B[n0+n,k]
// A2/B2 in combined hi|lo layout. grid = (32, SPLITK), 256 threads (8 warps).
// ---------------------------------------------------------------------------
__global__ __launch_bounds__(256, 1)
void gemm_tc(const __nv_bfloat16* __restrict__ A2,
             const __nv_bfloat16* __restrict__ B2,
             float* __restrict__ part)
{
    extern __shared__ __align__(16) char smem[];
    const uint32_t sb  = smem_u32(smem);
    const uint32_t st0 = sb + 64;

    const int tid  = threadIdx.x;
    const int wid  = tid >> 5, lane = tid & 31;
    const int wm   = wid >> 2;            // 0..1 -> m offset wm*64
    const int wn   = wid & 3;             // 0..3 -> n offset wn*32
    const int n0   = blockIdx.x * NT;
    const int split = blockIdx.y;

    // ---- producer: one 256B bulk op per thread per k-tile ----
    const int ptile = tid >> 7;           // 0 = A, 1 = B
    const int prow  = tid & 127;
    const __nv_bfloat16* src_base =
        (ptile == 0 ? A2 + (size_t)prow * (2 * NNODES)
                    : B2 + (size_t)(n0 + prow) * (2 * NNODES))
        + (size_t)split * (2 * KC);
    const uint32_t dst_off = (uint32_t)(ptile * TILESZ + prow * ROWSTR);

    if (tid == 0) {
        MBAR_INIT(sb + 0, 256);
        MBAR_INIT(sb + 8, 256);
        MBAR_INIT(sb + 16, 256);
    }
    __syncthreads();

    auto load_tile = [&](int tt) {
        const uint32_t s    = (uint32_t)(tt % 3);
        const uint32_t mbar = sb + s * 8;
        const uint32_t dst  = st0 + s * STAGESZ + dst_off;
        const __nv_bfloat16* src = src_base + tt * 128;
        MBAR_EXPECT(mbar, 256u);
        BULK_G2S(dst, src, 256u, mbar);
    };

    load_tile(0); load_tile(1); load_tile(2);

    // ---- ldmatrix row offsets (within a tile) ----
    const int r8  = lane & 7;
    const int seg = lane >> 3;            // 0..3
    const int sak = seg >> 1;             // A: k8 selector
    const int sam = seg & 1;              // A: m8 selector
    uint32_t rowOffA[4];
#pragma unroll
    for (int mt = 0; mt < 4; mt++)
        rowOffA[mt] = (uint32_t)(wm * 64 + mt * 16 + sam * 8 + r8) * ROWSTR;
    uint32_t rowOffB[2];
#pragma unroll
    for (int p = 0; p < 2; p++)
        rowOffB[p] = (uint32_t)(wn * 32 + p * 16 + sak * 8 + r8) * ROWSTR;
    const int sbk = seg & 1;              // B: k8 selector

    float acc[4][4][4] = {};

#pragma unroll 1
    for (int tt = 0; tt < NKT; tt++) {
        const uint32_t s = (uint32_t)(tt % 3);
        MBAR_WAIT(sb + s * 8, (uint32_t)((tt / 3) & 1));

        const uint32_t stA = st0 + s * STAGESZ;
        const uint32_t stB = stA + TILESZ;

#pragma unroll
        for (int ks = 0; ks < 4; ks++) {
            uint32_t ah[4][4], al[4][4];
#pragma unroll
            for (int mt = 0; mt < 4; mt++) {
                const uint32_t a = stA + rowOffA[mt] + (uint32_t)((ks * 2 + sak) << 4);
                ldsm4(ah[mt][0], ah[mt][1], ah[mt][2], ah[mt][3], a);
                ldsm4(al[mt][0], al[mt][1], al[mt][2], al[mt][3], a + 128);
            }
            uint32_t bh[4][2], bl[4][2];
#pragma unroll
            for (int p = 0; p < 2; p++) {
                const uint32_t b = stB + rowOffB[p] + (uint32_t)((ks * 2 + sbk) << 4);
                ldsm4(bh[2*p][0], bh[2*p][1], bh[2*p+1][0], bh[2*p+1][1], b);
                ldsm4(bl[2*p][0], bl[2*p][1], bl[2*p+1][0], bl[2*p+1][1], b + 128);
            }
#pragma unroll
            for (int mt = 0; mt < 4; mt++)
#pragma unroll
                for (int nt = 0; nt < 4; nt++) {
                    float* d = acc[mt][nt];
                    mma16816(d[0], d[1], d[2], d[3],
                             ah[mt][0], ah[mt][1], ah[mt][2], ah[mt][3],
                             bh[nt][0], bh[nt][1]);
                    mma16816(d[0], d[1], d[2], d[3],
                             ah[mt][0], ah[mt][1], ah[mt][2], ah[mt][3],
                             bl[nt][0], bl[nt][1]);
                    mma16816(d[0], d[1], d[2], d[3],
                             al[mt][0], al[mt][1], al[mt][2], al[mt][3],
                             bh[nt][0], bh[nt][1]);
                }
        }
        __syncthreads();                   // all warps done with stage s
        if (tt + 3 < NKT) load_tile(tt + 3);
    }

    // ---- epilogue: D frag -> part[(split*128 + c) * 4096 + n] ----
    const int mrow = lane >> 2;           // 0..7
    const int ncol = (lane & 3) * 2;      // 0,2,4,6
#pragma unroll
    for (int mt = 0; mt < 4; mt++) {
#pragma unroll
        for (int nt = 0; nt < 4; nt++) {
            const int c = wm * 64 + mt * 16 + mrow;
            const int n = n0 + wn * 32 + nt * 8 + ncol;
            float* d0 = part + ((size_t)(split * CC + c)) * NNODES + n;
            float* d1 = part + ((size_t)(split * CC + c + 8)) * NNODES + n;
            *reinterpret_cast<float2*>(d0) = make_float2(acc[mt][nt][0], acc[mt][nt][1]);
            *reinterpret_cast<float2*>(d1) = make_float2(acc[mt][nt][2], acc[mt][nt][3]);
        }
    }
}

// ---------------------------------------------------------------------------
// fp32 -> combined hi|lo bf16 layout, float4 granularity
// row = (idx4*4)>>12 (rows of length 4096), k = (idx4*4)&4095
// out[row*8192 + (k>>6)*128 + (k&63)] = hi, +64 = lo
// ---------------------------------------------------------------------------
__device__ __forceinline__ void split4(float4 a, uint2& H, uint2& L) {
    __nv_bfloat16 h0 = __float2bfloat16(a.x), h1 = __float2bfloat16(a.y);
    __nv_bfloat16 h2 = __float2bfloat16(a.z), h3 = __float2bfloat16(a.w);
    __nv_bfloat16 l0 = __float2bfloat16(a.x - __bfloat162float(h0));
    __nv_bfloat16 l1 = __float2bfloat16(a.y - __bfloat162float(h1));
    __nv_bfloat16 l2 = __float2bfloat16(a.z - __bfloat162float(h2));
    __nv_bfloat16 l3 = __float2bfloat16(a.w - __bfloat162float(h3));
    H.x = ((uint32_t)__bfloat16_as_ushort(h1) << 16) | __bfloat16_as_ushort(h0);
    H.y = ((uint32_t)__bfloat16_as_ushort(h3) << 16) | __bfloat16_as_ushort(h2);
    L.x = ((uint32_t)__bfloat16_as_ushort(l1) << 16) | __bfloat16_as_ushort(l0);
    L.y = ((uint32_t)__bfloat16_as_ushort(l3) << 16) | __bfloat16_as_ushort(l2);
}

__global__ __launch_bounds__(256)
void cvt2(const float4* __restrict__ in, __nv_bfloat16* __restrict__ out, int n4)
{
    int i = blockIdx.x * 256 + threadIdx.x;
    if (i >= n4) return;
    uint2 H, L;
    split4(in[i], H, L);
    const int e   = i * 4;
    const int row = e >> 12, k = e & 4095;
    const size_t base = (size_t)row * 8192 + ((k >> 6) << 7) + (k & 63);
    *reinterpret_cast<uint2*>(out + base)      = H;
    *reinterpret_cast<uint2*>(out + base + 64) = L;
}

// ---------------------------------------------------------------------------
// split-K reduce + epilogue. MODE 0: Y = sum; 1: Y = sum + V; 2: relu(sum+V+b)
// Writes fp32 (if Yf) and combined bf16 (if Y2).
// ---------------------------------------------------------------------------
template <int MODE>
__global__ __launch_bounds__(256)
void reduce_splitk(const float* __restrict__ part, const float* __restrict__ V,
                   const float* __restrict__ bias, float* __restrict__ Yf,
                   __nv_bfloat16* __restrict__ Y2)
{
    const int i = blockIdx.x * 256 + threadIdx.x;          // float4 index
    const float4* p = reinterpret_cast<const float4*>(part);
    const int STR = CC * NNODES / 4;
    float4 a = p[i];
    float4 b = p[i + STR];
    float4 c = p[i + 2 * STR];
    float4 d = p[i + 3 * STR];
    a.x += b.x + c.x + d.x; a.y += b.y + c.y + d.y;
    a.z += b.z + c.z + d.z; a.w += b.w + c.w + d.w;
    if (MODE >= 1) {
        float4 v = reinterpret_cast<const float4*>(V)[i];
        a.x += v.x; a.y += v.y; a.z += v.z; a.w += v.w;
    }
    const int e   = i * 4;
    const int ch  = e >> 12;                               // 0..127
    if (MODE == 2) {
        const float bv = bias[ch & 15];
        a.x = fmaxf(a.x + bv, 0.f); a.y = fmaxf(a.y + bv, 0.f);
        a.z = fmaxf(a.z + bv, 0.f); a.w = fmaxf(a.w + bv, 0.f);
    }
    if (Yf) reinterpret_cast<float4*>(Yf)[i] = a;
    if (Y2) {
        uint2 H, L;
        split4(a, H, L);
        const int k = e & 4095;
        const size_t base = (size_t)ch * 8192 + ((k >> 6) << 7) + (k & 63);
        *reinterpret_cast<uint2*>(Y2 + base)      = H;
        *reinterpret_cast<uint2*>(Y2 + base + 64) = L;
    }
}

// ---------------------------------------------------------------------------
// Combine (16 -> 32): out[b,g,n] = relu(bias[g] + sum_{k,f} W[g,k,f] z_k[b,f,n])
// ---------------------------------------------------------------------------
__global__ __launch_bounds__(256)
void combine_k3(const float* __restrict__ z0, const float* __restrict__ z1,
                const float* __restrict__ z2, const float* __restrict__ W,
                const float* __restrict__ bias, float* __restrict__ out)
{
    __shared__ float Ws[32 * 48];
    const int tid = threadIdx.x;
    for (int i = tid; i < 32 * 48; i += 256) Ws[i] = W[i];
    __syncthreads();

    const int n = blockIdx.x * 256 + tid;
    const int b = blockIdx.y;
    float acc[32];
#pragma unroll
    for (int g = 0; g < 32; g++) acc[g] = bias[g];
    const float* zs[3] = {z0, z1, z2};
#pragma unroll
    for (int k = 0; k < 3; k++) {
        const float* z = zs[k];
#pragma unroll
        for (int f = 0; f < 16; f++) {
            float zv = z[((size_t)b * 16 + f) * NNODES + n];
#pragma unroll
            for (int g = 0; g < 32; g++) acc[g] += Ws[g * 48 + k * 16 + f] * zv;
        }
    }
#pragma unroll
    for (int g = 0; g < 32; g++)
        out[((size_t)b * 32 + g) * NNODES + n] = fmaxf(acc[g], 0.f);
}

// ---------------------------------------------------------------------------
// Projection (32 -> 16): v_k[b,g,n] = sum_f W[g,k,f] x[b,f,n]
// k=0,1 -> fp32; k=2 -> combined bf16 hi|lo (next MMA A operand)
// ---------------------------------------------------------------------------
__global__ __launch_bounds__(256)
void proj_k3(const float* __restrict__ in, const float* __restrict__ W,
             float* __restrict__ v0, float* __restrict__ v1,
             __nv_bfloat16* __restrict__ v2c)
{
    const int k = blockIdx.z;
    __shared__ float Ws[16 * 32];
    const int tid = threadIdx.x;
    for (int i = tid; i < 16 * 32; i += 256)
        Ws[i] = W[(i >> 5) * 96 + k * 32 + (i & 31)];
    __syncthreads();

    const int n = blockIdx.x * 256 + tid;
    const int b = blockIdx.y;
    float acc[16] = {};
#pragma unroll
    for (int f = 0; f < 32; f++) {
        float xv = in[((size_t)b * 32 + f) * NNODES + n];
#pragma unroll
        for (int g = 0; g < 16; g++) acc[g] += Ws[g * 32 + f] * xv;
    }
    if (k < 2) {
        float* v = (k == 0) ? v0 : v1;
#pragma unroll
        for (int g = 0; g < 16; g++)
            v[((size_t)b * 16 + g) * NNODES + n] = acc[g];
    } else {
        const size_t kpos = (size_t)((n >> 6) << 7) + (n & 63);
#pragma unroll
        for (int g = 0; g < 16; g++) {
            const size_t o = (size_t)(b * 16 + g) * 8192 + kpos;
            __nv_bfloat16 h = __float2bfloat16(acc[g]);
            v2c[o]      = h;
            v2c[o + 64] = __float2bfloat16(acc[g] - __bfloat162float(h));
        }
    }
}

// ---------------------------------------------------------------------------
// MLP head. mlp1b: partial dot products, grid (8 j-groups, 8 k-slices).
// hp[ks][b][j] ; mlp2b sums slices, bias+relu, then final dot.
// ---------------------------------------------------------------------------
__global__ __launch_bounds__(256)
void mlp1b(const float* __restrict__ y, const float* __restrict__ W1,
           float* __restrict__ hp)
{
    const int jg = blockIdx.x;    // 8 groups of 8 outputs
    const int ks = blockIdx.y;    // 8 k-slices of 2048 float4
    const float4* Y4 = reinterpret_cast<const float4*>(y);
    const float4* W4 = reinterpret_cast<const float4*>(W1);

    float s[8][8] = {};           // [jj][b]
    for (int i = threadIdx.x; i < 2048; i += 256) {
        const int off = ks * 2048 + i;
        float4 yv[8];
#pragma unroll
        for (int b = 0; b < 8; b++) yv[b] = Y4[(size_t)b * 16384 + off];
#pragma unroll
        for (int jj = 0; jj < 8; jj++) {
            float4 w = W4[(size_t)(jg * 8 + jj) * 16384 + off];
#pragma unroll
            for (int b = 0; b < 8; b++)
                s[jj][b] += yv[b].x * w.x + yv[b].y * w.y + yv[b].z * w.z + yv[b].w * w.w;
        }
    }
    __shared__ float red[8][64];  // [warp][jj*8+b]
    const int wid = threadIdx.x >> 5, lane = threadIdx.x & 31;
#pragma unroll
    for (int jj = 0; jj < 8; jj++)
#pragma unroll
        for (int b = 0; b < 8; b++) {
            float v = s[jj][b];
#pragma unroll
            for (int o = 16; o > 0; o >>= 1) v += __shfl_down_sync(0xffffffffu, v, o);
            if (lane == 0) red[wid][jj * 8 + b] = v;
        }
    __syncthreads();
    if (threadIdx.x < 64) {
        const int jj = threadIdx.x >> 3, b = threadIdx.x & 7;
        float t = 0.f;
#pragma unroll
        for (int w = 0; w < 8; w++) t += red[w][jj * 8 + b];
        hp[((size_t)ks * 8 + b) * 64 + jg * 8 + jj] = t;
    }
}

__global__ __launch_bounds__(64)
void mlp2b(const float* __restrict__ hp, const float* __restrict__ b1,
           const float* __restrict__ W2, const float* __restrict__ b2,
           float* __restrict__ out)
{
    const int b = blockIdx.x, j = threadIdx.x;
    float hv = b1[j];
#pragma unroll
    for (int s = 0; s < 8; s++) hv += hp[((size_t)s * 8 + b) * 64 + j];
    float v = fmaxf(hv, 0.f) * W2[j];
#pragma unroll
    for (int o = 16; o > 0; o >>= 1) v += __shfl_down_sync(0xffffffffu, v, o);
    __shared__ float s2[2];
    if ((j & 31) == 0) s2[j >> 5] = v;
    __syncthreads();
    if (j == 0) out[b] = s2[0] + s2[1] + b2[0];
}

// ---------------------------------------------------------------------------
extern "C" void kernel_launch(void* const* d_in, const int* in_sizes, int n_in,
                              void* d_out, int out_size)
{
    const float* x   = (const float*)d_in[0];
    const float* Sc  = (const float*)d_in[1];
    const float* Sl  = (const float*)d_in[2];
    const float* Wc1 = (const float*)d_in[3];
    const float* bc1 = (const float*)d_in[4];
    const float* Wc2 = (const float*)d_in[5];
    const float* bc2 = (const float*)d_in[6];
    const float* Wl1 = (const float*)d_in[7];
    const float* bl1 = (const float*)d_in[8];
    const float* Wl2 = (const float*)d_in[9];
    const float* bl2 = (const float*)d_in[10];
    const float* Wm1 = (const float*)d_in[11];
    const float* bm1 = (const float*)d_in[12];
    const float* Wm2 = (const float*)d_in[13];
    const float* bm2 = (const float*)d_in[14];
    float* out = (float*)d_out;

    cudaFuncSetAttribute(gemm_tc, cudaFuncAttributeMaxDynamicSharedMemorySize, SMEMSZ);

    __nv_bfloat16 *Sc2, *Sl2, *x2, *a2, *b2;
    float *part, *z1f, *z2f, *v0, *v1, *y32, *y16, *hp;
    cudaGetSymbolAddress((void**)&Sc2, g_Sc2); cudaGetSymbolAddress((void**)&Sl2, g_Sl2);
    cudaGetSymbolAddress((void**)&x2, g_x2);
    cudaGetSymbolAddress((void**)&a2, g_a2);   cudaGetSymbolAddress((void**)&b2, g_b2);
    cudaGetSymbolAddress((void**)&part, g_part);
    cudaGetSymbolAddress((void**)&z1f, g_z1f); cudaGetSymbolAddress((void**)&z2f, g_z2f);
    cudaGetSymbolAddress((void**)&v0, g_v0);   cudaGetSymbolAddress((void**)&v1, g_v1);
    cudaGetSymbolAddress((void**)&y32, g_y32); cudaGetSymbolAddress((void**)&y16, g_y16);
    cudaGetSymbolAddress((void**)&hp, g_hp);

    const int SN4 = NNODES * NNODES / 4;          // 4M float4
    const int XN4 = CC * NNODES / 4;              // 128K float4
    cvt2<<<SN4 / 256, 256>>>((const float4*)Sc, Sc2, SN4);
    cvt2<<<SN4 / 256, 256>>>((const float4*)Sl, Sl2, SN4);
    cvt2<<<XN4 / 256, 256>>>((const float4*)x,  x2,  XN4);

    const dim3 gG(NNODES / NT, SPLITK);           // 32 x 4 = 128 CTAs
    const dim3 gR(CC * NNODES / 4 / 256);         // 512 blocks
    const dim3 gC(NNODES / 256, BATCH);
    const dim3 gP(NNODES / 256, BATCH, 3);

    // ---- Layer 1 (clique, 16 -> 32) ----
    gemm_tc<<<gG, 256, SMEMSZ>>>(x2, Sc2, part);
    reduce_splitk<0><<<gR, 256>>>(part, nullptr, nullptr, z1f, a2);
    gemm_tc<<<gG, 256, SMEMSZ>>>(a2, Sc2, part);
    reduce_splitk<0><<<gR, 256>>>(part, nullptr, nullptr, z2f, nullptr);
    combine_k3<<<gC, 256>>>(x, z1f, z2f, Wc1, bc1, y32);

    // ---- Layer 2 (clique, 32 -> 16): project then Horner ----
    proj_k3<<<gP, 256>>>(y32, Wc2, v0, v1, b2);
    gemm_tc<<<gG, 256, SMEMSZ>>>(b2, Sc2, part);
    reduce_splitk<1><<<gR, 256>>>(part, v1, nullptr, nullptr, a2);
    gemm_tc<<<gG, 256, SMEMSZ>>>(a2, Sc2, part);
    reduce_splitk<2><<<gR, 256>>>(part, v0, bc2, y16, b2);

    // ---- Layer 3 (line, 16 -> 32) ----
    gemm_tc<<<gG, 256, SMEMSZ>>>(b2, Sl2, part);
    reduce_splitk<0><<<gR, 256>>>(part, nullptr, nullptr, z1f, a2);
    gemm_tc<<<gG, 256, SMEMSZ>>>(a2, Sl2, part);
    reduce_splitk<0><<<gR, 256>>>(part, nullptr, nullptr, z2f, nullptr);
    combine_k3<<<gC, 256>>>(y16, z1f, z2f, Wl1, bl1, y32);

    // ---- Layer 4 (line, 32 -> 16) ----
    proj_k3<<<gP, 256>>>(y32, Wl2, v0, v1, b2);
    gemm_tc<<<gG, 256, SMEMSZ>>>(b2, Sl2, part);
    reduce_splitk<1><<<gR, 256>>>(part, v1, nullptr, nullptr, a2);
    gemm_tc<<<gG, 256, SMEMSZ>>>(a2, Sl2, part);
    reduce_splitk<2><<<gR, 256>>>(part, v0, bl2, y16, nullptr);

    // ---- MLP head ----
    mlp1b<<<dim3(8, 8), 256>>>(y16, Wm1, hp);
    mlp2b<<<BATCH, 64>>>(hp, bm1, Wm2, bm2, out);
}

// round 6
// speedup vs baseline: 4.1982x; 1.1683x over previous
#include <cuda_runtime.h>
#include <cuda_bf16.h>
#include <cstdint>

// ---------------------------------------------------------------------------
// SelectionGNN (clique+line), B=8, N=4096, E=1, K=3, F=[16,32,16]
// Diffusion GEMMs (8x: 128x4096x4096) on mma.sync bf16 hi/lo split
// (D += Ah*Bh + Ah*Bl + Al*Bh, fp32 accum). TMA bulk loads (one 256B op per
// row covering hi+lo) into 272B-stride padded smem rows (conflict-free
// ldmatrix). 3-stage mbarrier pipeline. 512 threads: 4x4 warp grid,
// warp tile 32x32 -> 4 warps per SMSP for latency hiding.
// ---------------------------------------------------------------------------

#define NNODES 4096
#define BATCH  8
#define CC     128            // channels = B*16 (GEMM M)
#define NT     128            // n-tile per CTA
#define SPLITK 4
#define KC     (NNODES / SPLITK)   // 1024 k per CTA
#define NKT    (KC / 64)           // 16 k-tiles (64 k each)

#define ROWSTR   272               // 256B data + 16B pad
#define TILESZ   (128 * ROWSTR)    // 34816
#define STAGESZ  (2 * TILESZ)      // A tile + B tile = 69632
#define NSTAGE   3
#define SMEMSZ   (64 + NSTAGE * STAGESZ)   // 208960

// ---------------- scratch (device globals; allocation is forbidden) --------
__device__ __align__(256) __nv_bfloat16 g_Sc2[NNODES * 2 * NNODES]; // 64MB
__device__ __align__(256) __nv_bfloat16 g_Sl2[NNODES * 2 * NNODES]; // 64MB
__device__ __align__(256) __nv_bfloat16 g_x2 [CC * 2 * NNODES];
__device__ __align__(256) __nv_bfloat16 g_a2 [CC * 2 * NNODES];
__device__ __align__(256) __nv_bfloat16 g_b2 [CC * 2 * NNODES];
__device__ __align__(256) float g_part[SPLITK * CC * NNODES];  // 8 MB
__device__ __align__(256) float g_z1f [CC * NNODES];
__device__ __align__(256) float g_z2f [CC * NNODES];
__device__ __align__(256) float g_v0  [CC * NNODES];
__device__ __align__(256) float g_v1  [CC * NNODES];
__device__ __align__(256) float g_y32 [BATCH * 32 * NNODES];
__device__ __align__(256) float g_y16 [CC * NNODES];
__device__ __align__(256) float g_hp  [8 * BATCH * 64];

// ---------------- PTX helpers (baseline sm_90-level PTX only) ---------------
__device__ __forceinline__ uint32_t smem_u32(const void* p) {
    uint32_t a;
    asm("{ .reg .u64 t; cvta.to.shared.u64 t, %1; cvt.u32.u64 %0, t; }" : "=r"(a) : "l"(p));
    return a;
}
#define MBAR_INIT(a, c) asm volatile("mbarrier.init.shared.b64 [%0], %1;" :: "r"(a), "r"(c) : "memory")

#define MBAR_WAIT(mbar, par) do {                                              \
    uint32_t _m = (mbar), _p = (par), _d;                                      \
    asm volatile("{ .reg .pred p;"                                             \
        " mbarrier.try_wait.parity.acquire.cta.shared::cta.b64 p, [%1], %2;"   \
        " selp.b32 %0, 1, 0, p; }" : "=r"(_d) : "r"(_m), "r"(_p) : "memory");  \
    if (!_d) {                                                                 \
        asm volatile("{ .reg .pred P1;"                                        \
        " W%=: mbarrier.try_wait.parity.acquire.cta.shared::cta.b64 P1, [%0], %1, 0x989680;" \
        " @P1 bra.uni D%=; bra.uni W%=; D%=: }" :: "r"(_m), "r"(_p) : "memory"); } \
} while (0)

#define MBAR_EXPECT(mbar, bytes) \
    asm volatile("mbarrier.arrive.expect_tx.shared.b64 _, [%0], %1;" :: "r"(mbar), "r"(bytes) : "memory")

#define BULK_G2S(dst, src, bytes, mbar) \
    asm volatile("cp.async.bulk.shared::cluster.global.mbarrier::complete_tx::bytes [%0], [%1], %2, [%3];" \
                 :: "r"(dst), "l"(src), "r"(bytes), "r"(mbar) : "memory")

__device__ __forceinline__ void ldsm4(uint32_t& r0, uint32_t& r1, uint32_t& r2,
                                      uint32_t& r3, uint32_t addr) {
    asm volatile("ldmatrix.sync.aligned.m8n8.x4.shared.b16 {%0,%1,%2,%3}, [%4];"
                 : "=r"(r0), "=r"(r1), "=r"(r2), "=r"(r3) : "r"(addr));
}
__device__ __forceinline__ void mma16816(float& d0, float& d1, float& d2, float& d3,
                                         uint32_t a0, uint32_t a1, uint32_t a2, uint32_t a3,
                                         uint32_t b0, uint32_t b1) {
    asm volatile("mma.sync.aligned.m16n8k16.row.col.f32.bf16.bf16.f32 "
                 "{%0,%1,%2,%3}, {%4,%5,%6,%7}, {%8,%9}, {%0,%1,%2,%3};"
                 : "+f"(d0), "+f"(d1), "+f"(d2), "+f"(d3)
                 : "r"(a0), "r"(a1), "r"(a2), "r"(a3), "r"(b0), "r"(b1));
}

// ---------------------------------------------------------------------------
// HMMA diffusion GEMM: part[split][c][n0+n] = sum_{k in split} A[c,k]*B[n0+n,k]
// A2/B2 in combined hi|lo layout. grid = (32, SPLITK), 512 threads (16 warps,
// 4x4 warp grid, 32x32 warp tile).
// ---------------------------------------------------------------------------
__global__ __launch_bounds__(512, 1)
void gemm_tc(const __nv_bfloat16* __restrict__ A2,
             const __nv_bfloat16* __restrict__ B2,
             float* __restrict__ part)
{
    extern __shared__ __align__(16) char smem[];
    const uint32_t sb  = smem_u32(smem);
    const uint32_t st0 = sb + 64;

    const int tid  = threadIdx.x;
    const int wid  = tid >> 5, lane = tid & 31;
    const int wm   = wid >> 2;            // 0..3 -> m offset wm*32
    const int wn   = wid & 3;             // 0..3 -> n offset wn*32
    const int n0   = blockIdx.x * NT;
    const int split = blockIdx.y;

    // ---- producer: threads 0..255, one 256B bulk op per thread per k-tile --
    const int ptile = (tid >> 7) & 1;     // 0 = A, 1 = B (tid < 256)
    const int prow  = tid & 127;
    const __nv_bfloat16* src_base =
        (ptile == 0 ? A2 + (size_t)prow * (2 * NNODES)
                    : B2 + (size_t)(n0 + prow) * (2 * NNODES))
        + (size_t)split * (2 * KC);
    const uint32_t dst_off = (uint32_t)(ptile * TILESZ + prow * ROWSTR);

    if (tid == 0) {
        MBAR_INIT(sb + 0, 256);
        MBAR_INIT(sb + 8, 256);
        MBAR_INIT(sb + 16, 256);
    }
    __syncthreads();

    auto load_tile = [&](int tt) {
        if (tid < 256) {
            const uint32_t s    = (uint32_t)(tt % 3);
            const uint32_t mbar = sb + s * 8;
            const uint32_t dst  = st0 + s * STAGESZ + dst_off;
            const __nv_bfloat16* src = src_base + tt * 128;
            MBAR_EXPECT(mbar, 256u);
            BULK_G2S(dst, src, 256u, mbar);
        }
    };

    load_tile(0); load_tile(1); load_tile(2);

    // ---- ldmatrix row offsets (within a tile) ----
    const int r8  = lane & 7;
    const int seg = lane >> 3;            // 0..3
    const int sak = seg >> 1;             // A: k8 selector
    const int sam = seg & 1;              // A: m8 selector
    uint32_t rowOffA[2];
#pragma unroll
    for (int mt = 0; mt < 2; mt++)
        rowOffA[mt] = (uint32_t)(wm * 32 + mt * 16 + sam * 8 + r8) * ROWSTR;
    uint32_t rowOffB[2];
#pragma unroll
    for (int p = 0; p < 2; p++)
        rowOffB[p] = (uint32_t)(wn * 32 + p * 16 + sak * 8 + r8) * ROWSTR;
    const int sbk = seg & 1;              // B: k8 selector

    float acc[2][4][4] = {};

#pragma unroll 1
    for (int tt = 0; tt < NKT; tt++) {
        const uint32_t s = (uint32_t)(tt % 3);
        MBAR_WAIT(sb + s * 8, (uint32_t)((tt / 3) & 1));

        const uint32_t stA = st0 + s * STAGESZ;
        const uint32_t stB = stA + TILESZ;

#pragma unroll
        for (int ks = 0; ks < 4; ks++) {
            uint32_t ah[2][4], al[2][4];
#pragma unroll
            for (int mt = 0; mt < 2; mt++) {
                const uint32_t a = stA + rowOffA[mt] + (uint32_t)((ks * 2 + sak) << 4);
                ldsm4(ah[mt][0], ah[mt][1], ah[mt][2], ah[mt][3], a);
                ldsm4(al[mt][0], al[mt][1], al[mt][2], al[mt][3], a + 128);
            }
            uint32_t bh[4][2], bl[4][2];
#pragma unroll
            for (int p = 0; p < 2; p++) {
                const uint32_t b = stB + rowOffB[p] + (uint32_t)((ks * 2 + sbk) << 4);
                ldsm4(bh[2*p][0], bh[2*p][1], bh[2*p+1][0], bh[2*p+1][1], b);
                ldsm4(bl[2*p][0], bl[2*p][1], bl[2*p+1][0], bl[2*p+1][1], b + 128);
            }
#pragma unroll
            for (int mt = 0; mt < 2; mt++)
#pragma unroll
                for (int nt = 0; nt < 4; nt++) {
                    float* d = acc[mt][nt];
                    mma16816(d[0], d[1], d[2], d[3],
                             ah[mt][0], ah[mt][1], ah[mt][2], ah[mt][3],
                             bh[nt][0], bh[nt][1]);
                    mma16816(d[0], d[1], d[2], d[3],
                             ah[mt][0], ah[mt][1], ah[mt][2], ah[mt][3],
                             bl[nt][0], bl[nt][1]);
                    mma16816(d[0], d[1], d[2], d[3],
                             al[mt][0], al[mt][1], al[mt][2], al[mt][3],
                             bh[nt][0], bh[nt][1]);
                }
        }
        __syncthreads();                   // all warps done with stage s
        if (tt + 3 < NKT) load_tile(tt + 3);
    }

    // ---- epilogue: D frag -> part[(split*128 + c) * 4096 + n] ----
    const int mrow = lane >> 2;           // 0..7
    const int ncol = (lane & 3) * 2;      // 0,2,4,6
#pragma unroll
    for (int mt = 0; mt < 2; mt++) {
#pragma unroll
        for (int nt = 0; nt < 4; nt++) {
            const int c = wm * 32 + mt * 16 + mrow;
            const int n = n0 + wn * 32 + nt * 8 + ncol;
            float* d0 = part + ((size_t)(split * CC + c)) * NNODES + n;
            float* d1 = part + ((size_t)(split * CC + c + 8)) * NNODES + n;
            *reinterpret_cast<float2*>(d0) = make_float2(acc[mt][nt][0], acc[mt][nt][1]);
            *reinterpret_cast<float2*>(d1) = make_float2(acc[mt][nt][2], acc[mt][nt][3]);
        }
    }
}

// ---------------------------------------------------------------------------
// fp32 -> combined hi|lo bf16 layout, float4 granularity
// ---------------------------------------------------------------------------
__device__ __forceinline__ void split4(float4 a, uint2& H, uint2& L) {
    __nv_bfloat16 h0 = __float2bfloat16(a.x), h1 = __float2bfloat16(a.y);
    __nv_bfloat16 h2 = __float2bfloat16(a.z), h3 = __float2bfloat16(a.w);
    __nv_bfloat16 l0 = __float2bfloat16(a.x - __bfloat162float(h0));
    __nv_bfloat16 l1 = __float2bfloat16(a.y - __bfloat162float(h1));
    __nv_bfloat16 l2 = __float2bfloat16(a.z - __bfloat162float(h2));
    __nv_bfloat16 l3 = __float2bfloat16(a.w - __bfloat162float(h3));
    H.x = ((uint32_t)__bfloat16_as_ushort(h1) << 16) | __bfloat16_as_ushort(h0);
    H.y = ((uint32_t)__bfloat16_as_ushort(h3) << 16) | __bfloat16_as_ushort(h2);
    L.x = ((uint32_t)__bfloat16_as_ushort(l1) << 16) | __bfloat16_as_ushort(l0);
    L.y = ((uint32_t)__bfloat16_as_ushort(l3) << 16) | __bfloat16_as_ushort(l2);
}

__global__ __launch_bounds__(256)
void cvt2(const float4* __restrict__ in, __nv_bfloat16* __restrict__ out, int n4)
{
    int i = blockIdx.x * 256 + threadIdx.x;
    if (i >= n4) return;
    uint2 H, L;
    split4(in[i], H, L);
    const int e   = i * 4;
    const int row = e >> 12, k = e & 4095;
    const size_t base = (size_t)row * 8192 + ((k >> 6) << 7) + (k & 63);
    *reinterpret_cast<uint2*>(out + base)      = H;
    *reinterpret_cast<uint2*>(out + base + 64) = L;
}

// ---------------------------------------------------------------------------
// split-K reduce + epilogue. MODE 0: Y = sum; 1: Y = sum + V; 2: relu(sum+V+b)
// ---------------------------------------------------------------------------
template <int MODE>
__global__ __launch_bounds__(256)
void reduce_splitk(const float* __restrict__ part, const float* __restrict__ V,
                   const float* __restrict__ bias, float* __restrict__ Yf,
                   __nv_bfloat16* __restrict__ Y2)
{
    const int i = blockIdx.x * 256 + threadIdx.x;          // float4 index
    const float4* p = reinterpret_cast<const float4*>(part);
    const int STR = CC * NNODES / 4;
    float4 a = p[i];
    float4 b = p[i + STR];
    float4 c = p[i + 2 * STR];
    float4 d = p[i + 3 * STR];
    a.x += b.x + c.x + d.x; a.y += b.y + c.y + d.y;
    a.z += b.z + c.z + d.z; a.w += b.w + c.w + d.w;
    if (MODE >= 1) {
        float4 v = reinterpret_cast<const float4*>(V)[i];
        a.x += v.x; a.y += v.y; a.z += v.z; a.w += v.w;
    }
    const int e   = i * 4;
    const int ch  = e >> 12;                               // 0..127
    if (MODE == 2) {
        const float bv = bias[ch & 15];
        a.x = fmaxf(a.x + bv, 0.f); a.y = fmaxf(a.y + bv, 0.f);
        a.z = fmaxf(a.z + bv, 0.f); a.w = fmaxf(a.w + bv, 0.f);
    }
    if (Yf) reinterpret_cast<float4*>(Yf)[i] = a;
    if (Y2) {
        uint2 H, L;
        split4(a, H, L);
        const int k = e & 4095;
        const size_t base = (size_t)ch * 8192 + ((k >> 6) << 7) + (k & 63);
        *reinterpret_cast<uint2*>(Y2 + base)      = H;
        *reinterpret_cast<uint2*>(Y2 + base + 64) = L;
    }
}

// ---------------------------------------------------------------------------
// Combine (16 -> 32): out[b,g,n] = relu(bias[g] + sum_{k,f} W[g,k,f] z_k[b,f,n])
// ---------------------------------------------------------------------------
__global__ __launch_bounds__(256)
void combine_k3(const float* __restrict__ z0, const float* __restrict__ z1,
                const float* __restrict__ z2, const float* __restrict__ W,
                const float* __restrict__ bias, float* __restrict__ out)
{
    __shared__ float Ws[32 * 48];
    const int tid = threadIdx.x;
    for (int i = tid; i < 32 * 48; i += 256) Ws[i] = W[i];
    __syncthreads();

    const int n = blockIdx.x * 256 + tid;
    const int b = blockIdx.y;
    float acc[32];
#pragma unroll
    for (int g = 0; g < 32; g++) acc[g] = bias[g];
    const float* zs[3] = {z0, z1, z2};
#pragma unroll
    for (int k = 0; k < 3; k++) {
        const float* z = zs[k];
#pragma unroll
        for (int f = 0; f < 16; f++) {
            float zv = z[((size_t)b * 16 + f) * NNODES + n];
#pragma unroll
            for (int g = 0; g < 32; g++) acc[g] += Ws[g * 48 + k * 16 + f] * zv;
        }
    }
#pragma unroll
    for (int g = 0; g < 32; g++)
        out[((size_t)b * 32 + g) * NNODES + n] = fmaxf(acc[g], 0.f);
}

// ---------------------------------------------------------------------------
// Projection (32 -> 16): v_k[b,g,n] = sum_f W[g,k,f] x[b,f,n]
// k=0,1 -> fp32; k=2 -> combined bf16 hi|lo (next MMA A operand)
// ---------------------------------------------------------------------------
__global__ __launch_bounds__(256)
void proj_k3(const float* __restrict__ in, const float* __restrict__ W,
             float* __restrict__ v0, float* __restrict__ v1,
             __nv_bfloat16* __restrict__ v2c)
{
    const int k = blockIdx.z;
    __shared__ float Ws[16 * 32];
    const int tid = threadIdx.x;
    for (int i = tid; i < 16 * 32; i += 256)
        Ws[i] = W[(i >> 5) * 96 + k * 32 + (i & 31)];
    __syncthreads();

    const int n = blockIdx.x * 256 + tid;
    const int b = blockIdx.y;
    float acc[16] = {};
#pragma unroll
    for (int f = 0; f < 32; f++) {
        float xv = in[((size_t)b * 32 + f) * NNODES + n];
#pragma unroll
        for (int g = 0; g < 16; g++) acc[g] += Ws[g * 32 + f] * xv;
    }
    if (k < 2) {
        float* v = (k == 0) ? v0 : v1;
#pragma unroll
        for (int g = 0; g < 16; g++)
            v[((size_t)b * 16 + g) * NNODES + n] = acc[g];
    } else {
        const size_t kpos = (size_t)((n >> 6) << 7) + (n & 63);
#pragma unroll
        for (int g = 0; g < 16; g++) {
            const size_t o = (size_t)(b * 16 + g) * 8192 + kpos;
            __nv_bfloat16 h = __float2bfloat16(acc[g]);
            v2c[o]      = h;
            v2c[o + 64] = __float2bfloat16(acc[g] - __bfloat162float(h));
        }
    }
}

// ---------------------------------------------------------------------------
// MLP head. mlp1b: partial dot products, grid (8 j-groups, 8 k-slices).
// ---------------------------------------------------------------------------
__global__ __launch_bounds__(256)
void mlp1b(const float* __restrict__ y, const float* __restrict__ W1,
           float* __restrict__ hp)
{
    const int jg = blockIdx.x;    // 8 groups of 8 outputs
    const int ks = blockIdx.y;    // 8 k-slices of 2048 float4
    const float4* Y4 = reinterpret_cast<const float4*>(y);
    const float4* W4 = reinterpret_cast<const float4*>(W1);

    float s[8][8] = {};           // [jj][b]
    for (int i = threadIdx.x; i < 2048; i += 256) {
        const int off = ks * 2048 + i;
        float4 yv[8];
#pragma unroll
        for (int b = 0; b < 8; b++) yv[b] = Y4[(size_t)b * 16384 + off];
#pragma unroll
        for (int jj = 0; jj < 8; jj++) {
            float4 w = W4[(size_t)(jg * 8 + jj) * 16384 + off];
#pragma unroll
            for (int b = 0; b < 8; b++)
                s[jj][b] += yv[b].x * w.x + yv[b].y * w.y + yv[b].z * w.z + yv[b].w * w.w;
        }
    }
    __shared__ float red[8][64];  // [warp][jj*8+b]
    const int wid = threadIdx.x >> 5, lane = threadIdx.x & 31;
#pragma unroll
    for (int jj = 0; jj < 8; jj++)
#pragma unroll
        for (int b = 0; b < 8; b++) {
            float v = s[jj][b];
#pragma unroll
            for (int o = 16; o > 0; o >>= 1) v += __shfl_down_sync(0xffffffffu, v, o);
            if (lane == 0) red[wid][jj * 8 + b] = v;
        }
    __syncthreads();
    if (threadIdx.x < 64) {
        const int jj = threadIdx.x >> 3, b = threadIdx.x & 7;
        float t = 0.f;
#pragma unroll
        for (int w = 0; w < 8; w++) t += red[w][jj * 8 + b];
        hp[((size_t)ks * 8 + b) * 64 + jg * 8 + jj] = t;
    }
}

__global__ __launch_bounds__(64)
void mlp2b(const float* __restrict__ hp, const float* __restrict__ b1,
           const float* __restrict__ W2, const float* __restrict__ b2,
           float* __restrict__ out)
{
    const int b = blockIdx.x, j = threadIdx.x;
    float hv = b1[j];
#pragma unroll
    for (int s = 0; s < 8; s++) hv += hp[((size_t)s * 8 + b) * 64 + j];
    float v = fmaxf(hv, 0.f) * W2[j];
#pragma unroll
    for (int o = 16; o > 0; o >>= 1) v += __shfl_down_sync(0xffffffffu, v, o);
    __shared__ float s2[2];
    if ((j & 31) == 0) s2[j >> 5] = v;
    __syncthreads();
    if (j == 0) out[b] = s2[0] + s2[1] + b2[0];
}

// ---------------------------------------------------------------------------
extern "C" void kernel_launch(void* const* d_in, const int* in_sizes, int n_in,
                              void* d_out, int out_size)
{
    const float* x   = (const float*)d_in[0];
    const float* Sc  = (const float*)d_in[1];
    const float* Sl  = (const float*)d_in[2];
    const float* Wc1 = (const float*)d_in[3];
    const float* bc1 = (const float*)d_in[4];
    const float* Wc2 = (const float*)d_in[5];
    const float* bc2 = (const float*)d_in[6];
    const float* Wl1 = (const float*)d_in[7];
    const float* bl1 = (const float*)d_in[8];
    const float* Wl2 = (const float*)d_in[9];
    const float* bl2 = (const float*)d_in[10];
    const float* Wm1 = (const float*)d_in[11];
    const float* bm1 = (const float*)d_in[12];
    const float* Wm2 = (const float*)d_in[13];
    const float* bm2 = (const float*)d_in[14];
    float* out = (float*)d_out;

    cudaFuncSetAttribute(gemm_tc, cudaFuncAttributeMaxDynamicSharedMemorySize, SMEMSZ);

    __nv_bfloat16 *Sc2, *Sl2, *x2, *a2, *b2;
    float *part, *z1f, *z2f, *v0, *v1, *y32, *y16, *hp;
    cudaGetSymbolAddress((void**)&Sc2, g_Sc2); cudaGetSymbolAddress((void**)&Sl2, g_Sl2);
    cudaGetSymbolAddress((void**)&x2, g_x2);
    cudaGetSymbolAddress((void**)&a2, g_a2);   cudaGetSymbolAddress((void**)&b2, g_b2);
    cudaGetSymbolAddress((void**)&part, g_part);
    cudaGetSymbolAddress((void**)&z1f, g_z1f); cudaGetSymbolAddress((void**)&z2f, g_z2f);
    cudaGetSymbolAddress((void**)&v0, g_v0);   cudaGetSymbolAddress((void**)&v1, g_v1);
    cudaGetSymbolAddress((void**)&y32, g_y32); cudaGetSymbolAddress((void**)&y16, g_y16);
    cudaGetSymbolAddress((void**)&hp, g_hp);

    const int SN4 = NNODES * NNODES / 4;          // 4M float4
    const int XN4 = CC * NNODES / 4;              // 128K float4
    cvt2<<<SN4 / 256, 256>>>((const float4*)Sc, Sc2, SN4);
    cvt2<<<SN4 / 256, 256>>>((const float4*)Sl, Sl2, SN4);
    cvt2<<<XN4 / 256, 256>>>((const float4*)x,  x2,  XN4);

    const dim3 gG(NNODES / NT, SPLITK);           // 32 x 4 = 128 CTAs
    const dim3 gR(CC * NNODES / 4 / 256);         // 512 blocks
    const dim3 gC(NNODES / 256, BATCH);
    const dim3 gP(NNODES / 256, BATCH, 3);

    // ---- Layer 1 (clique, 16 -> 32) ----
    gemm_tc<<<gG, 512, SMEMSZ>>>(x2, Sc2, part);
    reduce_splitk<0><<<gR, 256>>>(part, nullptr, nullptr, z1f, a2);
    gemm_tc<<<gG, 512, SMEMSZ>>>(a2, Sc2, part);
    reduce_splitk<0><<<gR, 256>>>(part, nullptr, nullptr, z2f, nullptr);
    combine_k3<<<gC, 256>>>(x, z1f, z2f, Wc1, bc1, y32);

    // ---- Layer 2 (clique, 32 -> 16): project then Horner ----
    proj_k3<<<gP, 256>>>(y32, Wc2, v0, v1, b2);
    gemm_tc<<<gG, 512, SMEMSZ>>>(b2, Sc2, part);
    reduce_splitk<1><<<gR, 256>>>(part, v1, nullptr, nullptr, a2);
    gemm_tc<<<gG, 512, SMEMSZ>>>(a2, Sc2, part);
    reduce_splitk<2><<<gR, 256>>>(part, v0, bc2, y16, b2);

    // ---- Layer 3 (line, 16 -> 32) ----
    gemm_tc<<<gG, 512, SMEMSZ>>>(b2, Sl2, part);
    reduce_splitk<0><<<gR, 256>>>(part, nullptr, nullptr, z1f, a2);
    gemm_tc<<<gG, 512, SMEMSZ>>>(a2, Sl2, part);
    reduce_splitk<0><<<gR, 256>>>(part, nullptr, nullptr, z2f, nullptr);
    combine_k3<<<gC, 256>>>(y16, z1f, z2f, Wl1, bl1, y32);

    // ---- Layer 4 (line, 32 -> 16) ----
    proj_k3<<<gP, 256>>>(y32, Wl2, v0, v1, b2);
    gemm_tc<<<gG, 512, SMEMSZ>>>(b2, Sl2, part);
    reduce_splitk<1><<<gR, 256>>>(part, v1, nullptr, nullptr, a2);
    gemm_tc<<<gG, 512, SMEMSZ>>>(a2, Sl2, part);
    reduce_splitk<2><<<gR, 256>>>(part, v0, bl2, y16, nullptr);

    // ---- MLP head ----
    mlp1b<<<dim3(8, 8), 256>>>(y16, Wm1, hp);
    mlp2b<<<BATCH, 64>>>(hp, bm1, Wm2, bm2, out);
}

// round 7
// speedup vs baseline: 4.9887x; 1.1883x over previous
#include <cuda_runtime.h>
#include <cuda_fp16.h>
#include <cstdint>

// ---------------------------------------------------------------------------
// SelectionGNN (clique+line), B=8, N=4096, E=1, K=3, F=[16,32,16]
// Diffusion GEMMs (8x: 128x4096x4096) via mma.sync fp16 2-pass:
//   D = Ah*Bh + Al*Bh   (A split into fp16 hi/lo; B = fp16(S) hi only)
// Dropped term Ah*Bl ~ 2^-12 -> rel_err ~2-4e-4 (measured error tracks the
// dropped term; bf16 3-pass gave exactly 2^-16). fp32 accumulation.
// TMA bulk loads, padded smem rows (conflict-free ldmatrix), 3-stage pipeline.
// CTA tile 128x256, warp tile 32x64 (16 warps), SPLITK=8 -> 128 CTAs.
// ---------------------------------------------------------------------------

#define NNODES 4096
#define BATCH  8
#define CC     128                 // channels = B*16 (GEMM M)
#define NT     256                 // n-tile per CTA
#define SPLITK 8
#define KC     (NNODES / SPLITK)   // 512 k per CTA
#define NKT    (KC / 64)           // 8 k-tiles (64 k each)

#define RSA      272               // A row: 256B data (64 hi + 64 lo fp16) + 16 pad
#define RSB      144               // B row: 128B data (64 hi fp16) + 16 pad
#define ATILESZ  (128 * RSA)       // 34816
#define BTILESZ  (256 * RSB)       // 36864
#define STAGESZ  (ATILESZ + BTILESZ)   // 71680
#define NSTAGE   3
#define SMEMSZ   (64 + NSTAGE * STAGESZ)   // 215104

// ---------------- scratch (device globals; allocation is forbidden) --------
__device__ __align__(256) __half g_Sc2[(size_t)NNODES * NNODES];   // 32MB hi-only
__device__ __align__(256) __half g_Sl2[(size_t)NNODES * NNODES];   // 32MB hi-only
__device__ __align__(256) __half g_x2 [CC * 2 * NNODES];           // hi|lo combined
__device__ __align__(256) __half g_a2 [CC * 2 * NNODES];
__device__ __align__(256) __half g_b2 [CC * 2 * NNODES];
__device__ __align__(256) float g_part[SPLITK * CC * NNODES];      // 16.8 MB
__device__ __align__(256) float g_z1f [CC * NNODES];
__device__ __align__(256) float g_z2f [CC * NNODES];
__device__ __align__(256) float g_v0  [CC * NNODES];
__device__ __align__(256) float g_v1  [CC * NNODES];
__device__ __align__(256) float g_y32 [BATCH * 32 * NNODES];
__device__ __align__(256) float g_y16 [CC * NNODES];
__device__ __align__(256) float g_hp  [8 * BATCH * 64];

// ---------------- PTX helpers (baseline sm_90-level PTX only) ---------------
__device__ __forceinline__ uint32_t smem_u32(const void* p) {
    uint32_t a;
    asm("{ .reg .u64 t; cvta.to.shared.u64 t, %1; cvt.u32.u64 %0, t; }" : "=r"(a) : "l"(p));
    return a;
}
#define MBAR_INIT(a, c) asm volatile("mbarrier.init.shared.b64 [%0], %1;" :: "r"(a), "r"(c) : "memory")

#define MBAR_WAIT(mbar, par) do {                                              \
    uint32_t _m = (mbar), _p = (par), _d;                                      \
    asm volatile("{ .reg .pred p;"                                             \
        " mbarrier.try_wait.parity.acquire.cta.shared::cta.b64 p, [%1], %2;"   \
        " selp.b32 %0, 1, 0, p; }" : "=r"(_d) : "r"(_m), "r"(_p) : "memory");  \
    if (!_d) {                                                                 \
        asm volatile("{ .reg .pred P1;"                                        \
        " W%=: mbarrier.try_wait.parity.acquire.cta.shared::cta.b64 P1, [%0], %1, 0x989680;" \
        " @P1 bra.uni D%=; bra.uni W%=; D%=: }" :: "r"(_m), "r"(_p) : "memory"); } \
} while (0)

#define MBAR_EXPECT(mbar, bytes) \
    asm volatile("mbarrier.arrive.expect_tx.shared.b64 _, [%0], %1;" :: "r"(mbar), "r"(bytes) : "memory")

#define BULK_G2S(dst, src, bytes, mbar) \
    asm volatile("cp.async.bulk.shared::cluster.global.mbarrier::complete_tx::bytes [%0], [%1], %2, [%3];" \
                 :: "r"(dst), "l"(src), "r"(bytes), "r"(mbar) : "memory")

__device__ __forceinline__ void ldsm4(uint32_t& r0, uint32_t& r1, uint32_t& r2,
                                      uint32_t& r3, uint32_t addr) {
    asm volatile("ldmatrix.sync.aligned.m8n8.x4.shared.b16 {%0,%1,%2,%3}, [%4];"
                 : "=r"(r0), "=r"(r1), "=r"(r2), "=r"(r3) : "r"(addr));
}
__device__ __forceinline__ void mma16816(float& d0, float& d1, float& d2, float& d3,
                                         uint32_t a0, uint32_t a1, uint32_t a2, uint32_t a3,
                                         uint32_t b0, uint32_t b1) {
    asm volatile("mma.sync.aligned.m16n8k16.row.col.f32.f16.f16.f32 "
                 "{%0,%1,%2,%3}, {%4,%5,%6,%7}, {%8,%9}, {%0,%1,%2,%3};"
                 : "+f"(d0), "+f"(d1), "+f"(d2), "+f"(d3)
                 : "r"(a0), "r"(a1), "r"(a2), "r"(a3), "r"(b0), "r"(b1));
}

// ---------------------------------------------------------------------------
// Diffusion GEMM: part[split][c][n0+n] = sum_{k in split} A[c,k]*B[n0+n,k]
// A2: [128][8192] fp16 (per 64-k tile: 64 hi | 64 lo). B2: [4096][4096] fp16.
// grid = (16, 8), 512 threads, 16 warps (4x4), warp tile 32x64.
// ---------------------------------------------------------------------------
__global__ __launch_bounds__(512, 1)
void gemm_tc(const __half* __restrict__ A2,
             const __half* __restrict__ B2,
             float* __restrict__ part)
{
    extern __shared__ __align__(16) char smem[];
    const uint32_t sb  = smem_u32(smem);
    const uint32_t st0 = sb + 64;

    const int tid  = threadIdx.x;
    const int wid  = tid >> 5, lane = tid & 31;
    const int wm   = wid >> 2;            // 0..3 -> m offset wm*32
    const int wn   = wid & 3;             // 0..3 -> n offset wn*64
    const int n0   = blockIdx.x * NT;
    const int split = blockIdx.y;

    // ---- producer: threads 0..383 (128 A rows @256B, 256 B rows @128B) ----
    const bool isA   = tid < 128;
    const bool isldr = tid < 384;
    const int  prow  = isA ? tid : (tid - 128);
    const __half* src_base = isA
        ? A2 + (size_t)prow * (2 * NNODES) + (size_t)split * (2 * KC)
        : B2 + (size_t)(n0 + prow) * NNODES + (size_t)split * KC;
    const uint32_t dst_off = isA ? (uint32_t)(prow * RSA)
                                 : (uint32_t)(ATILESZ + prow * RSB);
    const uint32_t ldbytes = isA ? 256u : 128u;
    const int      kstep   = isA ? 128 : 64;   // fp16 elems per tile in src row

    if (tid == 0) {
        MBAR_INIT(sb + 0, 384);
        MBAR_INIT(sb + 8, 384);
        MBAR_INIT(sb + 16, 384);
    }
    __syncthreads();

    auto load_tile = [&](int tt) {
        if (isldr) {
            const uint32_t s    = (uint32_t)(tt % 3);
            const uint32_t mbar = sb + s * 8;
            const uint32_t dst  = st0 + s * STAGESZ + dst_off;
            MBAR_EXPECT(mbar, ldbytes);
            BULK_G2S(dst, src_base + tt * kstep, ldbytes, mbar);
        }
    };

    load_tile(0); load_tile(1); load_tile(2);

    // ---- ldmatrix row offsets (within a stage) ----
    const int r8  = lane & 7;
    const int seg = lane >> 3;            // 0..3
    const int sak = seg >> 1;             // A: k8 selector
    const int sam = seg & 1;              // A: m8 selector
    const int sbn = seg >> 1;             // B: n8 selector
    const int sbk = seg & 1;              // B: k8 selector
    uint32_t rowOffA[2];
#pragma unroll
    for (int mt = 0; mt < 2; mt++)
        rowOffA[mt] = (uint32_t)((wm * 32 + mt * 16 + sam * 8 + r8) * RSA);
    uint32_t rowOffB[4];
#pragma unroll
    for (int p = 0; p < 4; p++)
        rowOffB[p] = (uint32_t)(ATILESZ + (wn * 64 + p * 16 + sbn * 8 + r8) * RSB);

    float acc[2][8][4] = {};

#pragma unroll 1
    for (int tt = 0; tt < NKT; tt++) {
        const uint32_t s = (uint32_t)(tt % 3);
        MBAR_WAIT(sb + s * 8, (uint32_t)((tt / 3) & 1));

        const uint32_t st = st0 + s * STAGESZ;

#pragma unroll
        for (int ks = 0; ks < 4; ks++) {
            uint32_t ah[2][4], al[2][4];
#pragma unroll
            for (int mt = 0; mt < 2; mt++) {
                const uint32_t a = st + rowOffA[mt] + (uint32_t)((ks * 2 + sak) << 4);
                ldsm4(ah[mt][0], ah[mt][1], ah[mt][2], ah[mt][3], a);
                ldsm4(al[mt][0], al[mt][1], al[mt][2], al[mt][3], a + 128);
            }
            uint32_t bh[8][2];
#pragma unroll
            for (int p = 0; p < 4; p++) {
                const uint32_t b = st + rowOffB[p] + (uint32_t)((ks * 2 + sbk) << 4);
                ldsm4(bh[2*p][0], bh[2*p][1], bh[2*p+1][0], bh[2*p+1][1], b);
            }
            // pass 1: hi*hi for all 16 (independent)
#pragma unroll
            for (int mt = 0; mt < 2; mt++)
#pragma unroll
                for (int nt = 0; nt < 8; nt++)
                    mma16816(acc[mt][nt][0], acc[mt][nt][1], acc[mt][nt][2], acc[mt][nt][3],
                             ah[mt][0], ah[mt][1], ah[mt][2], ah[mt][3],
                             bh[nt][0], bh[nt][1]);
            // pass 2: lo*hi
#pragma unroll
            for (int mt = 0; mt < 2; mt++)
#pragma unroll
                for (int nt = 0; nt < 8; nt++)
                    mma16816(acc[mt][nt][0], acc[mt][nt][1], acc[mt][nt][2], acc[mt][nt][3],
                             al[mt][0], al[mt][1], al[mt][2], al[mt][3],
                             bh[nt][0], bh[nt][1]);
        }
        __syncthreads();                   // stage s consumed by all warps
        if (tt + 3 < NKT) load_tile(tt + 3);
    }

    // ---- epilogue: D frag -> part[(split*128 + c) * 4096 + n] ----
    const int mrow = lane >> 2;           // 0..7
    const int ncol = (lane & 3) * 2;      // 0,2,4,6
#pragma unroll
    for (int mt = 0; mt < 2; mt++) {
#pragma unroll
        for (int nt = 0; nt < 8; nt++) {
            const int c = wm * 32 + mt * 16 + mrow;
            const int n = n0 + wn * 64 + nt * 8 + ncol;
            float* d0 = part + ((size_t)(split * CC + c)) * NNODES + n;
            float* d1 = part + ((size_t)(split * CC + c + 8)) * NNODES + n;
            *reinterpret_cast<float2*>(d0) = make_float2(acc[mt][nt][0], acc[mt][nt][1]);
            *reinterpret_cast<float2*>(d1) = make_float2(acc[mt][nt][2], acc[mt][nt][3]);
        }
    }
}

// ---------------------------------------------------------------------------
// fp32 -> fp16 hi/lo split helpers
// ---------------------------------------------------------------------------
__device__ __forceinline__ void split4h(float4 a, uint2& H, uint2& L) {
    __half h0 = __float2half_rn(a.x), h1 = __float2half_rn(a.y);
    __half h2 = __float2half_rn(a.z), h3 = __float2half_rn(a.w);
    __half l0 = __float2half_rn(a.x - __half2float(h0));
    __half l1 = __float2half_rn(a.y - __half2float(h1));
    __half l2 = __float2half_rn(a.z - __half2float(h2));
    __half l3 = __float2half_rn(a.w - __half2float(h3));
    H.x = ((uint32_t)__half_as_ushort(h1) << 16) | __half_as_ushort(h0);
    H.y = ((uint32_t)__half_as_ushort(h3) << 16) | __half_as_ushort(h2);
    L.x = ((uint32_t)__half_as_ushort(l1) << 16) | __half_as_ushort(l0);
    L.y = ((uint32_t)__half_as_ushort(l3) << 16) | __half_as_ushort(l2);
}

// S: fp32 -> fp16 hi only, plain row-major [4096][4096]
__global__ __launch_bounds__(256)
void cvtS(const float4* __restrict__ in, __half* __restrict__ out, int n4)
{
    int i = blockIdx.x * 256 + threadIdx.x;
    if (i >= n4) return;
    float4 a = in[i];
    __half h0 = __float2half_rn(a.x), h1 = __float2half_rn(a.y);
    __half h2 = __float2half_rn(a.z), h3 = __float2half_rn(a.w);
    uint2 H;
    H.x = ((uint32_t)__half_as_ushort(h1) << 16) | __half_as_ushort(h0);
    H.y = ((uint32_t)__half_as_ushort(h3) << 16) | __half_as_ushort(h2);
    *reinterpret_cast<uint2*>(out + (size_t)i * 4) = H;
}

// A-type: fp32 [rows][4096] -> fp16 combined [rows][8192] (64 hi | 64 lo per tile)
__global__ __launch_bounds__(256)
void cvtA(const float4* __restrict__ in, __half* __restrict__ out, int n4)
{
    int i = blockIdx.x * 256 + threadIdx.x;
    if (i >= n4) return;
    uint2 H, L;
    split4h(in[i], H, L);
    const int e   = i * 4;
    const int row = e >> 12, k = e & 4095;
    const size_t base = (size_t)row * 8192 + ((k >> 6) << 7) + (k & 63);
    *reinterpret_cast<uint2*>(out + base)      = H;
    *reinterpret_cast<uint2*>(out + base + 64) = L;
}

// ---------------------------------------------------------------------------
// split-K reduce + epilogue. MODE 0: Y = sum; 1: Y = sum + V; 2: relu(sum+V+b)
// ---------------------------------------------------------------------------
template <int MODE>
__global__ __launch_bounds__(256)
void reduce_splitk(const float* __restrict__ part, const float* __restrict__ V,
                   const float* __restrict__ bias, float* __restrict__ Yf,
                   __half* __restrict__ Y2)
{
    const int i = blockIdx.x * 256 + threadIdx.x;          // float4 index
    const float4* p = reinterpret_cast<const float4*>(part);
    const int STR = CC * NNODES / 4;
    float4 a = p[i];
#pragma unroll
    for (int s = 1; s < SPLITK; s++) {
        float4 q = p[i + s * STR];
        a.x += q.x; a.y += q.y; a.z += q.z; a.w += q.w;
    }
    if (MODE >= 1) {
        float4 v = reinterpret_cast<const float4*>(V)[i];
        a.x += v.x; a.y += v.y; a.z += v.z; a.w += v.w;
    }
    const int e  = i * 4;
    const int ch = e >> 12;                                // 0..127
    if (MODE == 2) {
        const float bv = bias[ch & 15];
        a.x = fmaxf(a.x + bv, 0.f); a.y = fmaxf(a.y + bv, 0.f);
        a.z = fmaxf(a.z + bv, 0.f); a.w = fmaxf(a.w + bv, 0.f);
    }
    if (Yf) reinterpret_cast<float4*>(Yf)[i] = a;
    if (Y2) {
        uint2 H, L;
        split4h(a, H, L);
        const int k = e & 4095;
        const size_t base = (size_t)ch * 8192 + ((k >> 6) << 7) + (k & 63);
        *reinterpret_cast<uint2*>(Y2 + base)      = H;
        *reinterpret_cast<uint2*>(Y2 + base + 64) = L;
    }
}

// ---------------------------------------------------------------------------
// Combine (16 -> 32): out[b,g,n] = relu(bias[g] + sum_{k,f} W[g,k,f] z_k[b,f,n])
// ---------------------------------------------------------------------------
__global__ __launch_bounds__(256)
void combine_k3(const float* __restrict__ z0, const float* __restrict__ z1,
                const float* __restrict__ z2, const float* __restrict__ W,
                const float* __restrict__ bias, float* __restrict__ out)
{
    __shared__ float Ws[32 * 48];
    const int tid = threadIdx.x;
    for (int i = tid; i < 32 * 48; i += 256) Ws[i] = W[i];
    __syncthreads();

    const int n = blockIdx.x * 256 + tid;
    const int b = blockIdx.y;
    float acc[32];
#pragma unroll
    for (int g = 0; g < 32; g++) acc[g] = bias[g];
    const float* zs[3] = {z0, z1, z2};
#pragma unroll
    for (int k = 0; k < 3; k++) {
        const float* z = zs[k];
#pragma unroll
        for (int f = 0; f < 16; f++) {
            float zv = z[((size_t)b * 16 + f) * NNODES + n];
#pragma unroll
            for (int g = 0; g < 32; g++) acc[g] += Ws[g * 48 + k * 16 + f] * zv;
        }
    }
#pragma unroll
    for (int g = 0; g < 32; g++)
        out[((size_t)b * 32 + g) * NNODES + n] = fmaxf(acc[g], 0.f);
}

// ---------------------------------------------------------------------------
// Projection (32 -> 16): v_k[b,g,n] = sum_f W[g,k,f] x[b,f,n]
// k=0,1 -> fp32; k=2 -> combined fp16 hi|lo (next MMA A operand)
// ---------------------------------------------------------------------------
__global__ __launch_bounds__(256)
void proj_k3(const float* __restrict__ in, const float* __restrict__ W,
             float* __restrict__ v0, float* __restrict__ v1,
             __half* __restrict__ v2c)
{
    const int k = blockIdx.z;
    __shared__ float Ws[16 * 32];
    const int tid = threadIdx.x;
    for (int i = tid; i < 16 * 32; i += 256)
        Ws[i] = W[(i >> 5) * 96 + k * 32 + (i & 31)];
    __syncthreads();

    const int n = blockIdx.x * 256 + tid;
    const int b = blockIdx.y;
    float acc[16] = {};
#pragma unroll
    for (int f = 0; f < 32; f++) {
        float xv = in[((size_t)b * 32 + f) * NNODES + n];
#pragma unroll
        for (int g = 0; g < 16; g++) acc[g] += Ws[g * 32 + f] * xv;
    }
    if (k < 2) {
        float* v = (k == 0) ? v0 : v1;
#pragma unroll
        for (int g = 0; g < 16; g++)
            v[((size_t)b * 16 + g) * NNODES + n] = acc[g];
    } else {
        const size_t kpos = (size_t)((n >> 6) << 7) + (n & 63);
#pragma unroll
        for (int g = 0; g < 16; g++) {
            const size_t o = (size_t)(b * 16 + g) * 8192 + kpos;
            __half h = __float2half_rn(acc[g]);
            v2c[o]      = h;
            v2c[o + 64] = __float2half_rn(acc[g] - __half2float(h));
        }
    }
}

// ---------------------------------------------------------------------------
// MLP head. mlp1b: partial dot products, grid (8 j-groups, 8 k-slices).
// ---------------------------------------------------------------------------
__global__ __launch_bounds__(256)
void mlp1b(const float* __restrict__ y, const float* __restrict__ W1,
           float* __restrict__ hp)
{
    const int jg = blockIdx.x;    // 8 groups of 8 outputs
    const int ks = blockIdx.y;    // 8 k-slices of 2048 float4
    const float4* Y4 = reinterpret_cast<const float4*>(y);
    const float4* W4 = reinterpret_cast<const float4*>(W1);

    float s[8][8] = {};           // [jj][b]
    for (int i = threadIdx.x; i < 2048; i += 256) {
        const int off = ks * 2048 + i;
        float4 yv[8];
#pragma unroll
        for (int b = 0; b < 8; b++) yv[b] = Y4[(size_t)b * 16384 + off];
#pragma unroll
        for (int jj = 0; jj < 8; jj++) {
            float4 w = W4[(size_t)(jg * 8 + jj) * 16384 + off];
#pragma unroll
            for (int b = 0; b < 8; b++)
                s[jj][b] += yv[b].x * w.x + yv[b].y * w.y + yv[b].z * w.z + yv[b].w * w.w;
        }
    }
    __shared__ float red[8][64];  // [warp][jj*8+b]
    const int wid = threadIdx.x >> 5, lane = threadIdx.x & 31;
#pragma unroll
    for (int jj = 0; jj < 8; jj++)
#pragma unroll
        for (int b = 0; b < 8; b++) {
            float v = s[jj][b];
#pragma unroll
            for (int o = 16; o > 0; o >>= 1) v += __shfl_down_sync(0xffffffffu, v, o);
            if (lane == 0) red[wid][jj * 8 + b] = v;
        }
    __syncthreads();
    if (threadIdx.x < 64) {
        const int jj = threadIdx.x >> 3, b = threadIdx.x & 7;
        float t = 0.f;
#pragma unroll
        for (int w = 0; w < 8; w++) t += red[w][jj * 8 + b];
        hp[((size_t)ks * 8 + b) * 64 + jg * 8 + jj] = t;
    }
}

__global__ __launch_bounds__(64)
void mlp2b(const float* __restrict__ hp, const float* __restrict__ b1,
           const float* __restrict__ W2, const float* __restrict__ b2,
           float* __restrict__ out)
{
    const int b = blockIdx.x, j = threadIdx.x;
    float hv = b1[j];
#pragma unroll
    for (int s = 0; s < 8; s++) hv += hp[((size_t)s * 8 + b) * 64 + j];
    float v = fmaxf(hv, 0.f) * W2[j];
#pragma unroll
    for (int o = 16; o > 0; o >>= 1) v += __shfl_down_sync(0xffffffffu, v, o);
    __shared__ float s2[2];
    if ((j & 31) == 0) s2[j >> 5] = v;
    __syncthreads();
    if (j == 0) out[b] = s2[0] + s2[1] + b2[0];
}

// ---------------------------------------------------------------------------
extern "C" void kernel_launch(void* const* d_in, const int* in_sizes, int n_in,
                              void* d_out, int out_size)
{
    const float* x   = (const float*)d_in[0];
    const float* Sc  = (const float*)d_in[1];
    const float* Sl  = (const float*)d_in[2];
    const float* Wc1 = (const float*)d_in[3];
    const float* bc1 = (const float*)d_in[4];
    const float* Wc2 = (const float*)d_in[5];
    const float* bc2 = (const float*)d_in[6];
    const float* Wl1 = (const float*)d_in[7];
    const float* bl1 = (const float*)d_in[8];
    const float* Wl2 = (const float*)d_in[9];
    const float* bl2 = (const float*)d_in[10];
    const float* Wm1 = (const float*)d_in[11];
    const float* bm1 = (const float*)d_in[12];
    const float* Wm2 = (const float*)d_in[13];
    const float* bm2 = (const float*)d_in[14];
    float* out = (float*)d_out;

    cudaFuncSetAttribute(gemm_tc, cudaFuncAttributeMaxDynamicSharedMemorySize, SMEMSZ);

    __half *Sc2, *Sl2, *x2, *a2, *b2;
    float *part, *z1f, *z2f, *v0, *v1, *y32, *y16, *hp;
    cudaGetSymbolAddress((void**)&Sc2, g_Sc2); cudaGetSymbolAddress((void**)&Sl2, g_Sl2);
    cudaGetSymbolAddress((void**)&x2, g_x2);
    cudaGetSymbolAddress((void**)&a2, g_a2);   cudaGetSymbolAddress((void**)&b2, g_b2);
    cudaGetSymbolAddress((void**)&part, g_part);
    cudaGetSymbolAddress((void**)&z1f, g_z1f); cudaGetSymbolAddress((void**)&z2f, g_z2f);
    cudaGetSymbolAddress((void**)&v0, g_v0);   cudaGetSymbolAddress((void**)&v1, g_v1);
    cudaGetSymbolAddress((void**)&y32, g_y32); cudaGetSymbolAddress((void**)&y16, g_y16);
    cudaGetSymbolAddress((void**)&hp, g_hp);

    const int SN4 = NNODES * NNODES / 4;          // 4M float4
    const int XN4 = CC * NNODES / 4;              // 128K float4
    cvtS<<<SN4 / 256, 256>>>((const float4*)Sc, Sc2, SN4);
    cvtS<<<SN4 / 256, 256>>>((const float4*)Sl, Sl2, SN4);
    cvtA<<<XN4 / 256, 256>>>((const float4*)x,  x2,  XN4);

    const dim3 gG(NNODES / NT, SPLITK);           // 16 x 8 = 128 CTAs
    const dim3 gR(CC * NNODES / 4 / 256);         // 512 blocks
    const dim3 gC(NNODES / 256, BATCH);
    const dim3 gP(NNODES / 256, BATCH, 3);

    // ---- Layer 1 (clique, 16 -> 32) ----
    gemm_tc<<<gG, 512, SMEMSZ>>>(x2, Sc2, part);
    reduce_splitk<0><<<gR, 256>>>(part, nullptr, nullptr, z1f, a2);
    gemm_tc<<<gG, 512, SMEMSZ>>>(a2, Sc2, part);
    reduce_splitk<0><<<gR, 256>>>(part, nullptr, nullptr, z2f, nullptr);
    combine_k3<<<gC, 256>>>(x, z1f, z2f, Wc1, bc1, y32);

    // ---- Layer 2 (clique, 32 -> 16): project then Horner ----
    proj_k3<<<gP, 256>>>(y32, Wc2, v0, v1, b2);
    gemm_tc<<<gG, 512, SMEMSZ>>>(b2, Sc2, part);
    reduce_splitk<1><<<gR, 256>>>(part, v1, nullptr, nullptr, a2);
    gemm_tc<<<gG, 512, SMEMSZ>>>(a2, Sc2, part);
    reduce_splitk<2><<<gR, 256>>>(part, v0, bc2, y16, b2);

    // ---- Layer 3 (line, 16 -> 32) ----
    gemm_tc<<<gG, 512, SMEMSZ>>>(b2, Sl2, part);
    reduce_splitk<0><<<gR, 256>>>(part, nullptr, nullptr, z1f, a2);
    gemm_tc<<<gG, 512, SMEMSZ>>>(a2, Sl2, part);
    reduce_splitk<0><<<gR, 256>>>(part, nullptr, nullptr, z2f, nullptr);
    combine_k3<<<gC, 256>>>(y16, z1f, z2f, Wl1, bl1, y32);

    // ---- Layer 4 (line, 32 -> 16) ----
    proj_k3<<<gP, 256>>>(y32, Wl2, v0, v1, b2);
    gemm_tc<<<gG, 512, SMEMSZ>>>(b2, Sl2, part);
    reduce_splitk<1><<<gR, 256>>>(part, v1, nullptr, nullptr, a2);
    gemm_tc<<<gG, 512, SMEMSZ>>>(a2, Sl2, part);
    reduce_splitk<2><<<gR, 256>>>(part, v0, bl2, y16, nullptr);

    // ---- MLP head ----
    mlp1b<<<dim3(8, 8), 256>>>(y16, Wm1, hp);
    mlp2b<<<BATCH, 64>>>(hp, bm1, Wm2, bm2, out);
}

// round 8
// speedup vs baseline: 5.4374x; 1.0899x over previous
#include <cuda_runtime.h>
#include <cuda_fp16.h>
#include <cstdint>

// ---------------------------------------------------------------------------
// SelectionGNN (clique+line), B=8, N=4096, E=1, K=3, F=[16,32,16]
// Diffusion GEMMs (8x: 128x4096x4096) via mma.sync fp16 2-pass:
//   D = Ah*Bh + Al*Bh  (A fp16 hi/lo split, B = fp16(S) hi only), fp32 accum.
// Operands stored in gmem PRE-TILED + PRE-SWIZZLED: each 64-k tile is a
// contiguous 32KB block that is byte-for-byte the smem image (128B rows,
// chunk XOR (row&7) swizzle -> conflict-free ldmatrix). Producer = ONE thread
// issuing one expect_tx + two 32KB cp.async.bulk per tile. 3-stage pipeline.
// CTA tile 128x256, warp tile 32x64 (16 warps), SPLITK=8 -> 128 CTAs.
//
// A tile (per kt): 128 rows x 256B  [hi 128B | lo 128B], swizzled per half.
// B tile (per nb,kt): 256 rows x 128B, swizzled.
// ---------------------------------------------------------------------------

#define NNODES 4096
#define BATCH  8
#define CC     128                 // channels = B*16 (GEMM M)
#define NT     256                 // n-tile per CTA
#define SPLITK 8
#define KC     (NNODES / SPLITK)   // 512 k per CTA
#define NKT    (KC / 64)           // 8 k-tiles (64 k each)
#define NKTOT  (NNODES / 64)       // 64 k-tiles total

#define ATILE_H  16384             // A tile halves (32KB)
#define BTILE_H  16384             // B tile halves (32KB)
#define STAGESZ  65536             // bytes: A(32K) + B(32K)
#define NSTAGE   3
#define SMEMSZ   (64 + NSTAGE * STAGESZ)   // 196672

// ---------------- scratch (device globals; allocation is forbidden) --------
__device__ __align__(256) __half g_Sc2[(size_t)NNODES * NNODES];   // 32MB tiled
__device__ __align__(256) __half g_Sl2[(size_t)NNODES * NNODES];   // 32MB tiled
__device__ __align__(256) __half g_x2 [NKTOT * ATILE_H];           // 2MB tiled
__device__ __align__(256) __half g_a2 [NKTOT * ATILE_H];
__device__ __align__(256) __half g_b2 [NKTOT * ATILE_H];
__device__ __align__(256) float g_part[SPLITK * CC * NNODES];      // 16.8 MB
__device__ __align__(256) float g_z1f [CC * NNODES];
__device__ __align__(256) float g_z2f [CC * NNODES];
__device__ __align__(256) float g_v0  [CC * NNODES];
__device__ __align__(256) float g_v1  [CC * NNODES];
__device__ __align__(256) float g_y32 [BATCH * 32 * NNODES];
__device__ __align__(256) float g_y16 [CC * NNODES];
__device__ __align__(256) float g_hp  [8 * BATCH * 64];

// ---------------- PTX helpers (baseline sm_90-level PTX only) ---------------
__device__ __forceinline__ uint32_t smem_u32(const void* p) {
    uint32_t a;
    asm("{ .reg .u64 t; cvta.to.shared.u64 t, %1; cvt.u32.u64 %0, t; }" : "=r"(a) : "l"(p));
    return a;
}
#define MBAR_INIT(a, c) asm volatile("mbarrier.init.shared.b64 [%0], %1;" :: "r"(a), "r"(c) : "memory")

#define MBAR_WAIT(mbar, par) do {                                              \
    uint32_t _m = (mbar), _p = (par), _d;                                      \
    asm volatile("{ .reg .pred p;"                                             \
        " mbarrier.try_wait.parity.acquire.cta.shared::cta.b64 p, [%1], %2;"   \
        " selp.b32 %0, 1, 0, p; }" : "=r"(_d) : "r"(_m), "r"(_p) : "memory");  \
    if (!_d) {                                                                 \
        asm volatile("{ .reg .pred P1;"                                        \
        " W%=: mbarrier.try_wait.parity.acquire.cta.shared::cta.b64 P1, [%0], %1, 0x989680;" \
        " @P1 bra.uni D%=; bra.uni W%=; D%=: }" :: "r"(_m), "r"(_p) : "memory"); } \
} while (0)

#define MBAR_EXPECT(mbar, bytes) \
    asm volatile("mbarrier.arrive.expect_tx.shared.b64 _, [%0], %1;" :: "r"(mbar), "r"(bytes) : "memory")

#define BULK_G2S(dst, src, bytes, mbar) \
    asm volatile("cp.async.bulk.shared::cluster.global.mbarrier::complete_tx::bytes [%0], [%1], %2, [%3];" \
                 :: "r"(dst), "l"(src), "r"(bytes), "r"(mbar) : "memory")

__device__ __forceinline__ void ldsm4(uint32_t& r0, uint32_t& r1, uint32_t& r2,
                                      uint32_t& r3, uint32_t addr) {
    asm volatile("ldmatrix.sync.aligned.m8n8.x4.shared.b16 {%0,%1,%2,%3}, [%4];"
                 : "=r"(r0), "=r"(r1), "=r"(r2), "=r"(r3) : "r"(addr));
}
__device__ __forceinline__ void mma16816(float& d0, float& d1, float& d2, float& d3,
                                         uint32_t a0, uint32_t a1, uint32_t a2, uint32_t a3,
                                         uint32_t b0, uint32_t b1) {
    asm volatile("mma.sync.aligned.m16n8k16.row.col.f32.f16.f16.f32 "
                 "{%0,%1,%2,%3}, {%4,%5,%6,%7}, {%8,%9}, {%0,%1,%2,%3};"
                 : "+f"(d0), "+f"(d1), "+f"(d2), "+f"(d3)
                 : "r"(a0), "r"(a1), "r"(a2), "r"(a3), "r"(b0), "r"(b1));
}

// ---------------------------------------------------------------------------
// Diffusion GEMM. A2 tiled [64 kt][128r][256B], B2 tiled [16 nb][64 kt][256r][128B]
// grid = (16 nb, 8 split), 512 threads, 16 warps (4x4), warp tile 32x64.
// ---------------------------------------------------------------------------
__global__ __launch_bounds__(512, 1)
void gemm_tc(const __half* __restrict__ A2,
             const __half* __restrict__ B2,
             float* __restrict__ part)
{
    extern __shared__ __align__(16) char smem[];
    const uint32_t sb  = smem_u32(smem);
    const uint32_t st0 = sb + 64;

    const int tid  = threadIdx.x;
    const int wid  = tid >> 5, lane = tid & 31;
    const int wm   = wid >> 2;            // 0..3 -> m offset wm*32
    const int wn   = wid & 3;             // 0..3 -> n offset wn*64
    const int nb   = blockIdx.x;
    const int n0   = nb * NT;
    const int split = blockIdx.y;

    if (tid == 0) {
        MBAR_INIT(sb + 0, 1);
        MBAR_INIT(sb + 8, 1);
        MBAR_INIT(sb + 16, 1);
    }
    __syncthreads();

    const __half* Asrc = A2 + (size_t)(split * NKT) * ATILE_H;
    const __half* Bsrc = B2 + (size_t)(nb * NKTOT + split * NKT) * BTILE_H;

    auto load_tile = [&](int tt) {
        if (tid == 0) {
            const uint32_t s    = (uint32_t)(tt % 3);
            const uint32_t mbar = sb + s * 8;
            const uint32_t dst  = st0 + s * STAGESZ;
            MBAR_EXPECT(mbar, 65536u);
            BULK_G2S(dst,          Asrc + (size_t)tt * ATILE_H, 32768u, mbar);
            BULK_G2S(dst + 32768u, Bsrc + (size_t)tt * BTILE_H, 32768u, mbar);
        }
    };

    load_tile(0); load_tile(1); load_tile(2);

    // ---- ldsm row bases (bytes within a stage) ----
    const int r8  = lane & 7;
    const int seg = lane >> 3;            // 0..3
    const int sak = seg >> 1;             // A: k8 selector
    const int sam = seg & 1;              // A: m8 selector
    const int sbn = seg >> 1;             // B: n8 selector
    const int sbk = seg & 1;              // B: k8 selector
    uint32_t baseA[2];
#pragma unroll
    for (int mt = 0; mt < 2; mt++)
        baseA[mt] = (uint32_t)((wm * 32 + mt * 16 + sam * 8 + r8) * 256);
    uint32_t baseB[4];
#pragma unroll
    for (int p = 0; p < 4; p++)
        baseB[p] = (uint32_t)(32768 + (wn * 64 + p * 16 + sbn * 8 + r8) * 128);

    float acc[2][8][4] = {};

#pragma unroll 1
    for (int tt = 0; tt < NKT; tt++) {
        const uint32_t s = (uint32_t)(tt % 3);
        MBAR_WAIT(sb + s * 8, (uint32_t)((tt / 3) & 1));

        const uint32_t st = st0 + s * STAGESZ;

#pragma unroll
        for (int ks = 0; ks < 4; ks++) {
            const uint32_t offA = (uint32_t)(((ks * 2 + sak) ^ r8) << 4);
            const uint32_t offB = (uint32_t)(((ks * 2 + sbk) ^ r8) << 4);
            uint32_t ah[2][4], al[2][4];
#pragma unroll
            for (int mt = 0; mt < 2; mt++) {
                const uint32_t a = st + baseA[mt] + offA;
                ldsm4(ah[mt][0], ah[mt][1], ah[mt][2], ah[mt][3], a);
                ldsm4(al[mt][0], al[mt][1], al[mt][2], al[mt][3], a + 128);
            }
            uint32_t bh[8][2];
#pragma unroll
            for (int p = 0; p < 4; p++) {
                const uint32_t b = st + baseB[p] + offB;
                ldsm4(bh[2*p][0], bh[2*p][1], bh[2*p+1][0], bh[2*p+1][1], b);
            }
            // pass 1: hi*hi (16 independent MMAs)
#pragma unroll
            for (int mt = 0; mt < 2; mt++)
#pragma unroll
                for (int nt = 0; nt < 8; nt++)
                    mma16816(acc[mt][nt][0], acc[mt][nt][1], acc[mt][nt][2], acc[mt][nt][3],
                             ah[mt][0], ah[mt][1], ah[mt][2], ah[mt][3],
                             bh[nt][0], bh[nt][1]);
            // pass 2: lo*hi
#pragma unroll
            for (int mt = 0; mt < 2; mt++)
#pragma unroll
                for (int nt = 0; nt < 8; nt++)
                    mma16816(acc[mt][nt][0], acc[mt][nt][1], acc[mt][nt][2], acc[mt][nt][3],
                             al[mt][0], al[mt][1], al[mt][2], al[mt][3],
                             bh[nt][0], bh[nt][1]);
        }
        __syncthreads();                   // stage s consumed by all warps
        if (tt + 3 < NKT) load_tile(tt + 3);
    }

    // ---- epilogue: D frag -> part[(split*128 + c) * 4096 + n] ----
    const int mrow = lane >> 2;           // 0..7
    const int ncol = (lane & 3) * 2;      // 0,2,4,6
#pragma unroll
    for (int mt = 0; mt < 2; mt++) {
#pragma unroll
        for (int nt = 0; nt < 8; nt++) {
            const int c = wm * 32 + mt * 16 + mrow;
            const int n = n0 + wn * 64 + nt * 8 + ncol;
            float* d0 = part + ((size_t)(split * CC + c)) * NNODES + n;
            float* d1 = part + ((size_t)(split * CC + c + 8)) * NNODES + n;
            *reinterpret_cast<float2*>(d0) = make_float2(acc[mt][nt][0], acc[mt][nt][1]);
            *reinterpret_cast<float2*>(d1) = make_float2(acc[mt][nt][2], acc[mt][nt][3]);
        }
    }
}

// ---------------------------------------------------------------------------
// fp32 -> fp16 hi/lo split helper
// ---------------------------------------------------------------------------
__device__ __forceinline__ void split4h(float4 a, uint2& H, uint2& L) {
    __half h0 = __float2half_rn(a.x), h1 = __float2half_rn(a.y);
    __half h2 = __float2half_rn(a.z), h3 = __float2half_rn(a.w);
    __half l0 = __float2half_rn(a.x - __half2float(h0));
    __half l1 = __float2half_rn(a.y - __half2float(h1));
    __half l2 = __float2half_rn(a.z - __half2float(h2));
    __half l3 = __float2half_rn(a.w - __half2float(h3));
    H.x = ((uint32_t)__half_as_ushort(h1) << 16) | __half_as_ushort(h0);
    H.y = ((uint32_t)__half_as_ushort(h3) << 16) | __half_as_ushort(h2);
    L.x = ((uint32_t)__half_as_ushort(l1) << 16) | __half_as_ushort(l0);
    L.y = ((uint32_t)__half_as_ushort(l3) << 16) | __half_as_ushort(l2);
}

// S: fp32 [4096][4096] -> fp16 hi-only, tiled+swizzled B layout:
// tile (nb = n>>8, kt = k>>6), row r = n&255, chunk c = (k&63)>>3
// halfidx = (nb*64+kt)*16384 + r*64 + ((c ^ (r&7))<<3) + (k&7)
__global__ __launch_bounds__(256)
void cvtS(const float4* __restrict__ in, __half* __restrict__ out, int n4)
{
    int i = blockIdx.x * 256 + threadIdx.x;
    if (i >= n4) return;
    float4 a = in[i];
    __half h0 = __float2half_rn(a.x), h1 = __float2half_rn(a.y);
    __half h2 = __float2half_rn(a.z), h3 = __float2half_rn(a.w);
    uint2 H;
    H.x = ((uint32_t)__half_as_ushort(h1) << 16) | __half_as_ushort(h0);
    H.y = ((uint32_t)__half_as_ushort(h3) << 16) | __half_as_ushort(h2);
    const int e  = i * 4;
    const int n  = e >> 12, k = e & 4095;
    const int nb = n >> 8,  r = n & 255;
    const int kt = k >> 6,  c = (k & 63) >> 3;
    const size_t base = (size_t)(nb * NKTOT + kt) * BTILE_H
                      + r * 64 + ((c ^ (r & 7)) << 3) + (k & 7);
    *reinterpret_cast<uint2*>(out + base) = H;
}

// A-type: fp32 [128][4096] -> fp16 hi/lo, tiled+swizzled A layout:
// halfidx = kt*16384 + row*128 + half*64 + ((c ^ (row&7))<<3) + (k&7)
__device__ __forceinline__ size_t a2_index(int row, int k) {
    const int kt = k >> 6, c = (k & 63) >> 3;
    return (size_t)kt * ATILE_H + row * 128 + ((c ^ (row & 7)) << 3) + (k & 7);
}

__global__ __launch_bounds__(256)
void cvtA(const float4* __restrict__ in, __half* __restrict__ out, int n4)
{
    int i = blockIdx.x * 256 + threadIdx.x;
    if (i >= n4) return;
    uint2 H, L;
    split4h(in[i], H, L);
    const int e   = i * 4;
    const int row = e >> 12, k = e & 4095;
    const size_t base = a2_index(row, k);
    *reinterpret_cast<uint2*>(out + base)      = H;
    *reinterpret_cast<uint2*>(out + base + 64) = L;
}

// ---------------------------------------------------------------------------
// split-K reduce + epilogue. MODE 0: Y = sum; 1: Y = sum + V; 2: relu(sum+V+b)
// ---------------------------------------------------------------------------
template <int MODE>
__global__ __launch_bounds__(256)
void reduce_splitk(const float* __restrict__ part, const float* __restrict__ V,
                   const float* __restrict__ bias, float* __restrict__ Yf,
                   __half* __restrict__ Y2)
{
    const int i = blockIdx.x * 256 + threadIdx.x;          // float4 index
    const float4* p = reinterpret_cast<const float4*>(part);
    const int STR = CC * NNODES / 4;
    float4 a = p[i];
#pragma unroll
    for (int s = 1; s < SPLITK; s++) {
        float4 q = p[i + s * STR];
        a.x += q.x; a.y += q.y; a.z += q.z; a.w += q.w;
    }
    if (MODE >= 1) {
        float4 v = reinterpret_cast<const float4*>(V)[i];
        a.x += v.x; a.y += v.y; a.z += v.z; a.w += v.w;
    }
    const int e  = i * 4;
    const int ch = e >> 12;                                // 0..127
    if (MODE == 2) {
        const float bv = bias[ch & 15];
        a.x = fmaxf(a.x + bv, 0.f); a.y = fmaxf(a.y + bv, 0.f);
        a.z = fmaxf(a.z + bv, 0.f); a.w = fmaxf(a.w + bv, 0.f);
    }
    if (Yf) reinterpret_cast<float4*>(Yf)[i] = a;
    if (Y2) {
        uint2 H, L;
        split4h(a, H, L);
        const size_t base = a2_index(ch, e & 4095);
        *reinterpret_cast<uint2*>(Y2 + base)      = H;
        *reinterpret_cast<uint2*>(Y2 + base + 64) = L;
    }
}

// ---------------------------------------------------------------------------
// Combine (16 -> 32): out[b,g,n] = relu(bias[g] + sum_{k,f} W[g,k,f] z_k[b,f,n])
// ---------------------------------------------------------------------------
__global__ __launch_bounds__(256)
void combine_k3(const float* __restrict__ z0, const float* __restrict__ z1,
                const float* __restrict__ z2, const float* __restrict__ W,
                const float* __restrict__ bias, float* __restrict__ out)
{
    __shared__ float Ws[32 * 48];
    const int tid = threadIdx.x;
    for (int i = tid; i < 32 * 48; i += 256) Ws[i] = W[i];
    __syncthreads();

    const int n = blockIdx.x * 256 + tid;
    const int b = blockIdx.y;
    float acc[32];
#pragma unroll
    for (int g = 0; g < 32; g++) acc[g] = bias[g];
    const float* zs[3] = {z0, z1, z2};
#pragma unroll
    for (int k = 0; k < 3; k++) {
        const float* z = zs[k];
#pragma unroll
        for (int f = 0; f < 16; f++) {
            float zv = z[((size_t)b * 16 + f) * NNODES + n];
#pragma unroll
            for (int g = 0; g < 32; g++) acc[g] += Ws[g * 48 + k * 16 + f] * zv;
        }
    }
#pragma unroll
    for (int g = 0; g < 32; g++)
        out[((size_t)b * 32 + g) * NNODES + n] = fmaxf(acc[g], 0.f);
}

// ---------------------------------------------------------------------------
// Projection (32 -> 16): v_k[b,g,n] = sum_f W[g,k,f] x[b,f,n]
// k=0,1 -> fp32; k=2 -> tiled+swizzled fp16 hi/lo (next MMA A operand)
// ---------------------------------------------------------------------------
__global__ __launch_bounds__(256)
void proj_k3(const float* __restrict__ in, const float* __restrict__ W,
             float* __restrict__ v0, float* __restrict__ v1,
             __half* __restrict__ v2c)
{
    const int k = blockIdx.z;
    __shared__ float Ws[16 * 32];
    const int tid = threadIdx.x;
    for (int i = tid; i < 16 * 32; i += 256)
        Ws[i] = W[(i >> 5) * 96 + k * 32 + (i & 31)];
    __syncthreads();

    const int n = blockIdx.x * 256 + tid;
    const int b = blockIdx.y;
    float acc[16] = {};
#pragma unroll
    for (int f = 0; f < 32; f++) {
        float xv = in[((size_t)b * 32 + f) * NNODES + n];
#pragma unroll
        for (int g = 0; g < 16; g++) acc[g] += Ws[g * 32 + f] * xv;
    }
    if (k < 2) {
        float* v = (k == 0) ? v0 : v1;
#pragma unroll
        for (int g = 0; g < 16; g++)
            v[((size_t)b * 16 + g) * NNODES + n] = acc[g];
    } else {
#pragma unroll
        for (int g = 0; g < 16; g++) {
            const size_t o = a2_index(b * 16 + g, n);
            __half h = __float2half_rn(acc[g]);
            v2c[o]      = h;
            v2c[o + 64] = __float2half_rn(acc[g] - __half2float(h));
        }
    }
}

// ---------------------------------------------------------------------------
// MLP head. mlp1b: partial dot products, grid (8 j-groups, 8 k-slices).
// ---------------------------------------------------------------------------
__global__ __launch_bounds__(256)
void mlp1b(const float* __restrict__ y, const float* __restrict__ W1,
           float* __restrict__ hp)
{
    const int jg = blockIdx.x;    // 8 groups of 8 outputs
    const int ks = blockIdx.y;    // 8 k-slices of 2048 float4
    const float4* Y4 = reinterpret_cast<const float4*>(y);
    const float4* W4 = reinterpret_cast<const float4*>(W1);

    float s[8][8] = {};           // [jj][b]
    for (int i = threadIdx.x; i < 2048; i += 256) {
        const int off = ks * 2048 + i;
        float4 yv[8];
#pragma unroll
        for (int b = 0; b < 8; b++) yv[b] = Y4[(size_t)b * 16384 + off];
#pragma unroll
        for (int jj = 0; jj < 8; jj++) {
            float4 w = W4[(size_t)(jg * 8 + jj) * 16384 + off];
#pragma unroll
            for (int b = 0; b < 8; b++)
                s[jj][b] += yv[b].x * w.x + yv[b].y * w.y + yv[b].z * w.z + yv[b].w * w.w;
        }
    }
    __shared__ float red[8][64];  // [warp][jj*8+b]
    const int wid = threadIdx.x >> 5, lane = threadIdx.x & 31;
#pragma unroll
    for (int jj = 0; jj < 8; jj++)
#pragma unroll
        for (int b = 0; b < 8; b++) {
            float v = s[jj][b];
#pragma unroll
            for (int o = 16; o > 0; o >>= 1) v += __shfl_down_sync(0xffffffffu, v, o);
            if (lane == 0) red[wid][jj * 8 + b] = v;
        }
    __syncthreads();
    if (threadIdx.x < 64) {
        const int jj = threadIdx.x >> 3, b = threadIdx.x & 7;
        float t = 0.f;
#pragma unroll
        for (int w = 0; w < 8; w++) t += red[w][jj * 8 + b];
        hp[((size_t)ks * 8 + b) * 64 + jg * 8 + jj] = t;
    }
}

__global__ __launch_bounds__(64)
void mlp2b(const float* __restrict__ hp, const float* __restrict__ b1,
           const float* __restrict__ W2, const float* __restrict__ b2,
           float* __restrict__ out)
{
    const int b = blockIdx.x, j = threadIdx.x;
    float hv = b1[j];
#pragma unroll
    for (int s = 0; s < 8; s++) hv += hp[((size_t)s * 8 + b) * 64 + j];
    float v = fmaxf(hv, 0.f) * W2[j];
#pragma unroll
    for (int o = 16; o > 0; o >>= 1) v += __shfl_down_sync(0xffffffffu, v, o);
    __shared__ float s2[2];
    if ((j & 31) == 0) s2[j >> 5] = v;
    __syncthreads();
    if (j == 0) out[b] = s2[0] + s2[1] + b2[0];
}

// ---------------------------------------------------------------------------
extern "C" void kernel_launch(void* const* d_in, const int* in_sizes, int n_in,
                              void* d_out, int out_size)
{
    const float* x   = (const float*)d_in[0];
    const float* Sc  = (const float*)d_in[1];
    const float* Sl  = (const float*)d_in[2];
    const float* Wc1 = (const float*)d_in[3];
    const float* bc1 = (const float*)d_in[4];
    const float* Wc2 = (const float*)d_in[5];
    const float* bc2 = (const float*)d_in[6];
    const float* Wl1 = (const float*)d_in[7];
    const float* bl1 = (const float*)d_in[8];
    const float* Wl2 = (const float*)d_in[9];
    const float* bl2 = (const float*)d_in[10];
    const float* Wm1 = (const float*)d_in[11];
    const float* bm1 = (const float*)d_in[12];
    const float* Wm2 = (const float*)d_in[13];
    const float* bm2 = (const float*)d_in[14];
    float* out = (float*)d_out;

    cudaFuncSetAttribute(gemm_tc, cudaFuncAttributeMaxDynamicSharedMemorySize, SMEMSZ);

    __half *Sc2, *Sl2, *x2, *a2, *b2;
    float *part, *z1f, *z2f, *v0, *v1, *y32, *y16, *hp;
    cudaGetSymbolAddress((void**)&Sc2, g_Sc2); cudaGetSymbolAddress((void**)&Sl2, g_Sl2);
    cudaGetSymbolAddress((void**)&x2, g_x2);
    cudaGetSymbolAddress((void**)&a2, g_a2);   cudaGetSymbolAddress((void**)&b2, g_b2);
    cudaGetSymbolAddress((void**)&part, g_part);
    cudaGetSymbolAddress((void**)&z1f, g_z1f); cudaGetSymbolAddress((void**)&z2f, g_z2f);
    cudaGetSymbolAddress((void**)&v0, g_v0);   cudaGetSymbolAddress((void**)&v1, g_v1);
    cudaGetSymbolAddress((void**)&y32, g_y32); cudaGetSymbolAddress((void**)&y16, g_y16);
    cudaGetSymbolAddress((void**)&hp, g_hp);

    const int SN4 = NNODES * NNODES / 4;          // 4M float4
    const int XN4 = CC * NNODES / 4;              // 128K float4
    cvtS<<<SN4 / 256, 256>>>((const float4*)Sc, Sc2, SN4);
    cvtS<<<SN4 / 256, 256>>>((const float4*)Sl, Sl2, SN4);
    cvtA<<<XN4 / 256, 256>>>((const float4*)x,  x2,  XN4);

    const dim3 gG(NNODES / NT, SPLITK);           // 16 x 8 = 128 CTAs
    const dim3 gR(CC * NNODES / 4 / 256);         // 512 blocks
    const dim3 gC(NNODES / 256, BATCH);
    const dim3 gP(NNODES / 256, BATCH, 3);

    // ---- Layer 1 (clique, 16 -> 32) ----
    gemm_tc<<<gG, 512, SMEMSZ>>>(x2, Sc2, part);
    reduce_splitk<0><<<gR, 256>>>(part, nullptr, nullptr, z1f, a2);
    gemm_tc<<<gG, 512, SMEMSZ>>>(a2, Sc2, part);
    reduce_splitk<0><<<gR, 256>>>(part, nullptr, nullptr, z2f, nullptr);
    combine_k3<<<gC, 256>>>(x, z1f, z2f, Wc1, bc1, y32);

    // ---- Layer 2 (clique, 32 -> 16): project then Horner ----
    proj_k3<<<gP, 256>>>(y32, Wc2, v0, v1, b2);
    gemm_tc<<<gG, 512, SMEMSZ>>>(b2, Sc2, part);
    reduce_splitk<1><<<gR, 256>>>(part, v1, nullptr, nullptr, a2);
    gemm_tc<<<gG, 512, SMEMSZ>>>(a2, Sc2, part);
    reduce_splitk<2><<<gR, 256>>>(part, v0, bc2, y16, b2);

    // ---- Layer 3 (line, 16 -> 32) ----
    gemm_tc<<<gG, 512, SMEMSZ>>>(b2, Sl2, part);
    reduce_splitk<0><<<gR, 256>>>(part, nullptr, nullptr, z1f, a2);
    gemm_tc<<<gG, 512, SMEMSZ>>>(a2, Sl2, part);
    reduce_splitk<0><<<gR, 256>>>(part, nullptr, nullptr, z2f, nullptr);
    combine_k3<<<gC, 256>>>(y16, z1f, z2f, Wl1, bl1, y32);

    // ---- Layer 4 (line, 32 -> 16) ----
    proj_k3<<<gP, 256>>>(y32, Wl2, v0, v1, b2);
    gemm_tc<<<gG, 512, SMEMSZ>>>(b2, Sl2, part);
    reduce_splitk<1><<<gR, 256>>>(part, v1, nullptr, nullptr, a2);
    gemm_tc<<<gG, 512, SMEMSZ>>>(a2, Sl2, part);
    reduce_splitk<2><<<gR, 256>>>(part, v0, bl2, y16, nullptr);

    // ---- MLP head ----
    mlp1b<<<dim3(8, 8), 256>>>(y16, Wm1, hp);
    mlp2b<<<BATCH, 64>>>(hp, bm1, Wm2, bm2, out);
}

// round 9
// speedup vs baseline: 5.6720x; 1.0432x over previous
#include <cuda_runtime.h>
#include <cuda_fp16.h>
#include <cstdint>

// ---------------------------------------------------------------------------
// SelectionGNN (clique+line), B=8, N=4096, E=1, K=3, F=[16,32,16]
// Diffusion GEMMs (8x: 128x4096x4096) via mma.sync fp16 2-pass:
//   D = Ah*Bh + Al*Bh  (A fp16 hi/lo split, B = fp16(S) hi only), fp32 accum.
// Operands PRE-TILED + PRE-SWIZZLED in gmem (32KB tile = smem image).
// Producer = thread 0: one expect_tx + two 32KB cp.async.bulk per tile.
// Consumer/producer sync via full/empty mbarriers (NO per-tile __syncthreads):
// each warp arrives on empty[s] independently; only thread 0 waits for all.
// CTA tile 128x256, warp tile 32x64 (16 warps), SPLITK=8 -> 128 CTAs.
// ---------------------------------------------------------------------------

#define NNODES 4096
#define BATCH  8
#define CC     128                 // channels = B*16 (GEMM M)
#define NT     256                 // n-tile per CTA
#define SPLITK 8
#define KC     (NNODES / SPLITK)   // 512 k per CTA
#define NKT    (KC / 64)           // 8 k-tiles (64 k each)
#define NKTOT  (NNODES / 64)       // 64 k-tiles total

#define ATILE_H  16384             // A tile halves (32KB)
#define BTILE_H  16384             // B tile halves (32KB)
#define STAGESZ  65536             // bytes: A(32K) + B(32K)
#define NSTAGE   3
#define SMEMSZ   (64 + NSTAGE * STAGESZ)   // 196672

// ---------------- scratch (device globals; allocation is forbidden) --------
__device__ __align__(256) __half g_Sc2[(size_t)NNODES * NNODES];   // 32MB tiled
__device__ __align__(256) __half g_Sl2[(size_t)NNODES * NNODES];   // 32MB tiled
__device__ __align__(256) __half g_x2 [NKTOT * ATILE_H];           // 2MB tiled
__device__ __align__(256) __half g_a2 [NKTOT * ATILE_H];
__device__ __align__(256) __half g_b2 [NKTOT * ATILE_H];
__device__ __align__(256) float g_part[SPLITK * CC * NNODES];      // 16.8 MB
__device__ __align__(256) float g_z1f [CC * NNODES];
__device__ __align__(256) float g_z2f [CC * NNODES];
__device__ __align__(256) float g_v0  [CC * NNODES];
__device__ __align__(256) float g_v1  [CC * NNODES];
__device__ __align__(256) float g_y32 [BATCH * 32 * NNODES];
__device__ __align__(256) float g_y16 [CC * NNODES];
__device__ __align__(256) float g_hp  [8 * BATCH * 64];

// ---------------- PTX helpers (baseline sm_90-level PTX only) ---------------
__device__ __forceinline__ uint32_t smem_u32(const void* p) {
    uint32_t a;
    asm("{ .reg .u64 t; cvta.to.shared.u64 t, %1; cvt.u32.u64 %0, t; }" : "=r"(a) : "l"(p));
    return a;
}
#define MBAR_INIT(a, c) asm volatile("mbarrier.init.shared.b64 [%0], %1;" :: "r"(a), "r"(c) : "memory")

#define MBAR_WAIT(mbar, par) do {                                              \
    uint32_t _m = (mbar), _p = (par), _d;                                      \
    asm volatile("{ .reg .pred p;"                                             \
        " mbarrier.try_wait.parity.acquire.cta.shared::cta.b64 p, [%1], %2;"   \
        " selp.b32 %0, 1, 0, p; }" : "=r"(_d) : "r"(_m), "r"(_p) : "memory");  \
    if (!_d) {                                                                 \
        asm volatile("{ .reg .pred P1;"                                        \
        " W%=: mbarrier.try_wait.parity.acquire.cta.shared::cta.b64 P1, [%0], %1, 0x989680;" \
        " @P1 bra.uni D%=; bra.uni W%=; D%=: }" :: "r"(_m), "r"(_p) : "memory"); } \
} while (0)

#define MBAR_ARRIVE(mbar) \
    asm volatile("mbarrier.arrive.shared.b64 _, [%0];" :: "r"(mbar) : "memory")

#define MBAR_EXPECT(mbar, bytes) \
    asm volatile("mbarrier.arrive.expect_tx.shared.b64 _, [%0], %1;" :: "r"(mbar), "r"(bytes) : "memory")

#define BULK_G2S(dst, src, bytes, mbar) \
    asm volatile("cp.async.bulk.shared::cluster.global.mbarrier::complete_tx::bytes [%0], [%1], %2, [%3];" \
                 :: "r"(dst), "l"(src), "r"(bytes), "r"(mbar) : "memory")

__device__ __forceinline__ void ldsm4(uint32_t& r0, uint32_t& r1, uint32_t& r2,
                                      uint32_t& r3, uint32_t addr) {
    asm volatile("ldmatrix.sync.aligned.m8n8.x4.shared.b16 {%0,%1,%2,%3}, [%4];"
                 : "=r"(r0), "=r"(r1), "=r"(r2), "=r"(r3) : "r"(addr));
}
__device__ __forceinline__ void mma16816(float& d0, float& d1, float& d2, float& d3,
                                         uint32_t a0, uint32_t a1, uint32_t a2, uint32_t a3,
                                         uint32_t b0, uint32_t b1) {
    asm volatile("mma.sync.aligned.m16n8k16.row.col.f32.f16.f16.f32 "
                 "{%0,%1,%2,%3}, {%4,%5,%6,%7}, {%8,%9}, {%0,%1,%2,%3};"
                 : "+f"(d0), "+f"(d1), "+f"(d2), "+f"(d3)
                 : "r"(a0), "r"(a1), "r"(a2), "r"(a3), "r"(b0), "r"(b1));
}

// ---------------------------------------------------------------------------
// Diffusion GEMM. A2 tiled [64 kt][128r][256B], B2 tiled [16 nb][64 kt][256r][128B]
// grid = (16 nb, 8 split), 512 threads, 16 warps (4x4), warp tile 32x64.
// smem barriers: full[3] @ sb+0,8,16 (count 1, tx) ; empty[3] @ sb+24,32,40
// (count 16, one arrive per consumer warp).
// ---------------------------------------------------------------------------
__global__ __launch_bounds__(512, 1)
void gemm_tc(const __half* __restrict__ A2,
             const __half* __restrict__ B2,
             float* __restrict__ part)
{
    extern __shared__ __align__(16) char smem[];
    const uint32_t sb  = smem_u32(smem);
    const uint32_t st0 = sb + 64;

    const int tid  = threadIdx.x;
    const int wid  = tid >> 5, lane = tid & 31;
    const int wm   = wid >> 2;            // 0..3 -> m offset wm*32
    const int wn   = wid & 3;             // 0..3 -> n offset wn*64
    const int nb   = blockIdx.x;
    const int n0   = nb * NT;
    const int split = blockIdx.y;

    if (tid == 0) {
        MBAR_INIT(sb + 0, 1);   MBAR_INIT(sb + 8, 1);   MBAR_INIT(sb + 16, 1);
        MBAR_INIT(sb + 24, 16); MBAR_INIT(sb + 32, 16); MBAR_INIT(sb + 40, 16);
    }
    __syncthreads();

    const __half* Asrc = A2 + (size_t)(split * NKT) * ATILE_H;
    const __half* Bsrc = B2 + (size_t)(nb * NKTOT + split * NKT) * BTILE_H;

    auto issue_load = [&](int tt) {       // thread 0 only
        const uint32_t s    = (uint32_t)(tt % 3);
        const uint32_t mbar = sb + s * 8;
        const uint32_t dst  = st0 + s * STAGESZ;
        MBAR_EXPECT(mbar, 65536u);
        BULK_G2S(dst,          Asrc + (size_t)tt * ATILE_H, 32768u, mbar);
        BULK_G2S(dst + 32768u, Bsrc + (size_t)tt * BTILE_H, 32768u, mbar);
    };

    if (tid == 0) { issue_load(0); issue_load(1); issue_load(2); }

    // ---- ldsm row bases (bytes within a stage) ----
    const int r8  = lane & 7;
    const int seg = lane >> 3;            // 0..3
    const int sak = seg >> 1;             // A: k8 selector
    const int sam = seg & 1;              // A: m8 selector
    const int sbn = seg >> 1;             // B: n8 selector
    const int sbk = seg & 1;              // B: k8 selector
    uint32_t baseA[2];
#pragma unroll
    for (int mt = 0; mt < 2; mt++)
        baseA[mt] = (uint32_t)((wm * 32 + mt * 16 + sam * 8 + r8) * 256);
    uint32_t baseB[4];
#pragma unroll
    for (int p = 0; p < 4; p++)
        baseB[p] = (uint32_t)(32768 + (wn * 64 + p * 16 + sbn * 8 + r8) * 128);

    float acc[2][8][4] = {};

#pragma unroll 1
    for (int tt = 0; tt < NKT; tt++) {
        const uint32_t s   = (uint32_t)(tt % 3);
        const uint32_t par = (uint32_t)((tt / 3) & 1);
        MBAR_WAIT(sb + s * 8, par);       // full[s]

        const uint32_t st = st0 + s * STAGESZ;

#pragma unroll
        for (int ks = 0; ks < 4; ks++) {
            const uint32_t offA = (uint32_t)(((ks * 2 + sak) ^ r8) << 4);
            const uint32_t offB = (uint32_t)(((ks * 2 + sbk) ^ r8) << 4);
            uint32_t ah[2][4], al[2][4];
#pragma unroll
            for (int mt = 0; mt < 2; mt++) {
                const uint32_t a = st + baseA[mt] + offA;
                ldsm4(ah[mt][0], ah[mt][1], ah[mt][2], ah[mt][3], a);
                ldsm4(al[mt][0], al[mt][1], al[mt][2], al[mt][3], a + 128);
            }
            uint32_t bh[8][2];
#pragma unroll
            for (int p = 0; p < 4; p++) {
                const uint32_t b = st + baseB[p] + offB;
                ldsm4(bh[2*p][0], bh[2*p][1], bh[2*p+1][0], bh[2*p+1][1], b);
            }
            // pass 1: hi*hi (16 independent MMAs)
#pragma unroll
            for (int mt = 0; mt < 2; mt++)
#pragma unroll
                for (int nt = 0; nt < 8; nt++)
                    mma16816(acc[mt][nt][0], acc[mt][nt][1], acc[mt][nt][2], acc[mt][nt][3],
                             ah[mt][0], ah[mt][1], ah[mt][2], ah[mt][3],
                             bh[nt][0], bh[nt][1]);
            // pass 2: lo*hi
#pragma unroll
            for (int mt = 0; mt < 2; mt++)
#pragma unroll
                for (int nt = 0; nt < 8; nt++)
                    mma16816(acc[mt][nt][0], acc[mt][nt][1], acc[mt][nt][2], acc[mt][nt][3],
                             al[mt][0], al[mt][1], al[mt][2], al[mt][3],
                             bh[nt][0], bh[nt][1]);
        }

        // this warp is done reading stage s (all ldsm before this point)
        if (lane == 0) MBAR_ARRIVE(sb + 24 + s * 8);

        // producer duty: refill stage s once ALL warps have released it
        if (tid == 0 && tt + 3 < NKT) {
            MBAR_WAIT(sb + 24 + s * 8, par);   // empty[s]
            issue_load(tt + 3);
        }
    }

    // ---- epilogue: D frag -> part[(split*128 + c) * 4096 + n] ----
    const int mrow = lane >> 2;           // 0..7
    const int ncol = (lane & 3) * 2;      // 0,2,4,6
#pragma unroll
    for (int mt = 0; mt < 2; mt++) {
#pragma unroll
        for (int nt = 0; nt < 8; nt++) {
            const int c = wm * 32 + mt * 16 + mrow;
            const int n = n0 + wn * 64 + nt * 8 + ncol;
            float* d0 = part + ((size_t)(split * CC + c)) * NNODES + n;
            float* d1 = part + ((size_t)(split * CC + c + 8)) * NNODES + n;
            *reinterpret_cast<float2*>(d0) = make_float2(acc[mt][nt][0], acc[mt][nt][1]);
            *reinterpret_cast<float2*>(d1) = make_float2(acc[mt][nt][2], acc[mt][nt][3]);
        }
    }
}

// ---------------------------------------------------------------------------
// fp32 -> fp16 hi/lo split helper
// ---------------------------------------------------------------------------
__device__ __forceinline__ void split4h(float4 a, uint2& H, uint2& L) {
    __half h0 = __float2half_rn(a.x), h1 = __float2half_rn(a.y);
    __half h2 = __float2half_rn(a.z), h3 = __float2half_rn(a.w);
    __half l0 = __float2half_rn(a.x - __half2float(h0));
    __half l1 = __float2half_rn(a.y - __half2float(h1));
    __half l2 = __float2half_rn(a.z - __half2float(h2));
    __half l3 = __float2half_rn(a.w - __half2float(h3));
    H.x = ((uint32_t)__half_as_ushort(h1) << 16) | __half_as_ushort(h0);
    H.y = ((uint32_t)__half_as_ushort(h3) << 16) | __half_as_ushort(h2);
    L.x = ((uint32_t)__half_as_ushort(l1) << 16) | __half_as_ushort(l0);
    L.y = ((uint32_t)__half_as_ushort(l3) << 16) | __half_as_ushort(l2);
}

// S: fp32 [4096][4096] -> fp16 hi-only, tiled+swizzled B layout
__global__ __launch_bounds__(256)
void cvtS(const float4* __restrict__ in, __half* __restrict__ out, int n4)
{
    int i = blockIdx.x * 256 + threadIdx.x;
    if (i >= n4) return;
    float4 a = in[i];
    __half h0 = __float2half_rn(a.x), h1 = __float2half_rn(a.y);
    __half h2 = __float2half_rn(a.z), h3 = __float2half_rn(a.w);
    uint2 H;
    H.x = ((uint32_t)__half_as_ushort(h1) << 16) | __half_as_ushort(h0);
    H.y = ((uint32_t)__half_as_ushort(h3) << 16) | __half_as_ushort(h2);
    const int e  = i * 4;
    const int n  = e >> 12, k = e & 4095;
    const int nb = n >> 8,  r = n & 255;
    const int kt = k >> 6,  c = (k & 63) >> 3;
    const size_t base = (size_t)(nb * NKTOT + kt) * BTILE_H
                      + r * 64 + ((c ^ (r & 7)) << 3) + (k & 7);
    *reinterpret_cast<uint2*>(out + base) = H;
}

// A-type index: tiled+swizzled A layout
__device__ __forceinline__ size_t a2_index(int row, int k) {
    const int kt = k >> 6, c = (k & 63) >> 3;
    return (size_t)kt * ATILE_H + row * 128 + ((c ^ (row & 7)) << 3) + (k & 7);
}

__global__ __launch_bounds__(256)
void cvtA(const float4* __restrict__ in, __half* __restrict__ out, int n4)
{
    int i = blockIdx.x * 256 + threadIdx.x;
    if (i >= n4) return;
    uint2 H, L;
    split4h(in[i], H, L);
    const int e   = i * 4;
    const int row = e >> 12, k = e & 4095;
    const size_t base = a2_index(row, k);
    *reinterpret_cast<uint2*>(out + base)      = H;
    *reinterpret_cast<uint2*>(out + base + 64) = L;
}

// ---------------------------------------------------------------------------
// split-K reduce + epilogue. MODE 0: Y = sum; 1: Y = sum + V; 2: relu(sum+V+b)
// ---------------------------------------------------------------------------
template <int MODE>
__global__ __launch_bounds__(256)
void reduce_splitk(const float* __restrict__ part, const float* __restrict__ V,
                   const float* __restrict__ bias, float* __restrict__ Yf,
                   __half* __restrict__ Y2)
{
    const int i = blockIdx.x * 256 + threadIdx.x;          // float4 index
    const float4* p = reinterpret_cast<const float4*>(part);
    const int STR = CC * NNODES / 4;
    float4 a = p[i];
#pragma unroll
    for (int s = 1; s < SPLITK; s++) {
        float4 q = p[i + s * STR];
        a.x += q.x; a.y += q.y; a.z += q.z; a.w += q.w;
    }
    if (MODE >= 1) {
        float4 v = reinterpret_cast<const float4*>(V)[i];
        a.x += v.x; a.y += v.y; a.z += v.z; a.w += v.w;
    }
    const int e  = i * 4;
    const int ch = e >> 12;                                // 0..127
    if (MODE == 2) {
        const float bv = bias[ch & 15];
        a.x = fmaxf(a.x + bv, 0.f); a.y = fmaxf(a.y + bv, 0.f);
        a.z = fmaxf(a.z + bv, 0.f); a.w = fmaxf(a.w + bv, 0.f);
    }
    if (Yf) reinterpret_cast<float4*>(Yf)[i] = a;
    if (Y2) {
        uint2 H, L;
        split4h(a, H, L);
        const size_t base = a2_index(ch, e & 4095);
        *reinterpret_cast<uint2*>(Y2 + base)      = H;
        *reinterpret_cast<uint2*>(Y2 + base + 64) = L;
    }
}

// ---------------------------------------------------------------------------
// Combine (16 -> 32): out[b,g,n] = relu(bias[g] + sum_{k,f} W[g,k,f] z_k[b,f,n])
// ---------------------------------------------------------------------------
__global__ __launch_bounds__(256)
void combine_k3(const float* __restrict__ z0, const float* __restrict__ z1,
                const float* __restrict__ z2, const float* __restrict__ W,
                const float* __restrict__ bias, float* __restrict__ out)
{
    __shared__ float Ws[32 * 48];
    const int tid = threadIdx.x;
    for (int i = tid; i < 32 * 48; i += 256) Ws[i] = W[i];
    __syncthreads();

    const int n = blockIdx.x * 256 + tid;
    const int b = blockIdx.y;
    float acc[32];
#pragma unroll
    for (int g = 0; g < 32; g++) acc[g] = bias[g];
    const float* zs[3] = {z0, z1, z2};
#pragma unroll
    for (int k = 0; k < 3; k++) {
        const float* z = zs[k];
#pragma unroll
        for (int f = 0; f < 16; f++) {
            float zv = z[((size_t)b * 16 + f) * NNODES + n];
#pragma unroll
            for (int g = 0; g < 32; g++) acc[g] += Ws[g * 48 + k * 16 + f] * zv;
        }
    }
#pragma unroll
    for (int g = 0; g < 32; g++)
        out[((size_t)b * 32 + g) * NNODES + n] = fmaxf(acc[g], 0.f);
}

// ---------------------------------------------------------------------------
// Projection (32 -> 16): v_k[b,g,n] = sum_f W[g,k,f] x[b,f,n]
// ---------------------------------------------------------------------------
__global__ __launch_bounds__(256)
void proj_k3(const float* __restrict__ in, const float* __restrict__ W,
             float* __restrict__ v0, float* __restrict__ v1,
             __half* __restrict__ v2c)
{
    const int k = blockIdx.z;
    __shared__ float Ws[16 * 32];
    const int tid = threadIdx.x;
    for (int i = tid; i < 16 * 32; i += 256)
        Ws[i] = W[(i >> 5) * 96 + k * 32 + (i & 31)];
    __syncthreads();

    const int n = blockIdx.x * 256 + tid;
    const int b = blockIdx.y;
    float acc[16] = {};
#pragma unroll
    for (int f = 0; f < 32; f++) {
        float xv = in[((size_t)b * 32 + f) * NNODES + n];
#pragma unroll
        for (int g = 0; g < 16; g++) acc[g] += Ws[g * 32 + f] * xv;
    }
    if (k < 2) {
        float* v = (k == 0) ? v0 : v1;
#pragma unroll
        for (int g = 0; g < 16; g++)
            v[((size_t)b * 16 + g) * NNODES + n] = acc[g];
    } else {
#pragma unroll
        for (int g = 0; g < 16; g++) {
            const size_t o = a2_index(b * 16 + g, n);
            __half h = __float2half_rn(acc[g]);
            v2c[o]      = h;
            v2c[o + 64] = __float2half_rn(acc[g] - __half2float(h));
        }
    }
}

// ---------------------------------------------------------------------------
// MLP head
// ---------------------------------------------------------------------------
__global__ __launch_bounds__(256)
void mlp1b(const float* __restrict__ y, const float* __restrict__ W1,
           float* __restrict__ hp)
{
    const int jg = blockIdx.x;    // 8 groups of 8 outputs
    const int ks = blockIdx.y;    // 8 k-slices of 2048 float4
    const float4* Y4 = reinterpret_cast<const float4*>(y);
    const float4* W4 = reinterpret_cast<const float4*>(W1);

    float s[8][8] = {};           // [jj][b]
    for (int i = threadIdx.x; i < 2048; i += 256) {
        const int off = ks * 2048 + i;
        float4 yv[8];
#pragma unroll
        for (int b = 0; b < 8; b++) yv[b] = Y4[(size_t)b * 16384 + off];
#pragma unroll
        for (int jj = 0; jj < 8; jj++) {
            float4 w = W4[(size_t)(jg * 8 + jj) * 16384 + off];
#pragma unroll
            for (int b = 0; b < 8; b++)
                s[jj][b] += yv[b].x * w.x + yv[b].y * w.y + yv[b].z * w.z + yv[b].w * w.w;
        }
    }
    __shared__ float red[8][64];  // [warp][jj*8+b]
    const int wid = threadIdx.x >> 5, lane = threadIdx.x & 31;
#pragma unroll
    for (int jj = 0; jj < 8; jj++)
#pragma unroll
        for (int b = 0; b < 8; b++) {
            float v = s[jj][b];
#pragma unroll
            for (int o = 16; o > 0; o >>= 1) v += __shfl_down_sync(0xffffffffu, v, o);
            if (lane == 0) red[wid][jj * 8 + b] = v;
        }
    __syncthreads();
    if (threadIdx.x < 64) {
        const int jj = threadIdx.x >> 3, b = threadIdx.x & 7;
        float t = 0.f;
#pragma unroll
        for (int w = 0; w < 8; w++) t += red[w][jj * 8 + b];
        hp[((size_t)ks * 8 + b) * 64 + jg * 8 + jj] = t;
    }
}

__global__ __launch_bounds__(64)
void mlp2b(const float* __restrict__ hp, const float* __restrict__ b1,
           const float* __restrict__ W2, const float* __restrict__ b2,
           float* __restrict__ out)
{
    const int b = blockIdx.x, j = threadIdx.x;
    float hv = b1[j];
#pragma unroll
    for (int s = 0; s < 8; s++) hv += hp[((size_t)s * 8 + b) * 64 + j];
    float v = fmaxf(hv, 0.f) * W2[j];
#pragma unroll
    for (int o = 16; o > 0; o >>= 1) v += __shfl_down_sync(0xffffffffu, v, o);
    __shared__ float s2[2];
    if ((j & 31) == 0) s2[j >> 5] = v;
    __syncthreads();
    if (j == 0) out[b] = s2[0] + s2[1] + b2[0];
}

// ---------------------------------------------------------------------------
extern "C" void kernel_launch(void* const* d_in, const int* in_sizes, int n_in,
                              void* d_out, int out_size)
{
    const float* x   = (const float*)d_in[0];
    const float* Sc  = (const float*)d_in[1];
    const float* Sl  = (const float*)d_in[2];
    const float* Wc1 = (const float*)d_in[3];
    const float* bc1 = (const float*)d_in[4];
    const float* Wc2 = (const float*)d_in[5];
    const float* bc2 = (const float*)d_in[6];
    const float* Wl1 = (const float*)d_in[7];
    const float* bl1 = (const float*)d_in[8];
    const float* Wl2 = (const float*)d_in[9];
    const float* bl2 = (const float*)d_in[10];
    const float* Wm1 = (const float*)d_in[11];
    const float* bm1 = (const float*)d_in[12];
    const float* Wm2 = (const float*)d_in[13];
    const float* bm2 = (const float*)d_in[14];
    float* out = (float*)d_out;

    cudaFuncSetAttribute(gemm_tc, cudaFuncAttributeMaxDynamicSharedMemorySize, SMEMSZ);

    __half *Sc2, *Sl2, *x2, *a2, *b2;
    float *part, *z1f, *z2f, *v0, *v1, *y32, *y16, *hp;
    cudaGetSymbolAddress((void**)&Sc2, g_Sc2); cudaGetSymbolAddress((void**)&Sl2, g_Sl2);
    cudaGetSymbolAddress((void**)&x2, g_x2);
    cudaGetSymbolAddress((void**)&a2, g_a2);   cudaGetSymbolAddress((void**)&b2, g_b2);
    cudaGetSymbolAddress((void**)&part, g_part);
    cudaGetSymbolAddress((void**)&z1f, g_z1f); cudaGetSymbolAddress((void**)&z2f, g_z2f);
    cudaGetSymbolAddress((void**)&v0, g_v0);   cudaGetSymbolAddress((void**)&v1, g_v1);
    cudaGetSymbolAddress((void**)&y32, g_y32); cudaGetSymbolAddress((void**)&y16, g_y16);
    cudaGetSymbolAddress((void**)&hp, g_hp);

    const int SN4 = NNODES * NNODES / 4;          // 4M float4
    const int XN4 = CC * NNODES / 4;              // 128K float4
    cvtS<<<SN4 / 256, 256>>>((const float4*)Sc, Sc2, SN4);
    cvtS<<<SN4 / 256, 256>>>((const float4*)Sl, Sl2, SN4);
    cvtA<<<XN4 / 256, 256>>>((const float4*)x,  x2,  XN4);

    const dim3 gG(NNODES / NT, SPLITK);           // 16 x 8 = 128 CTAs
    const dim3 gR(CC * NNODES / 4 / 256);         // 512 blocks
    const dim3 gC(NNODES / 256, BATCH);
    const dim3 gP(NNODES / 256, BATCH, 3);

    // ---- Layer 1 (clique, 16 -> 32) ----
    gemm_tc<<<gG, 512, SMEMSZ>>>(x2, Sc2, part);
    reduce_splitk<0><<<gR, 256>>>(part, nullptr, nullptr, z1f, a2);
    gemm_tc<<<gG, 512, SMEMSZ>>>(a2, Sc2, part);
    reduce_splitk<0><<<gR, 256>>>(part, nullptr, nullptr, z2f, nullptr);
    combine_k3<<<gC, 256>>>(x, z1f, z2f, Wc1, bc1, y32);

    // ---- Layer 2 (clique, 32 -> 16): project then Horner ----
    proj_k3<<<gP, 256>>>(y32, Wc2, v0, v1, b2);
    gemm_tc<<<gG, 512, SMEMSZ>>>(b2, Sc2, part);
    reduce_splitk<1><<<gR, 256>>>(part, v1, nullptr, nullptr, a2);
    gemm_tc<<<gG, 512, SMEMSZ>>>(a2, Sc2, part);
    reduce_splitk<2><<<gR, 256>>>(part, v0, bc2, y16, b2);

    // ---- Layer 3 (line, 16 -> 32) ----
    gemm_tc<<<gG, 512, SMEMSZ>>>(b2, Sl2, part);
    reduce_splitk<0><<<gR, 256>>>(part, nullptr, nullptr, z1f, a2);
    gemm_tc<<<gG, 512, SMEMSZ>>>(a2, Sl2, part);
    reduce_splitk<0><<<gR, 256>>>(part, nullptr, nullptr, z2f, nullptr);
    combine_k3<<<gC, 256>>>(y16, z1f, z2f, Wl1, bl1, y32);

    // ---- Layer 4 (line, 32 -> 16) ----
    proj_k3<<<gP, 256>>>(y32, Wl2, v0, v1, b2);
    gemm_tc<<<gG, 512, SMEMSZ>>>(b2, Sl2, part);
    reduce_splitk<1><<<gR, 256>>>(part, v1, nullptr, nullptr, a2);
    gemm_tc<<<gG, 512, SMEMSZ>>>(a2, Sl2, part);
    reduce_splitk<2><<<gR, 256>>>(part, v0, bl2, y16, nullptr);

    // ---- MLP head ----
    mlp1b<<<dim3(8, 8), 256>>>(y16, Wm1, hp);
    mlp2b<<<BATCH, 64>>>(hp, bm1, Wm2, bm2, out);
}

// round 10
// speedup vs baseline: 5.8217x; 1.0264x over previous
#include <cuda_runtime.h>
#include <cuda_fp16.h>
#include <cstdint>

// ---------------------------------------------------------------------------
// SelectionGNN (clique+line), B=8, N=4096, E=1, K=3, F=[16,32,16]
// Diffusion GEMMs (8x: 128x4096x4096) via mma.sync fp16 2-pass:
//   D = Ah*Bh + Al*Bh  (A fp16 hi/lo split, B = fp16(S) hi only), fp32 accum.
// Operands PRE-TILED + PRE-SWIZZLED in gmem (tile = smem image).
// Round 10: 2 CTAs per SM. CTA tile 128x128, 256 threads (8 warps, warp tile
// 32x64), 2 stages x 48KB, launch_bounds(256,2) -> two independent pipelines
// per SM hide each other's TMA/ldsm bubbles. Grid 32nb x 8split = 256 CTAs.
// ---------------------------------------------------------------------------

#define NNODES 4096
#define BATCH  8
#define CC     128                 // channels = B*16 (GEMM M)
#define NT     128                 // n-tile per CTA
#define SPLITK 8
#define KC     (NNODES / SPLITK)   // 512 k per CTA
#define NKT    (KC / 64)           // 8 k-tiles (64 k each)
#define NKTOT  (NNODES / 64)       // 64 k-tiles total

#define ATILE_H  16384             // A tile halves (32KB): 128 rows x 256B
#define BTILE_H  8192              // B tile halves (16KB): 128 rows x 128B
#define STAGESZ  49152             // bytes: A(32K) + B(16K)
#define NSTAGE   2
#define SMEMSZ   (64 + NSTAGE * STAGESZ)   // 98368 -> 2 CTAs/SM fit

// ---------------- scratch (device globals; allocation is forbidden) --------
__device__ __align__(256) __half g_Sc2[(size_t)NNODES * NNODES];   // 32MB tiled
__device__ __align__(256) __half g_Sl2[(size_t)NNODES * NNODES];   // 32MB tiled
__device__ __align__(256) __half g_x2 [NKTOT * ATILE_H];           // 2MB tiled
__device__ __align__(256) __half g_a2 [NKTOT * ATILE_H];
__device__ __align__(256) __half g_b2 [NKTOT * ATILE_H];
__device__ __align__(256) float g_part[SPLITK * CC * NNODES];      // 16.8 MB
__device__ __align__(256) float g_z1f [CC * NNODES];
__device__ __align__(256) float g_z2f [CC * NNODES];
__device__ __align__(256) float g_v0  [CC * NNODES];
__device__ __align__(256) float g_v1  [CC * NNODES];
__device__ __align__(256) float g_y32 [BATCH * 32 * NNODES];
__device__ __align__(256) float g_y16 [CC * NNODES];
__device__ __align__(256) float g_hp  [8 * BATCH * 64];

// ---------------- PTX helpers (baseline sm_90-level PTX only) ---------------
__device__ __forceinline__ uint32_t smem_u32(const void* p) {
    uint32_t a;
    asm("{ .reg .u64 t; cvta.to.shared.u64 t, %1; cvt.u32.u64 %0, t; }" : "=r"(a) : "l"(p));
    return a;
}
#define MBAR_INIT(a, c) asm volatile("mbarrier.init.shared.b64 [%0], %1;" :: "r"(a), "r"(c) : "memory")

#define MBAR_WAIT(mbar, par) do {                                              \
    uint32_t _m = (mbar), _p = (par), _d;                                      \
    asm volatile("{ .reg .pred p;"                                             \
        " mbarrier.try_wait.parity.acquire.cta.shared::cta.b64 p, [%1], %2;"   \
        " selp.b32 %0, 1, 0, p; }" : "=r"(_d) : "r"(_m), "r"(_p) : "memory");  \
    if (!_d) {                                                                 \
        asm volatile("{ .reg .pred P1;"                                        \
        " W%=: mbarrier.try_wait.parity.acquire.cta.shared::cta.b64 P1, [%0], %1, 0x989680;" \
        " @P1 bra.uni D%=; bra.uni W%=; D%=: }" :: "r"(_m), "r"(_p) : "memory"); } \
} while (0)

#define MBAR_ARRIVE(mbar) \
    asm volatile("mbarrier.arrive.shared.b64 _, [%0];" :: "r"(mbar) : "memory")

#define MBAR_EXPECT(mbar, bytes) \
    asm volatile("mbarrier.arrive.expect_tx.shared.b64 _, [%0], %1;" :: "r"(mbar), "r"(bytes) : "memory")

#define BULK_G2S(dst, src, bytes, mbar) \
    asm volatile("cp.async.bulk.shared::cluster.global.mbarrier::complete_tx::bytes [%0], [%1], %2, [%3];" \
                 :: "r"(dst), "l"(src), "r"(bytes), "r"(mbar) : "memory")

__device__ __forceinline__ void ldsm4(uint32_t& r0, uint32_t& r1, uint32_t& r2,
                                      uint32_t& r3, uint32_t addr) {
    asm volatile("ldmatrix.sync.aligned.m8n8.x4.shared.b16 {%0,%1,%2,%3}, [%4];"
                 : "=r"(r0), "=r"(r1), "=r"(r2), "=r"(r3) : "r"(addr));
}
__device__ __forceinline__ void mma16816(float& d0, float& d1, float& d2, float& d3,
                                         uint32_t a0, uint32_t a1, uint32_t a2, uint32_t a3,
                                         uint32_t b0, uint32_t b1) {
    asm volatile("mma.sync.aligned.m16n8k16.row.col.f32.f16.f16.f32 "
                 "{%0,%1,%2,%3}, {%4,%5,%6,%7}, {%8,%9}, {%0,%1,%2,%3};"
                 : "+f"(d0), "+f"(d1), "+f"(d2), "+f"(d3)
                 : "r"(a0), "r"(a1), "r"(a2), "r"(a3), "r"(b0), "r"(b1));
}

// ---------------------------------------------------------------------------
// Diffusion GEMM. A2 tiled [64 kt][128r][256B], B2 tiled [32 nb][64 kt][128r][128B]
// grid = (32 nb, 8 split), 256 threads, 8 warps (4m x 2n), warp tile 32x64.
// barriers: full[2] @ sb+0,8 (count 1, tx) ; empty[2] @ sb+16,24 (count 8).
// ---------------------------------------------------------------------------
__global__ __launch_bounds__(256, 2)
void gemm_tc(const __half* __restrict__ A2,
             const __half* __restrict__ B2,
             float* __restrict__ part)
{
    extern __shared__ __align__(16) char smem[];
    const uint32_t sb  = smem_u32(smem);
    const uint32_t st0 = sb + 64;

    const int tid  = threadIdx.x;
    const int wid  = tid >> 5, lane = tid & 31;
    const int wm   = wid >> 1;            // 0..3 -> m offset wm*32
    const int wn   = wid & 1;             // 0..1 -> n offset wn*64
    const int nb   = blockIdx.x;
    const int n0   = nb * NT;
    const int split = blockIdx.y;

    if (tid == 0) {
        MBAR_INIT(sb + 0, 1);  MBAR_INIT(sb + 8, 1);
        MBAR_INIT(sb + 16, 8); MBAR_INIT(sb + 24, 8);
    }
    __syncthreads();

    const __half* Asrc = A2 + (size_t)(split * NKT) * ATILE_H;
    const __half* Bsrc = B2 + (size_t)(nb * NKTOT + split * NKT) * BTILE_H;

    auto issue_load = [&](int tt) {       // thread 0 only
        const uint32_t s    = (uint32_t)(tt & 1);
        const uint32_t mbar = sb + s * 8;
        const uint32_t dst  = st0 + s * STAGESZ;
        MBAR_EXPECT(mbar, 49152u);
        BULK_G2S(dst,          Asrc + (size_t)tt * ATILE_H, 32768u, mbar);
        BULK_G2S(dst + 32768u, Bsrc + (size_t)tt * BTILE_H, 16384u, mbar);
    };

    if (tid == 0) { issue_load(0); issue_load(1); }

    // ---- ldsm row bases (bytes within a stage) ----
    const int r8  = lane & 7;
    const int seg = lane >> 3;            // 0..3
    const int sak = seg >> 1;             // A: k8 selector
    const int sam = seg & 1;              // A: m8 selector
    const int sbn = seg >> 1;             // B: n8 selector
    const int sbk = seg & 1;              // B: k8 selector
    uint32_t baseA[2];
#pragma unroll
    for (int mt = 0; mt < 2; mt++)
        baseA[mt] = (uint32_t)((wm * 32 + mt * 16 + sam * 8 + r8) * 256);
    uint32_t baseB[4];
#pragma unroll
    for (int p = 0; p < 4; p++)
        baseB[p] = (uint32_t)(32768 + (wn * 64 + p * 16 + sbn * 8 + r8) * 128);

    float acc[2][8][4] = {};

#pragma unroll 1
    for (int tt = 0; tt < NKT; tt++) {
        const uint32_t s   = (uint32_t)(tt & 1);
        const uint32_t par = (uint32_t)((tt >> 1) & 1);
        MBAR_WAIT(sb + s * 8, par);       // full[s]

        const uint32_t st = st0 + s * STAGESZ;

#pragma unroll
        for (int ks = 0; ks < 4; ks++) {
            const uint32_t offA = (uint32_t)(((ks * 2 + sak) ^ r8) << 4);
            const uint32_t offB = (uint32_t)(((ks * 2 + sbk) ^ r8) << 4);
            uint32_t ah[2][4], al[2][4];
#pragma unroll
            for (int mt = 0; mt < 2; mt++) {
                const uint32_t a = st + baseA[mt] + offA;
                ldsm4(ah[mt][0], ah[mt][1], ah[mt][2], ah[mt][3], a);
                ldsm4(al[mt][0], al[mt][1], al[mt][2], al[mt][3], a + 128);
            }
            uint32_t bh[8][2];
#pragma unroll
            for (int p = 0; p < 4; p++) {
                const uint32_t b = st + baseB[p] + offB;
                ldsm4(bh[2*p][0], bh[2*p][1], bh[2*p+1][0], bh[2*p+1][1], b);
            }
            // pass 1: hi*hi (16 independent MMAs)
#pragma unroll
            for (int mt = 0; mt < 2; mt++)
#pragma unroll
                for (int nt = 0; nt < 8; nt++)
                    mma16816(acc[mt][nt][0], acc[mt][nt][1], acc[mt][nt][2], acc[mt][nt][3],
                             ah[mt][0], ah[mt][1], ah[mt][2], ah[mt][3],
                             bh[nt][0], bh[nt][1]);
            // pass 2: lo*hi
#pragma unroll
            for (int mt = 0; mt < 2; mt++)
#pragma unroll
                for (int nt = 0; nt < 8; nt++)
                    mma16816(acc[mt][nt][0], acc[mt][nt][1], acc[mt][nt][2], acc[mt][nt][3],
                             al[mt][0], al[mt][1], al[mt][2], al[mt][3],
                             bh[nt][0], bh[nt][1]);
        }

        // this warp is done reading stage s
        if (lane == 0) MBAR_ARRIVE(sb + 16 + s * 8);

        // producer duty: refill stage s once ALL warps have released it
        if (tid == 0 && tt + 2 < NKT) {
            MBAR_WAIT(sb + 16 + s * 8, par);   // empty[s]
            issue_load(tt + 2);
        }
    }

    // ---- epilogue: D frag -> part[(split*128 + c) * 4096 + n] ----
    const int mrow = lane >> 2;           // 0..7
    const int ncol = (lane & 3) * 2;      // 0,2,4,6
#pragma unroll
    for (int mt = 0; mt < 2; mt++) {
#pragma unroll
        for (int nt = 0; nt < 8; nt++) {
            const int c = wm * 32 + mt * 16 + mrow;
            const int n = n0 + wn * 64 + nt * 8 + ncol;
            float* d0 = part + ((size_t)(split * CC + c)) * NNODES + n;
            float* d1 = part + ((size_t)(split * CC + c + 8)) * NNODES + n;
            *reinterpret_cast<float2*>(d0) = make_float2(acc[mt][nt][0], acc[mt][nt][1]);
            *reinterpret_cast<float2*>(d1) = make_float2(acc[mt][nt][2], acc[mt][nt][3]);
        }
    }
}

// ---------------------------------------------------------------------------
// fp32 -> fp16 hi/lo split helper
// ---------------------------------------------------------------------------
__device__ __forceinline__ void split4h(float4 a, uint2& H, uint2& L) {
    __half h0 = __float2half_rn(a.x), h1 = __float2half_rn(a.y);
    __half h2 = __float2half_rn(a.z), h3 = __float2half_rn(a.w);
    __half l0 = __float2half_rn(a.x - __half2float(h0));
    __half l1 = __float2half_rn(a.y - __half2float(h1));
    __half l2 = __float2half_rn(a.z - __half2float(h2));
    __half l3 = __float2half_rn(a.w - __half2float(h3));
    H.x = ((uint32_t)__half_as_ushort(h1) << 16) | __half_as_ushort(h0);
    H.y = ((uint32_t)__half_as_ushort(h3) << 16) | __half_as_ushort(h2);
    L.x = ((uint32_t)__half_as_ushort(l1) << 16) | __half_as_ushort(l0);
    L.y = ((uint32_t)__half_as_ushort(l3) << 16) | __half_as_ushort(l2);
}

// S: fp32 [4096][4096] -> fp16 hi-only, tiled+swizzled B layout (NT=128):
// tile (nb = n>>7, kt = k>>6), row r = n&127, chunk c = (k&63)>>3
__global__ __launch_bounds__(256)
void cvtS(const float4* __restrict__ in, __half* __restrict__ out, int n4)
{
    int i = blockIdx.x * 256 + threadIdx.x;
    if (i >= n4) return;
    float4 a = in[i];
    __half h0 = __float2half_rn(a.x), h1 = __float2half_rn(a.y);
    __half h2 = __float2half_rn(a.z), h3 = __float2half_rn(a.w);
    uint2 H;
    H.x = ((uint32_t)__half_as_ushort(h1) << 16) | __half_as_ushort(h0);
    H.y = ((uint32_t)__half_as_ushort(h3) << 16) | __half_as_ushort(h2);
    const int e  = i * 4;
    const int n  = e >> 12, k = e & 4095;
    const int nb = n >> 7,  r = n & 127;
    const int kt = k >> 6,  c = (k & 63) >> 3;
    const size_t base = (size_t)(nb * NKTOT + kt) * BTILE_H
                      + r * 64 + ((c ^ (r & 7)) << 3) + (k & 7);
    *reinterpret_cast<uint2*>(out + base) = H;
}

// A-type index: tiled+swizzled A layout (unchanged)
__device__ __forceinline__ size_t a2_index(int row, int k) {
    const int kt = k >> 6, c = (k & 63) >> 3;
    return (size_t)kt * ATILE_H + row * 128 + ((c ^ (row & 7)) << 3) + (k & 7);
}

__global__ __launch_bounds__(256)
void cvtA(const float4* __restrict__ in, __half* __restrict__ out, int n4)
{
    int i = blockIdx.x * 256 + threadIdx.x;
    if (i >= n4) return;
    uint2 H, L;
    split4h(in[i], H, L);
    const int e   = i * 4;
    const int row = e >> 12, k = e & 4095;
    const size_t base = a2_index(row, k);
    *reinterpret_cast<uint2*>(out + base)      = H;
    *reinterpret_cast<uint2*>(out + base + 64) = L;
}

// ---------------------------------------------------------------------------
// split-K reduce + epilogue. MODE 0: Y = sum; 1: Y = sum + V; 2: relu(sum+V+b)
// ---------------------------------------------------------------------------
template <int MODE>
__global__ __launch_bounds__(256)
void reduce_splitk(const float* __restrict__ part, const float* __restrict__ V,
                   const float* __restrict__ bias, float* __restrict__ Yf,
                   __half* __restrict__ Y2)
{
    const int i = blockIdx.x * 256 + threadIdx.x;          // float4 index
    const float4* p = reinterpret_cast<const float4*>(part);
    const int STR = CC * NNODES / 4;
    float4 a = p[i];
#pragma unroll
    for (int s = 1; s < SPLITK; s++) {
        float4 q = p[i + s * STR];
        a.x += q.x; a.y += q.y; a.z += q.z; a.w += q.w;
    }
    if (MODE >= 1) {
        float4 v = reinterpret_cast<const float4*>(V)[i];
        a.x += v.x; a.y += v.y; a.z += v.z; a.w += v.w;
    }
    const int e  = i * 4;
    const int ch = e >> 12;                                // 0..127
    if (MODE == 2) {
        const float bv = bias[ch & 15];
        a.x = fmaxf(a.x + bv, 0.f); a.y = fmaxf(a.y + bv, 0.f);
        a.z = fmaxf(a.z + bv, 0.f); a.w = fmaxf(a.w + bv, 0.f);
    }
    if (Yf) reinterpret_cast<float4*>(Yf)[i] = a;
    if (Y2) {
        uint2 H, L;
        split4h(a, H, L);
        const size_t base = a2_index(ch, e & 4095);
        *reinterpret_cast<uint2*>(Y2 + base)      = H;
        *reinterpret_cast<uint2*>(Y2 + base + 64) = L;
    }
}

// ---------------------------------------------------------------------------
// Combine (16 -> 32): out[b,g,n] = relu(bias[g] + sum_{k,f} W[g,k,f] z_k[b,f,n])
// ---------------------------------------------------------------------------
__global__ __launch_bounds__(256)
void combine_k3(const float* __restrict__ z0, const float* __restrict__ z1,
                const float* __restrict__ z2, const float* __restrict__ W,
                const float* __restrict__ bias, float* __restrict__ out)
{
    __shared__ float Ws[32 * 48];
    const int tid = threadIdx.x;
    for (int i = tid; i < 32 * 48; i += 256) Ws[i] = W[i];
    __syncthreads();

    const int n = blockIdx.x * 256 + tid;
    const int b = blockIdx.y;
    float acc[32];
#pragma unroll
    for (int g = 0; g < 32; g++) acc[g] = bias[g];
    const float* zs[3] = {z0, z1, z2};
#pragma unroll
    for (int k = 0; k < 3; k++) {
        const float* z = zs[k];
#pragma unroll
        for (int f = 0; f < 16; f++) {
            float zv = z[((size_t)b * 16 + f) * NNODES + n];
#pragma unroll
            for (int g = 0; g < 32; g++) acc[g] += Ws[g * 48 + k * 16 + f] * zv;
        }
    }
#pragma unroll
    for (int g = 0; g < 32; g++)
        out[((size_t)b * 32 + g) * NNODES + n] = fmaxf(acc[g], 0.f);
}

// ---------------------------------------------------------------------------
// Projection (32 -> 16): v_k[b,g,n] = sum_f W[g,k,f] x[b,f,n]
// ---------------------------------------------------------------------------
__global__ __launch_bounds__(256)
void proj_k3(const float* __restrict__ in, const float* __restrict__ W,
             float* __restrict__ v0, float* __restrict__ v1,
             __half* __restrict__ v2c)
{
    const int k = blockIdx.z;
    __shared__ float Ws[16 * 32];
    const int tid = threadIdx.x;
    for (int i = tid; i < 16 * 32; i += 256)
        Ws[i] = W[(i >> 5) * 96 + k * 32 + (i & 31)];
    __syncthreads();

    const int n = blockIdx.x * 256 + tid;
    const int b = blockIdx.y;
    float acc[16] = {};
#pragma unroll
    for (int f = 0; f < 32; f++) {
        float xv = in[((size_t)b * 32 + f) * NNODES + n];
#pragma unroll
        for (int g = 0; g < 16; g++) acc[g] += Ws[g * 32 + f] * xv;
    }
    if (k < 2) {
        float* v = (k == 0) ? v0 : v1;
#pragma unroll
        for (int g = 0; g < 16; g++)
            v[((size_t)b * 16 + g) * NNODES + n] = acc[g];
    } else {
#pragma unroll
        for (int g = 0; g < 16; g++) {
            const size_t o = a2_index(b * 16 + g, n);
            __half h = __float2half_rn(acc[g]);
            v2c[o]      = h;
            v2c[o + 64] = __float2half_rn(acc[g] - __half2float(h));
        }
    }
}

// ---------------------------------------------------------------------------
// MLP head
// ---------------------------------------------------------------------------
__global__ __launch_bounds__(256)
void mlp1b(const float* __restrict__ y, const float* __restrict__ W1,
           float* __restrict__ hp)
{
    const int jg = blockIdx.x;    // 8 groups of 8 outputs
    const int ks = blockIdx.y;    // 8 k-slices of 2048 float4
    const float4* Y4 = reinterpret_cast<const float4*>(y);
    const float4* W4 = reinterpret_cast<const float4*>(W1);

    float s[8][8] = {};           // [jj][b]
    for (int i = threadIdx.x; i < 2048; i += 256) {
        const int off = ks * 2048 + i;
        float4 yv[8];
#pragma unroll
        for (int b = 0; b < 8; b++) yv[b] = Y4[(size_t)b * 16384 + off];
#pragma unroll
        for (int jj = 0; jj < 8; jj++) {
            float4 w = W4[(size_t)(jg * 8 + jj) * 16384 + off];
#pragma unroll
            for (int b = 0; b < 8; b++)
                s[jj][b] += yv[b].x * w.x + yv[b].y * w.y + yv[b].z * w.z + yv[b].w * w.w;
        }
    }
    __shared__ float red[8][64];  // [warp][jj*8+b]
    const int wid = threadIdx.x >> 5, lane = threadIdx.x & 31;
#pragma unroll
    for (int jj = 0; jj < 8; jj++)
#pragma unroll
        for (int b = 0; b < 8; b++) {
            float v = s[jj][b];
#pragma unroll
            for (int o = 16; o > 0; o >>= 1) v += __shfl_down_sync(0xffffffffu, v, o);
            if (lane == 0) red[wid][jj * 8 + b] = v;
        }
    __syncthreads();
    if (threadIdx.x < 64) {
        const int jj = threadIdx.x >> 3, b = threadIdx.x & 7;
        float t = 0.f;
#pragma unroll
        for (int w = 0; w < 8; w++) t += red[w][jj * 8 + b];
        hp[((size_t)ks * 8 + b) * 64 + jg * 8 + jj] = t;
    }
}

__global__ __launch_bounds__(64)
void mlp2b(const float* __restrict__ hp, const float* __restrict__ b1,
           const float* __restrict__ W2, const float* __restrict__ b2,
           float* __restrict__ out)
{
    const int b = blockIdx.x, j = threadIdx.x;
    float hv = b1[j];
#pragma unroll
    for (int s = 0; s < 8; s++) hv += hp[((size_t)s * 8 + b) * 64 + j];
    float v = fmaxf(hv, 0.f) * W2[j];
#pragma unroll
    for (int o = 16; o > 0; o >>= 1) v += __shfl_down_sync(0xffffffffu, v, o);
    __shared__ float s2[2];
    if ((j & 31) == 0) s2[j >> 5] = v;
    __syncthreads();
    if (j == 0) out[b] = s2[0] + s2[1] + b2[0];
}

// ---------------------------------------------------------------------------
extern "C" void kernel_launch(void* const* d_in, const int* in_sizes, int n_in,
                              void* d_out, int out_size)
{
    const float* x   = (const float*)d_in[0];
    const float* Sc  = (const float*)d_in[1];
    const float* Sl  = (const float*)d_in[2];
    const float* Wc1 = (const float*)d_in[3];
    const float* bc1 = (const float*)d_in[4];
    const float* Wc2 = (const float*)d_in[5];
    const float* bc2 = (const float*)d_in[6];
    const float* Wl1 = (const float*)d_in[7];
    const float* bl1 = (const float*)d_in[8];
    const float* Wl2 = (const float*)d_in[9];
    const float* bl2 = (const float*)d_in[10];
    const float* Wm1 = (const float*)d_in[11];
    const float* bm1 = (const float*)d_in[12];
    const float* Wm2 = (const float*)d_in[13];
    const float* bm2 = (const float*)d_in[14];
    float* out = (float*)d_out;

    cudaFuncSetAttribute(gemm_tc, cudaFuncAttributeMaxDynamicSharedMemorySize, SMEMSZ);

    __half *Sc2, *Sl2, *x2, *a2, *b2;
    float *part, *z1f, *z2f, *v0, *v1, *y32, *y16, *hp;
    cudaGetSymbolAddress((void**)&Sc2, g_Sc2); cudaGetSymbolAddress((void**)&Sl2, g_Sl2);
    cudaGetSymbolAddress((void**)&x2, g_x2);
    cudaGetSymbolAddress((void**)&a2, g_a2);   cudaGetSymbolAddress((void**)&b2, g_b2);
    cudaGetSymbolAddress((void**)&part, g_part);
    cudaGetSymbolAddress((void**)&z1f, g_z1f); cudaGetSymbolAddress((void**)&z2f, g_z2f);
    cudaGetSymbolAddress((void**)&v0, g_v0);   cudaGetSymbolAddress((void**)&v1, g_v1);
    cudaGetSymbolAddress((void**)&y32, g_y32); cudaGetSymbolAddress((void**)&y16, g_y16);
    cudaGetSymbolAddress((void**)&hp, g_hp);

    const int SN4 = NNODES * NNODES / 4;          // 4M float4
    const int XN4 = CC * NNODES / 4;              // 128K float4
    cvtS<<<SN4 / 256, 256>>>((const float4*)Sc, Sc2, SN4);
    cvtS<<<SN4 / 256, 256>>>((const float4*)Sl, Sl2, SN4);
    cvtA<<<XN4 / 256, 256>>>((const float4*)x,  x2,  XN4);

    const dim3 gG(NNODES / NT, SPLITK);           // 32 x 8 = 256 CTAs
    const dim3 gR(CC * NNODES / 4 / 256);         // 512 blocks
    const dim3 gC(NNODES / 256, BATCH);
    const dim3 gP(NNODES / 256, BATCH, 3);

    // ---- Layer 1 (clique, 16 -> 32) ----
    gemm_tc<<<gG, 256, SMEMSZ>>>(x2, Sc2, part);
    reduce_splitk<0><<<gR, 256>>>(part, nullptr, nullptr, z1f, a2);
    gemm_tc<<<gG, 256, SMEMSZ>>>(a2, Sc2, part);
    reduce_splitk<0><<<gR, 256>>>(part, nullptr, nullptr, z2f, nullptr);
    combine_k3<<<gC, 256>>>(x, z1f, z2f, Wc1, bc1, y32);

    // ---- Layer 2 (clique, 32 -> 16): project then Horner ----
    proj_k3<<<gP, 256>>>(y32, Wc2, v0, v1, b2);
    gemm_tc<<<gG, 256, SMEMSZ>>>(b2, Sc2, part);
    reduce_splitk<1><<<gR, 256>>>(part, v1, nullptr, nullptr, a2);
    gemm_tc<<<gG, 256, SMEMSZ>>>(a2, Sc2, part);
    reduce_splitk<2><<<gR, 256>>>(part, v0, bc2, y16, b2);

    // ---- Layer 3 (line, 16 -> 32) ----
    gemm_tc<<<gG, 256, SMEMSZ>>>(b2, Sl2, part);
    reduce_splitk<0><<<gR, 256>>>(part, nullptr, nullptr, z1f, a2);
    gemm_tc<<<gG, 256, SMEMSZ>>>(a2, Sl2, part);
    reduce_splitk<0><<<gR, 256>>>(part, nullptr, nullptr, z2f, nullptr);
    combine_k3<<<gC, 256>>>(y16, z1f, z2f, Wl1, bl1, y32);

    // ---- Layer 4 (line, 32 -> 16) ----
    proj_k3<<<gP, 256>>>(y32, Wl2, v0, v1, b2);
    gemm_tc<<<gG, 256, SMEMSZ>>>(b2, Sl2, part);
    reduce_splitk<1><<<gR, 256>>>(part, v1, nullptr, nullptr, a2);
    gemm_tc<<<gG, 256, SMEMSZ>>>(a2, Sl2, part);
    reduce_splitk<2><<<gR, 256>>>(part, v0, bl2, y16, nullptr);

    // ---- MLP head ----
    mlp1b<<<dim3(8, 8), 256>>>(y16, Wm1, hp);
    mlp2b<<<BATCH, 64>>>(hp, bm1, Wm2, bm2, out);
}